// round 2
// baseline (speedup 1.0000x reference)
#include <cuda_runtime.h>
#include <math.h>

#define NN    50000
#define NE    800000
#define D_IN  500
#define D_HID 100
#define D_OUT 64

// Scratch (static __device__ — no allocation at runtime). 5 x 20MB + small.
__device__ float g_B1[NN * D_HID];
__device__ float g_B2[NN * D_HID];
__device__ float g_B3[NN * D_HID];
__device__ float g_B4[NN * D_HID];
__device__ float g_B5[NN * D_HID];
__device__ float g_dinv[NN];
__device__ int   g_deg[NN];

// ---------------------------------------------------------------------------
// Generic tiled fp32 GEMM: C[nrows, M] = A[nrows, K] @ W[K, M]  (+ epilogue)
// EPI: 0 = plain, 1 = +bias, 2 = +bias, LayerNorm, ReLU, 3 = *dinv[row], dual-write
// One thread per output column, 16 rows register-blocked per CTA.
// ---------------------------------------------------------------------------
template<int K, int M, int EPI>
__global__ void gemm_kernel(const float* __restrict__ A,
                            const float* __restrict__ W,
                            const float* __restrict__ bias,
                            const float* __restrict__ gamma,
                            const float* __restrict__ beta,
                            float* __restrict__ out,
                            float* __restrict__ out2)
{
    constexpr int RT = 16, KT = 32, BLK = 128, RTP = 20;  // RTP pad: fewer STS conflicts
    __shared__ __align__(16) float sA[KT][RTP];
    __shared__ float sW[KT][M];
    __shared__ float sC[RT][M];

    const int tid = threadIdx.x;
    const int r0  = blockIdx.x * RT;   // NN divisible by 16 -> no row guard needed

    float acc[RT];
#pragma unroll
    for (int r = 0; r < RT; r++) acc[r] = 0.f;

    for (int k0 = 0; k0 < K; k0 += KT) {
        // A tile, transposed into smem: sA[kk][r]
#pragma unroll
        for (int i = tid; i < KT * RT; i += BLK) {
            int r = i / KT, kk = i % KT;
            int gk = k0 + kk;
            float v = 0.f;
            if (gk < K) v = A[(r0 + r) * K + gk];
            sA[kk][r] = v;
        }
        // W tile: contiguous KT*M block
        const int nv = ((K - k0) < KT ? (K - k0) : KT) * M;
#pragma unroll
        for (int i = tid; i < KT * M; i += BLK) {
            (&sW[0][0])[i] = (i < nv) ? W[k0 * M + i] : 0.f;
        }
        __syncthreads();

        if (tid < M) {
#pragma unroll 8
            for (int kk = 0; kk < KT; kk++) {
                float w = sW[kk][tid];
                const float4* a4 = reinterpret_cast<const float4*>(&sA[kk][0]);
#pragma unroll
                for (int q = 0; q < RT / 4; q++) {
                    float4 a = a4[q];
                    acc[q*4+0] = fmaf(a.x, w, acc[q*4+0]);
                    acc[q*4+1] = fmaf(a.y, w, acc[q*4+1]);
                    acc[q*4+2] = fmaf(a.z, w, acc[q*4+2]);
                    acc[q*4+3] = fmaf(a.w, w, acc[q*4+3]);
                }
            }
        }
        __syncthreads();
    }

    if (EPI == 0 || EPI == 1) {
        if (tid < M) {
            float b = (EPI == 1) ? bias[tid] : 0.f;
#pragma unroll
            for (int r = 0; r < RT; r++)
                out[(r0 + r) * M + tid] = acc[r] + b;
        }
    } else if (EPI == 3) {
        if (tid < M) {
#pragma unroll
            for (int r = 0; r < RT; r++) {
                int row = r0 + r;
                float v = acc[r] * g_dinv[row];
                out [row * M + tid] = v;
                out2[row * M + tid] = v;
            }
        }
    } else {  // EPI == 2: bias + LayerNorm + ReLU
        if (tid < M) {
            float b = bias[tid];
#pragma unroll
            for (int r = 0; r < RT; r++) sC[r][tid] = acc[r] + b;
        }
        __syncthreads();
        constexpr int CJ = (M + 31) / 32;
        const int warp = tid >> 5, lane = tid & 31;
        for (int r = warp; r < RT; r += BLK / 32) {
            float vals[CJ];
            float s = 0.f, sq = 0.f;
#pragma unroll
            for (int j = 0; j < CJ; j++) {
                int c = lane + 32 * j;
                float v = (c < M) ? sC[r][c] : 0.f;
                vals[j] = v;
                s += v; sq += v * v;
            }
#pragma unroll
            for (int off = 16; off > 0; off >>= 1) {
                s  += __shfl_xor_sync(0xffffffffu, s,  off);
                sq += __shfl_xor_sync(0xffffffffu, sq, off);
            }
            float mean = s / M;
            float var  = sq / M - mean * mean;
            float rstd = rsqrtf(var + 1e-5f);
            int row = r0 + r;
#pragma unroll
            for (int j = 0; j < CJ; j++) {
                int c = lane + 32 * j;
                if (c < M) {
                    float y = (vals[j] - mean) * rstd * gamma[c] + beta[c];
                    out[row * M + c] = fmaxf(y, 0.f);
                }
            }
        }
    }
}

// Warp-per-edge scatter-add: acc[tgt[e]] += h[src[e]]
template<int M>
__global__ void scatter_kernel(const float* __restrict__ h,
                               const int* __restrict__ src,
                               const int* __restrict__ tgt,
                               float* __restrict__ acc)
{
    int gi = blockIdx.x * blockDim.x + threadIdx.x;
    int e = gi >> 5;
    if (e >= NE) return;
    int lane = gi & 31;
    int s = src[e], t = tgt[e];
    const float* hr = h + s * M;
    float* ar = acc + t * M;
#pragma unroll
    for (int c = lane; c < M; c += 32)
        atomicAdd(&ar[c], __ldg(&hr[c]));
}

__global__ void deg_init_kernel() {
    int i = blockIdx.x * blockDim.x + threadIdx.x;
    if (i < NN) g_deg[i] = 1;  // self-loop
}
__global__ void deg_count_kernel(const int* __restrict__ tgt) {
    int e = blockIdx.x * blockDim.x + threadIdx.x;
    if (e < NE) atomicAdd(&g_deg[tgt[e]], 1);
}
__global__ void dinv_kernel() {
    int i = blockIdx.x * blockDim.x + threadIdx.x;
    if (i < NN) g_dinv[i] = rsqrtf((float)g_deg[i]);
}
__global__ void relu_kernel(float* __restrict__ x, int n) {
    int i = blockIdx.x * blockDim.x + threadIdx.x;
    if (i < n) x[i] = fmaxf(x[i], 0.f);
}
// conv1 finalize: out = relu(dinv[row]*acc + b)
__global__ void fin1_kernel(const float* __restrict__ acc, const float* __restrict__ b,
                            float* __restrict__ out) {
    int i = blockIdx.x * blockDim.x + threadIdx.x;
    if (i < NN * D_HID) {
        int row = i / D_HID, c = i % D_HID;
        out[i] = fmaxf(g_dinv[row] * acc[i] + b[c], 0.f);
    }
}
// conv2 finalize + log_softmax (warp per row, D_OUT=64 -> 2 vals/lane)
__global__ void fin2_kernel(const float* __restrict__ acc, const float* __restrict__ b,
                            float* __restrict__ out) {
    int gi = blockIdx.x * blockDim.x + threadIdx.x;
    int row = gi >> 5, lane = gi & 31;
    if (row >= NN) return;
    float di = g_dinv[row];
    float v0 = di * acc[row * D_OUT + lane]      + b[lane];
    float v1 = di * acc[row * D_OUT + 32 + lane] + b[32 + lane];
    float m = fmaxf(v0, v1);
#pragma unroll
    for (int off = 16; off > 0; off >>= 1)
        m = fmaxf(m, __shfl_xor_sync(0xffffffffu, m, off));
    float se = expf(v0 - m) + expf(v1 - m);
#pragma unroll
    for (int off = 16; off > 0; off >>= 1)
        se += __shfl_xor_sync(0xffffffffu, se, off);
    float lse = m + logf(se);
    out[row * D_OUT + lane]      = v0 - lse;
    out[row * D_OUT + 32 + lane] = v1 - lse;
}

extern "C" void kernel_launch(void* const* d_in, const int* in_sizes, int n_in,
                              void* d_out, int out_size)
{
    const float* X     = (const float*)d_in[0];
    const int*   ei    = (const int*)  d_in[1];
    // d_in[2] = edge_attr (all zero, single relation) — unused
    const float* W1    = (const float*)d_in[3];
    const float* b1    = (const float*)d_in[4];
    const float* g1    = (const float*)d_in[5];
    const float* be1   = (const float*)d_in[6];
    const float* W2    = (const float*)d_in[7];
    const float* b2    = (const float*)d_in[8];
    const float* g2    = (const float*)d_in[9];
    const float* be2   = (const float*)d_in[10];
    const float* Wrel  = (const float*)d_in[11];
    const float* Wself = (const float*)d_in[12];
    const float* rb    = (const float*)d_in[13];
    const float* c1W   = (const float*)d_in[14];
    const float* c1b   = (const float*)d_in[15];
    const float* c2W   = (const float*)d_in[16];
    const float* c2b   = (const float*)d_in[17];
    float* out = (float*)d_out;

    const int* src = ei;
    const int* tgt = ei + NE;

    float *B1, *B2, *B3, *B4, *B5;
    cudaGetSymbolAddress((void**)&B1, g_B1);
    cudaGetSymbolAddress((void**)&B2, g_B2);
    cudaGetSymbolAddress((void**)&B3, g_B3);
    cudaGetSymbolAddress((void**)&B4, g_B4);
    cudaGetSymbolAddress((void**)&B5, g_B5);

    const int GROWS = NN / 16;

    // Degree / normalization (shared by both GCN convs)
    deg_init_kernel <<<(NN + 255) / 256, 256>>>();
    deg_count_kernel<<<(NE + 255) / 256, 256>>>(tgt);
    dinv_kernel     <<<(NN + 255) / 256, 256>>>();

    // transform: Linear->LN->ReLU twice
    gemm_kernel<D_IN,  D_HID, 2><<<GROWS, 128>>>(X,  W1, b1, g1, be1, B1, nullptr);
    gemm_kernel<D_HID, D_HID, 2><<<GROWS, 128>>>(B1, W2, b2, g2, be2, B2, nullptr);

    // RGCN (1 relation): x3 = x2@Wself + rb + scatter(x2@Wrel), then ReLU
    gemm_kernel<D_HID, D_HID, 1><<<GROWS, 128>>>(B2, Wself, rb, nullptr, nullptr, B3, nullptr);
    gemm_kernel<D_HID, D_HID, 0><<<GROWS, 128>>>(B2, Wrel, nullptr, nullptr, nullptr, B4, nullptr);
    scatter_kernel<D_HID><<<(NE * 32 + 255) / 256, 256>>>(B4, src, tgt, B3);
    relu_kernel<<<(NN * D_HID + 255) / 256, 256>>>(B3, NN * D_HID);

    // GCNConv 1: hs = dinv*(x3@c1W) -> B4 and acc init (self-loop) -> B5
    gemm_kernel<D_HID, D_HID, 3><<<GROWS, 128>>>(B3, c1W, nullptr, nullptr, nullptr, B4, B5);
    scatter_kernel<D_HID><<<(NE * 32 + 255) / 256, 256>>>(B4, src, tgt, B5);
    fin1_kernel<<<(NN * D_HID + 255) / 256, 256>>>(B5, c1b, B1);

    // GCNConv 2 (-> 64) + log_softmax
    gemm_kernel<D_HID, D_OUT, 3><<<GROWS, 128>>>(B1, c2W, nullptr, nullptr, nullptr, B4, B2);
    scatter_kernel<D_OUT><<<(NE * 32 + 255) / 256, 256>>>(B4, src, tgt, B2);
    fin2_kernel<<<(NN * 32 + 255) / 256, 256>>>(B2, c2b, out);
}

// round 3
// speedup vs baseline: 1.3491x; 1.3491x over previous
#include <cuda_runtime.h>
#include <math.h>

#define NN    50000
#define NE    800000
#define D_IN  500
#define D_HID 100
#define D_OUT 64

// Scratch (static __device__ — no runtime allocation).
__device__ float g_B1[NN * D_HID];
__device__ float g_B2[NN * D_HID];
__device__ float g_B3[NN * D_HID];
__device__ float g_B4[NN * D_HID];
__device__ float g_dinv[NN];
__device__ int   g_deg[NN];
__device__ int   g_off[NN + 1];
__device__ int   g_cur[NN];
__device__ int   g_el[NE];

// ---------------------------------------------------------------------------
// CSR construction
// ---------------------------------------------------------------------------
__global__ void deg_zero_kernel() {
    int i = blockIdx.x * blockDim.x + threadIdx.x;
    if (i < NN) g_deg[i] = 0;
}
__global__ void deg_count_kernel(const int* __restrict__ tgt) {
    int e = blockIdx.x * blockDim.x + threadIdx.x;
    if (e < NE) atomicAdd(&g_deg[tgt[e]], 1);
}
// Single-block exclusive scan of g_deg -> g_off, plus dinv (incl. self-loop)
// and cursor zeroing. 1024 threads.
__global__ void scan_kernel() {
    __shared__ int warp_sums[32];
    const int tid = threadIdx.x;
    const int lane = tid & 31, wid = tid >> 5;
    int carry = 0;
    for (int base = 0; base < NN; base += 1024) {
        int i = base + tid;
        int v = (i < NN) ? g_deg[i] : 0;
        int x = v;
#pragma unroll
        for (int d = 1; d < 32; d <<= 1) {
            int t = __shfl_up_sync(0xffffffffu, x, d);
            if (lane >= d) x += t;
        }
        if (lane == 31) warp_sums[wid] = x;
        __syncthreads();
        if (wid == 0) {
            int s = warp_sums[lane];
#pragma unroll
            for (int d = 1; d < 32; d <<= 1) {
                int t = __shfl_up_sync(0xffffffffu, s, d);
                if (lane >= d) s += t;
            }
            warp_sums[lane] = s;
        }
        __syncthreads();
        int warp_prefix = (wid > 0) ? warp_sums[wid - 1] : 0;
        int incl = warp_prefix + x;
        if (i < NN) {
            g_off[i]  = carry + incl - v;          // exclusive prefix
            g_dinv[i] = rsqrtf((float)(v + 1));    // +1 self-loop
            g_cur[i]  = 0;
        }
        carry += warp_sums[31];
        __syncthreads();
    }
    if (tid == 0) g_off[NN] = carry;
}
__global__ void fill_kernel(const int* __restrict__ src, const int* __restrict__ tgt) {
    int e = blockIdx.x * blockDim.x + threadIdx.x;
    if (e < NE) {
        int t = tgt[e];
        int p = g_off[t] + atomicAdd(&g_cur[t], 1);
        g_el[p] = src[e];
    }
}

// ---------------------------------------------------------------------------
// GEMM v2: C[50000, M] = A[50000, K] @ W[K, M] (+ epilogue)
// Block (XT, 8), BM=80 rows, TM=10 rows x TN=4 cols per thread, BK=50.
// M=100 padded to 112 in smem. EPI: 0 plain, 1 +bias, 2 +bias,LN,ReLU, 3 *dinv
// ---------------------------------------------------------------------------
template<int K, int M, int EPI>
__global__ void gemm2_kernel(const float* __restrict__ A,
                             const float* __restrict__ W,
                             const float* __restrict__ bias,
                             const float* __restrict__ gamma,
                             const float* __restrict__ beta,
                             float* __restrict__ out)
{
    constexpr int MP  = (M == 100) ? 112 : M;
    constexpr int XT  = MP / 4;           // 28 or 16
    constexpr int BLK = XT * 8;           // 224 or 128
    constexpr int BM = 80, TM = 10, BK = 50;
    constexpr int SA = BM * BK;           // 4000
    constexpr int SW = BK * MP;           // 5600 or 3200
    constexpr int SC = BM * M;
    constexpr int SMEMF = (EPI == 2) ? ((SA + SW) > SC ? (SA + SW) : SC) : (SA + SW);
    __shared__ __align__(16) float sm[SMEMF];
    float* sA = sm;
    float* sW = sm + SA;

    const int tx = threadIdx.x, ty = threadIdx.y;
    const int tid = ty * XT + tx;
    const int r0 = blockIdx.x * BM;

    float4 acc[TM];
#pragma unroll
    for (int j = 0; j < TM; j++) acc[j] = make_float4(0.f, 0.f, 0.f, 0.f);

    for (int k0 = 0; k0 < K; k0 += BK) {
#pragma unroll 2
        for (int i = tid; i < SA; i += BLK) {
            int r = i / BK, kk = i % BK;
            sA[i] = A[(r0 + r) * K + (k0 + kk)];
        }
#pragma unroll 2
        for (int i = tid; i < SW; i += BLK) {
            int kk = i / MP, c = i % MP;
            sW[i] = (c < M) ? W[(k0 + kk) * M + c] : 0.f;
        }
        __syncthreads();

        const float* aBase = sA + (ty * TM) * BK;
        const float* wBase = sW + tx * 4;
#pragma unroll 10
        for (int kk = 0; kk < BK; kk++) {
            float4 w4 = *(const float4*)(wBase + kk * MP);
#pragma unroll
            for (int j = 0; j < TM; j++) {
                float a = aBase[j * BK + kk];
                acc[j].x = fmaf(a, w4.x, acc[j].x);
                acc[j].y = fmaf(a, w4.y, acc[j].y);
                acc[j].z = fmaf(a, w4.z, acc[j].z);
                acc[j].w = fmaf(a, w4.w, acc[j].w);
            }
        }
        __syncthreads();
    }

    const int c0 = tx * 4;
    if (EPI == 0 || EPI == 1) {
        if (c0 < M) {
            float4 b = make_float4(0.f, 0.f, 0.f, 0.f);
            if (EPI == 1) b = *(const float4*)(bias + c0);
#pragma unroll
            for (int j = 0; j < TM; j++) {
                int row = r0 + ty * TM + j;
                float4 o;
                o.x = acc[j].x + b.x; o.y = acc[j].y + b.y;
                o.z = acc[j].z + b.z; o.w = acc[j].w + b.w;
                *(float4*)(out + row * M + c0) = o;
            }
        }
    } else if (EPI == 3) {
        if (c0 < M) {
#pragma unroll
            for (int j = 0; j < TM; j++) {
                int row = r0 + ty * TM + j;
                float di = g_dinv[row];
                float4 o;
                o.x = di * acc[j].x; o.y = di * acc[j].y;
                o.z = di * acc[j].z; o.w = di * acc[j].w;
                *(float4*)(out + row * M + c0) = o;
            }
        }
    } else {  // EPI == 2: bias + LayerNorm + ReLU (M == 100 only)
        float* sC = sm;   // reuse tile smem (safe: post-sync)
        if (c0 < M) {
            float4 b = *(const float4*)(bias + c0);
#pragma unroll
            for (int j = 0; j < TM; j++) {
                int lr = ty * TM + j;
                float4 o;
                o.x = acc[j].x + b.x; o.y = acc[j].y + b.y;
                o.z = acc[j].z + b.z; o.w = acc[j].w + b.w;
                *(float4*)(sC + lr * M + c0) = o;
            }
        }
        __syncthreads();
        const int wid = tid >> 5, lane = tid & 31;
        constexpr int NWARP = BLK / 32;
        for (int r = wid; r < BM; r += NWARP) {
            float vals[4];
            float s = 0.f, sq = 0.f;
#pragma unroll
            for (int q = 0; q < 4; q++) {
                int c = lane + 32 * q;
                float v = (c < M) ? sC[r * M + c] : 0.f;
                vals[q] = v; s += v; sq += v * v;
            }
#pragma unroll
            for (int o2 = 16; o2 > 0; o2 >>= 1) {
                s  += __shfl_xor_sync(0xffffffffu, s,  o2);
                sq += __shfl_xor_sync(0xffffffffu, sq, o2);
            }
            float mean = s / M;
            float var  = sq / M - mean * mean;
            float rstd = rsqrtf(var + 1e-5f);
            int row = r0 + r;
#pragma unroll
            for (int q = 0; q < 4; q++) {
                int c = lane + 32 * q;
                if (c < M)
                    out[row * M + c] = fmaxf((vals[q] - mean) * rstd * gamma[c] + beta[c], 0.f);
            }
        }
    }
}

// ---------------------------------------------------------------------------
// Gather aggregation (warp per node), CSR edge list, register accumulators.
// MODE 0: out = relu(self[n] + sum h[s])                       (RGCN)
// MODE 1: out = relu(dinv[n]*(h[n] + sum h[s]) + bias)         (GCNConv1)
// MODE 2: out = log_softmax(dinv[n]*(h[n] + sum h[s]) + bias)  (GCNConv2)
// M4 = cols/4 (25 for 100, 16 for 64)
// ---------------------------------------------------------------------------
template<int M4, int MODE>
__global__ void gather_kernel(const float* __restrict__ h,
                              const float* __restrict__ self,
                              const float* __restrict__ bias,
                              float* __restrict__ out)
{
    int w = (blockIdx.x * blockDim.x + threadIdx.x) >> 5;
    if (w >= NN) return;
    const int lane = threadIdx.x & 31;
    const bool act = lane < M4;
    const float4* h4 = (const float4*)h;

    float4 acc = make_float4(0.f, 0.f, 0.f, 0.f);
    if (act) {
        if (MODE == 0) acc = ((const float4*)self)[w * M4 + lane];
        else           acc = h4[w * M4 + lane];
    }

    const int off = g_off[w];
    const int dg  = g_off[w + 1] - off;
    for (int base = 0; base < dg; base += 32) {
        int idx = base + lane;
        int myel = (idx < dg) ? g_el[off + idx] : 0;
        int cnt = dg - base; if (cnt > 32) cnt = 32;
        for (int j = 0; j < cnt; j++) {
            int s = __shfl_sync(0xffffffffu, myel, j);
            if (act) {
                float4 v = h4[s * M4 + lane];
                acc.x += v.x; acc.y += v.y; acc.z += v.z; acc.w += v.w;
            }
        }
    }

    if (MODE == 0) {
        if (act) {
            float4 o;
            o.x = fmaxf(acc.x, 0.f); o.y = fmaxf(acc.y, 0.f);
            o.z = fmaxf(acc.z, 0.f); o.w = fmaxf(acc.w, 0.f);
            ((float4*)out)[w * M4 + lane] = o;
        }
    } else if (MODE == 1) {
        if (act) {
            float di = g_dinv[w];
            float4 b = ((const float4*)bias)[lane];
            float4 o;
            o.x = fmaxf(fmaf(di, acc.x, b.x), 0.f);
            o.y = fmaxf(fmaf(di, acc.y, b.y), 0.f);
            o.z = fmaxf(fmaf(di, acc.z, b.z), 0.f);
            o.w = fmaxf(fmaf(di, acc.w, b.w), 0.f);
            ((float4*)out)[w * M4 + lane] = o;
        }
    } else {
        float di = g_dinv[w];
        float4 v = make_float4(0.f, 0.f, 0.f, 0.f);
        if (act) {
            float4 b = ((const float4*)bias)[lane];
            v.x = fmaf(di, acc.x, b.x); v.y = fmaf(di, acc.y, b.y);
            v.z = fmaf(di, acc.z, b.z); v.w = fmaf(di, acc.w, b.w);
        }
        float m = act ? fmaxf(fmaxf(v.x, v.y), fmaxf(v.z, v.w)) : -3.4e38f;
#pragma unroll
        for (int o2 = 16; o2 > 0; o2 >>= 1)
            m = fmaxf(m, __shfl_xor_sync(0xffffffffu, m, o2));
        float se = act ? (expf(v.x - m) + expf(v.y - m) + expf(v.z - m) + expf(v.w - m)) : 0.f;
#pragma unroll
        for (int o2 = 16; o2 > 0; o2 >>= 1)
            se += __shfl_xor_sync(0xffffffffu, se, o2);
        float lse = m + logf(se);
        if (act) {
            float4 o;
            o.x = v.x - lse; o.y = v.y - lse; o.z = v.z - lse; o.w = v.w - lse;
            ((float4*)out)[w * M4 + lane] = o;
        }
    }
}

extern "C" void kernel_launch(void* const* d_in, const int* in_sizes, int n_in,
                              void* d_out, int out_size)
{
    const float* X     = (const float*)d_in[0];
    const int*   ei    = (const int*)  d_in[1];
    const float* W1    = (const float*)d_in[3];
    const float* b1    = (const float*)d_in[4];
    const float* g1    = (const float*)d_in[5];
    const float* be1   = (const float*)d_in[6];
    const float* W2    = (const float*)d_in[7];
    const float* b2    = (const float*)d_in[8];
    const float* g2    = (const float*)d_in[9];
    const float* be2   = (const float*)d_in[10];
    const float* Wrel  = (const float*)d_in[11];
    const float* Wself = (const float*)d_in[12];
    const float* rb    = (const float*)d_in[13];
    const float* c1W   = (const float*)d_in[14];
    const float* c1b   = (const float*)d_in[15];
    const float* c2W   = (const float*)d_in[16];
    const float* c2b   = (const float*)d_in[17];
    float* out = (float*)d_out;

    const int* src = ei;
    const int* tgt = ei + NE;

    float *B1, *B2, *B3, *B4;
    cudaGetSymbolAddress((void**)&B1, g_B1);
    cudaGetSymbolAddress((void**)&B2, g_B2);
    cudaGetSymbolAddress((void**)&B3, g_B3);
    cudaGetSymbolAddress((void**)&B4, g_B4);

    const int GB = NN / 80;                 // 625 blocks
    dim3 blk100(28, 8), blk64(16, 8);
    const int GGATHER = (NN * 32 + 255) / 256;

    // CSR build (shared by RGCN aggregation and both GCN convs)
    deg_zero_kernel <<<(NN + 255) / 256, 256>>>();
    deg_count_kernel<<<(NE + 255) / 256, 256>>>(tgt);
    scan_kernel     <<<1, 1024>>>();
    fill_kernel     <<<(NE + 255) / 256, 256>>>(src, tgt);

    // transform: (Linear -> LN -> ReLU) x2
    gemm2_kernel<D_IN,  D_HID, 2><<<GB, blk100>>>(X,  W1, b1, g1, be1, B1);
    gemm2_kernel<D_HID, D_HID, 2><<<GB, blk100>>>(B1, W2, b2, g2, be2, B2);

    // RGCN: relu(x@Wself + rb + gather(x@Wrel))
    gemm2_kernel<D_HID, D_HID, 1><<<GB, blk100>>>(B2, Wself, rb, nullptr, nullptr, B3);
    gemm2_kernel<D_HID, D_HID, 0><<<GB, blk100>>>(B2, Wrel, nullptr, nullptr, nullptr, B4);
    gather_kernel<25, 0><<<GGATHER, 256>>>(B4, B3, nullptr, B1);

    // GCNConv1: relu(dinv*(hs[n] + gather(hs)) + b), hs = dinv * (x@W)
    gemm2_kernel<D_HID, D_HID, 3><<<GB, blk100>>>(B1, c1W, nullptr, nullptr, nullptr, B2);
    gather_kernel<25, 1><<<GGATHER, 256>>>(B2, nullptr, c1b, B3);

    // GCNConv2 (->64) + log_softmax
    gemm2_kernel<D_HID, D_OUT, 3><<<GB, blk64>>>(B3, c2W, nullptr, nullptr, nullptr, B4);
    gather_kernel<16, 2><<<GGATHER, 256>>>(B4, nullptr, c2b, out);
}

// round 5
// speedup vs baseline: 1.7779x; 1.3179x over previous
#include <cuda_runtime.h>
#include <math.h>

#define NN    50000
#define NE    800000
#define D_IN  500
#define D_HID 100
#define D_OUT 64
#define XP    50048   // padded pitch for Xt rows (16B-aligned, covers tile overrun)

// Scratch (static __device__ — no runtime allocation).
__device__ float g_Xt[D_IN * XP];     // transposed X, ~100 MB
__device__ float g_B1[NN * D_HID];
__device__ float g_B2[NN * D_HID];
__device__ float g_B3[NN * D_HID];
__device__ float g_B4[NN * D_HID];
__device__ float g_dinv[NN];
__device__ int   g_deg[NN];
__device__ int   g_off[NN + 1];
__device__ int   g_cur[NN];
__device__ int   g_el[NE];

// ---------------------------------------------------------------------------
// f32x2 packed helpers (Blackwell FFMA2 path)
// ---------------------------------------------------------------------------
__device__ __forceinline__ unsigned long long ffma2(unsigned long long a,
                                                    unsigned long long b,
                                                    unsigned long long c) {
    unsigned long long d;
    asm("fma.rn.f32x2 %0, %1, %2, %3;" : "=l"(d) : "l"(a), "l"(b), "l"(c));
    return d;
}
__device__ __forceinline__ unsigned long long pack2(float x, float y) {
    unsigned long long d;
    asm("mov.b64 %0, {%1, %2};" : "=l"(d)
        : "r"(__float_as_uint(x)), "r"(__float_as_uint(y)));
    return d;
}
__device__ __forceinline__ float2 unpack2(unsigned long long v) {
    unsigned int lo, hi;
    asm("mov.b64 {%0, %1}, %2;" : "=r"(lo), "=r"(hi) : "l"(v));
    float2 r; r.x = __uint_as_float(lo); r.y = __uint_as_float(hi);
    return r;
}
__device__ __forceinline__ unsigned int smem_u32(const void* p) {
    unsigned int a;
    asm("{ .reg .u64 t; cvta.to.shared.u64 t, %1; cvt.u32.u64 %0, t; }"
        : "=r"(a) : "l"(p));
    return a;
}
__device__ __forceinline__ void cp16(unsigned int s, const void* g, int srcsz) {
    asm volatile("cp.async.ca.shared.global [%0], [%1], 16, %2;"
                 :: "r"(s), "l"(g), "r"(srcsz));
}

// ---------------------------------------------------------------------------
// X transpose: g_Xt[k][r] = X[r][k]; rows [NN, XP) zero-filled.
// ---------------------------------------------------------------------------
__global__ void transpose_kernel(const float* __restrict__ X) {
    __shared__ float t[32][33];
    const int kb = blockIdx.x * 32, rb = blockIdx.y * 32;
    const int tx = threadIdx.x, ty = threadIdx.y;
#pragma unroll
    for (int i = 0; i < 32; i += 8) {
        int r = rb + ty + i, k = kb + tx;
        t[ty + i][tx] = (r < NN && k < D_IN) ? X[r * D_IN + k] : 0.f;
    }
    __syncthreads();
#pragma unroll
    for (int i = 0; i < 32; i += 8) {
        int k = kb + ty + i, r = rb + tx;
        if (k < D_IN && r < XP) g_Xt[(size_t)k * XP + r] = t[tx][ty + i];
    }
}

// ---------------------------------------------------------------------------
// CSR construction
// ---------------------------------------------------------------------------
__global__ void deg_zero_kernel() {
    int i = blockIdx.x * blockDim.x + threadIdx.x;
    if (i < NN) g_deg[i] = 0;
}
__global__ void deg_count_kernel(const int* __restrict__ tgt) {
    int e = blockIdx.x * blockDim.x + threadIdx.x;
    if (e < NE) atomicAdd(&g_deg[tgt[e]], 1);
}
__global__ void scan_kernel() {
    __shared__ int warp_sums[32];
    const int tid = threadIdx.x;
    const int lane = tid & 31, wid = tid >> 5;
    int carry = 0;
    for (int base = 0; base < NN; base += 1024) {
        int i = base + tid;
        int v = (i < NN) ? g_deg[i] : 0;
        int x = v;
#pragma unroll
        for (int d = 1; d < 32; d <<= 1) {
            int t = __shfl_up_sync(0xffffffffu, x, d);
            if (lane >= d) x += t;
        }
        if (lane == 31) warp_sums[wid] = x;
        __syncthreads();
        if (wid == 0) {
            int s = warp_sums[lane];
#pragma unroll
            for (int d = 1; d < 32; d <<= 1) {
                int t = __shfl_up_sync(0xffffffffu, s, d);
                if (lane >= d) s += t;
            }
            warp_sums[lane] = s;
        }
        __syncthreads();
        int warp_prefix = (wid > 0) ? warp_sums[wid - 1] : 0;
        int incl = warp_prefix + x;
        if (i < NN) {
            g_off[i]  = carry + incl - v;
            g_dinv[i] = rsqrtf((float)(v + 1));
            g_cur[i]  = 0;
        }
        carry += warp_sums[31];
        __syncthreads();
    }
    if (tid == 0) g_off[NN] = carry;
}
__global__ void fill_kernel(const int* __restrict__ src, const int* __restrict__ tgt) {
    int e = blockIdx.x * blockDim.x + threadIdx.x;
    if (e < NE) {
        int t = tgt[e];
        int p = g_off[t] + atomicAdd(&g_cur[t], 1);
        g_el[p] = src[e];
    }
}

// ---------------------------------------------------------------------------
// Big GEMM (K=500): C = Xt^T @ W1 + b1 -> LayerNorm -> ReLU   [FFMA2 + cp.async]
// BM=128, BK=32, block (14,16)=224, 2-stage pipeline, N pad 112 (M=100).
// ---------------------------------------------------------------------------
__global__ void __launch_bounds__(224)
gemm_big_kernel(const float* __restrict__ Xt,
                const float* __restrict__ W,
                const float* __restrict__ bias,
                const float* __restrict__ gamma,
                const float* __restrict__ beta,
                float* __restrict__ out)
{
    extern __shared__ float sm[];
    float* sA = sm;            // 2 x 32 x 128
    float* sW = sm + 8192;     // 2 x 32 x 128
    const int tx = threadIdx.x, ty = threadIdx.y;
    const int tid = ty * 14 + tx;
    const int r0 = blockIdx.x * 128;
    const int NT = 16;         // 500 -> 16 tiles of 32 (zero-padded tail)

    unsigned long long acc[4][8];
#pragma unroll
    for (int p = 0; p < 4; p++)
#pragma unroll
        for (int c = 0; c < 8; c++) acc[p][c] = 0ULL;

    auto load_tile = [&](int t, int s) {
        const int k0 = t * 32;
        float* dA = sA + s * 4096;
        float* dW = sW + s * 4096;
        for (int i = tid; i < 1024; i += 224) {
            int kk = i >> 5, rq = i & 31;
            int gk = k0 + kk;
            int gka = (gk < D_IN) ? gk : 0;
            cp16(smem_u32(dA + kk * 128 + rq * 4),
                 Xt + (size_t)gka * XP + r0 + rq * 4,
                 (gk < D_IN) ? 16 : 0);
        }
        for (int i = tid; i < 896; i += 224) {
            int kk = i / 28, c = (i % 28) * 4;
            int gk = k0 + kk;
            int gka = (gk < D_IN) ? gk : 0;
            int ca  = (c < D_HID) ? c : 0;
            cp16(smem_u32(dW + kk * 128 + c),
                 W + gka * D_HID + ca,
                 (gk < D_IN && c < D_HID) ? 16 : 0);
        }
    };

    load_tile(0, 0);
    asm volatile("cp.async.commit_group;" ::: "memory");

    for (int t = 0; t < NT; t++) {
        if (t + 1 < NT) {
            load_tile(t + 1, (t + 1) & 1);
            asm volatile("cp.async.commit_group;" ::: "memory");
            asm volatile("cp.async.wait_group 1;" ::: "memory");
        } else {
            asm volatile("cp.async.wait_group 0;" ::: "memory");
        }
        __syncthreads();
        const float* cA = sA + (t & 1) * 4096;
        const float* cW = sW + (t & 1) * 4096;
#pragma unroll 8
        for (int kk = 0; kk < 32; kk++) {
            float4 a0 = *(const float4*)(cA + kk * 128 + ty * 4);
            float4 a1 = *(const float4*)(cA + kk * 128 + 64 + ty * 4);
            float4 w0 = *(const float4*)(cW + kk * 128 + tx * 4);
            float4 w1 = *(const float4*)(cW + kk * 128 + 56 + tx * 4);
            unsigned long long ap[4] = {
                pack2(a0.x, a0.y), pack2(a0.z, a0.w),
                pack2(a1.x, a1.y), pack2(a1.z, a1.w)};
            unsigned long long wd[8] = {
                pack2(w0.x, w0.x), pack2(w0.y, w0.y), pack2(w0.z, w0.z), pack2(w0.w, w0.w),
                pack2(w1.x, w1.x), pack2(w1.y, w1.y), pack2(w1.z, w1.z), pack2(w1.w, w1.w)};
#pragma unroll
            for (int p = 0; p < 4; p++)
#pragma unroll
                for (int c = 0; c < 8; c++)
                    acc[p][c] = ffma2(ap[p], wd[c], acc[p][c]);
        }
        __syncthreads();
    }

    // Epilogue: bias + LayerNorm + ReLU (reuse smem as sC[128][100])
    float* sC = sm;
#pragma unroll
    for (int p = 0; p < 4; p++) {
        int lr = (p < 2) ? (ty * 4 + 2 * p) : (64 + ty * 4 + 2 * (p - 2));
#pragma unroll
        for (int h = 0; h < 2; h++) {
#pragma unroll
            for (int j = 0; j < 4; j++) {
                int c = (h ? 56 : 0) + tx * 4 + j;
                if (c < D_HID) {
                    float2 v = unpack2(acc[p][h * 4 + j]);
                    float b = bias[c];
                    sC[lr * D_HID + c]       = v.x + b;
                    sC[(lr + 1) * D_HID + c] = v.y + b;
                }
            }
        }
    }
    __syncthreads();
    const int wid = tid >> 5, lane = tid & 31;
    for (int r = wid; r < 128; r += 7) {
        int row = r0 + r;
        float vals[4];
        float s = 0.f, sq = 0.f;
#pragma unroll
        for (int q = 0; q < 4; q++) {
            int c = lane + 32 * q;
            float v = (c < D_HID) ? sC[r * D_HID + c] : 0.f;
            vals[q] = v; s += v; sq += v * v;
        }
#pragma unroll
        for (int o2 = 16; o2 > 0; o2 >>= 1) {
            s  += __shfl_xor_sync(0xffffffffu, s,  o2);
            sq += __shfl_xor_sync(0xffffffffu, sq, o2);
        }
        float mean = s / D_HID;
        float var  = sq / D_HID - mean * mean;
        float rstd = rsqrtf(var + 1e-5f);
        if (row < NN) {
#pragma unroll
            for (int q = 0; q < 4; q++) {
                int c = lane + 32 * q;
                if (c < D_HID)
                    out[row * D_HID + c] =
                        fmaxf((vals[q] - mean) * rstd * gamma[c] + beta[c], 0.f);
            }
        }
    }
}

// ---------------------------------------------------------------------------
// Small GEMM (K=100, whole K in smem), FFMA2.
// NPAD: 112 (M=100), 224 (dual 100+100), 64 (M=64). Block (NPAD/8, 16).
// EPI: 2 = +bias,LN,ReLU | 3 = *dinv[row] | 4 = dual: out=A@Wa+rb, out2=A@Wb
// ---------------------------------------------------------------------------
template<int NPAD, int EPI>
__global__ void __launch_bounds__((NPAD/8)*16)
gemm_small_kernel(const float* __restrict__ A,
                  const float* __restrict__ Wa,
                  const float* __restrict__ Wb,
                  const float* __restrict__ bias,
                  const float* __restrict__ gamma,
                  const float* __restrict__ beta,
                  float* __restrict__ out,
                  float* __restrict__ out2)
{
    constexpr int TX = NPAD / 8, BLK = TX * 16, OFF1 = NPAD / 2;
    constexpr int KK = 100;
    constexpr int M = (NPAD == 64) ? 64 : 100;
    extern __shared__ float sm[];
    float* sA = sm;               // 128 x 104
    float* sW = sm + 128 * 104;   // 100 x NPAD
    const int tx = threadIdx.x, ty = threadIdx.y;
    const int tid = ty * TX + tx;
    const int r0 = blockIdx.x * 128;

    for (int i = tid; i < 128 * 25; i += BLK) {
        int r = i / 25, kq = i % 25;
        int row = r0 + r;
        float4 v = make_float4(0.f, 0.f, 0.f, 0.f);
        if (row < NN) v = *(const float4*)(A + row * 100 + kq * 4);
        *(float4*)(sA + r * 104 + kq * 4) = v;
    }
    for (int i = tid; i < KK * (NPAD / 4); i += BLK) {
        int kk = i / (NPAD / 4), c = (i % (NPAD / 4)) * 4;
        float4 v = make_float4(0.f, 0.f, 0.f, 0.f);
        if (EPI == 4) {
            if (c < 100)                  v = *(const float4*)(Wa + kk * 100 + c);
            else if (c >= 112 && c < 212) v = *(const float4*)(Wb + kk * 100 + (c - 112));
        } else {
            if (c < M) v = *(const float4*)(Wa + kk * M + c);
        }
        *(float4*)(sW + kk * NPAD + c) = v;
    }
    __syncthreads();

    unsigned long long acc[4][8];
#pragma unroll
    for (int p = 0; p < 4; p++)
#pragma unroll
        for (int c = 0; c < 8; c++) acc[p][c] = 0ULL;

    const float* a0p = sA + (ty * 4) * 104;
    const float* a1p = sA + (64 + ty * 4) * 104;
#pragma unroll 4
    for (int kk = 0; kk < KK; kk++) {
        unsigned long long ap[4] = {
            pack2(a0p[kk], a0p[104 + kk]),
            pack2(a0p[208 + kk], a0p[312 + kk]),
            pack2(a1p[kk], a1p[104 + kk]),
            pack2(a1p[208 + kk], a1p[312 + kk])};
        float4 w0 = *(const float4*)(sW + kk * NPAD + tx * 4);
        float4 w1 = *(const float4*)(sW + kk * NPAD + OFF1 + tx * 4);
        unsigned long long wd[8] = {
            pack2(w0.x, w0.x), pack2(w0.y, w0.y), pack2(w0.z, w0.z), pack2(w0.w, w0.w),
            pack2(w1.x, w1.x), pack2(w1.y, w1.y), pack2(w1.z, w1.z), pack2(w1.w, w1.w)};
#pragma unroll
        for (int p = 0; p < 4; p++)
#pragma unroll
            for (int c = 0; c < 8; c++)
                acc[p][c] = ffma2(ap[p], wd[c], acc[p][c]);
    }

    if (EPI == 2) {
        __syncthreads();
        float* sC = sm;
#pragma unroll
        for (int p = 0; p < 4; p++) {
            int lr = (p < 2) ? (ty * 4 + 2 * p) : (64 + ty * 4 + 2 * (p - 2));
#pragma unroll
            for (int h = 0; h < 2; h++) {
#pragma unroll
                for (int j = 0; j < 4; j++) {
                    int c = (h ? OFF1 : 0) + tx * 4 + j;
                    if (c < M) {
                        float2 v = unpack2(acc[p][h * 4 + j]);
                        float b = bias[c];
                        sC[lr * M + c]       = v.x + b;
                        sC[(lr + 1) * M + c] = v.y + b;
                    }
                }
            }
        }
        __syncthreads();
        const int wid = tid >> 5, lane = tid & 31;
        for (int r = wid; r < 128; r += BLK / 32) {
            int row = r0 + r;
            float vals[4];
            float s = 0.f, sq = 0.f;
#pragma unroll
            for (int q = 0; q < 4; q++) {
                int c = lane + 32 * q;
                float v = (c < M) ? sC[r * M + c] : 0.f;
                vals[q] = v; s += v; sq += v * v;
            }
#pragma unroll
            for (int o2 = 16; o2 > 0; o2 >>= 1) {
                s  += __shfl_xor_sync(0xffffffffu, s,  o2);
                sq += __shfl_xor_sync(0xffffffffu, sq, o2);
            }
            float mean = s / M;
            float var  = sq / M - mean * mean;
            float rstd = rsqrtf(var + 1e-5f);
            if (row < NN) {
#pragma unroll
                for (int q = 0; q < 4; q++) {
                    int c = lane + 32 * q;
                    if (c < M)
                        out[row * M + c] =
                            fmaxf((vals[q] - mean) * rstd * gamma[c] + beta[c], 0.f);
                }
            }
        }
    } else if (EPI == 3) {
#pragma unroll
        for (int p = 0; p < 4; p++) {
            int rl = r0 + ((p < 2) ? (ty * 4 + 2 * p) : (64 + ty * 4 + 2 * (p - 2)));
            float dl = (rl < NN)     ? g_dinv[rl]     : 0.f;
            float dh = (rl + 1 < NN) ? g_dinv[rl + 1] : 0.f;
#pragma unroll
            for (int h = 0; h < 2; h++) {
                int c0 = (h ? OFF1 : 0) + tx * 4;
                if (c0 + 3 >= M) continue;
                float2 v0 = unpack2(acc[p][h * 4 + 0]);
                float2 v1 = unpack2(acc[p][h * 4 + 1]);
                float2 v2 = unpack2(acc[p][h * 4 + 2]);
                float2 v3 = unpack2(acc[p][h * 4 + 3]);
                if (rl < NN) {
                    float4 o = make_float4(dl * v0.x, dl * v1.x, dl * v2.x, dl * v3.x);
                    *(float4*)(out + rl * M + c0) = o;
                }
                if (rl + 1 < NN) {
                    float4 o = make_float4(dh * v0.y, dh * v1.y, dh * v2.y, dh * v3.y);
                    *(float4*)(out + (rl + 1) * M + c0) = o;
                }
            }
        }
    } else {  // EPI == 4: dual output, bias on first half
#pragma unroll
        for (int p = 0; p < 4; p++) {
            int rl = r0 + ((p < 2) ? (ty * 4 + 2 * p) : (64 + ty * 4 + 2 * (p - 2)));
            int c0 = tx * 4;
            if (c0 + 3 < 100) {
                float2 v0 = unpack2(acc[p][0]);
                float2 v1 = unpack2(acc[p][1]);
                float2 v2 = unpack2(acc[p][2]);
                float2 v3 = unpack2(acc[p][3]);
                float4 b = *(const float4*)(bias + c0);
                if (rl < NN)
                    *(float4*)(out + rl * 100 + c0) =
                        make_float4(v0.x + b.x, v1.x + b.y, v2.x + b.z, v3.x + b.w);
                if (rl + 1 < NN)
                    *(float4*)(out + (rl + 1) * 100 + c0) =
                        make_float4(v0.y + b.x, v1.y + b.y, v2.y + b.z, v3.y + b.w);
                float2 u0 = unpack2(acc[p][4]);
                float2 u1 = unpack2(acc[p][5]);
                float2 u2 = unpack2(acc[p][6]);
                float2 u3 = unpack2(acc[p][7]);
                if (rl < NN)
                    *(float4*)(out2 + rl * 100 + c0) = make_float4(u0.x, u1.x, u2.x, u3.x);
                if (rl + 1 < NN)
                    *(float4*)(out2 + (rl + 1) * 100 + c0) = make_float4(u0.y, u1.y, u2.y, u3.y);
            }
        }
    }
}

// ---------------------------------------------------------------------------
// Gather aggregation (warp per node) — unchanged (proven correct).
// ---------------------------------------------------------------------------
template<int M4, int MODE>
__global__ void gather_kernel(const float* __restrict__ h,
                              const float* __restrict__ self,
                              const float* __restrict__ bias,
                              float* __restrict__ out)
{
    int w = (blockIdx.x * blockDim.x + threadIdx.x) >> 5;
    if (w >= NN) return;
    const int lane = threadIdx.x & 31;
    const bool act = lane < M4;
    const float4* h4 = (const float4*)h;

    float4 acc = make_float4(0.f, 0.f, 0.f, 0.f);
    if (act) {
        if (MODE == 0) acc = ((const float4*)self)[w * M4 + lane];
        else           acc = h4[w * M4 + lane];
    }

    const int off = g_off[w];
    const int dg  = g_off[w + 1] - off;
    for (int base = 0; base < dg; base += 32) {
        int idx = base + lane;
        int myel = (idx < dg) ? g_el[off + idx] : 0;
        int cnt = dg - base; if (cnt > 32) cnt = 32;
        for (int j = 0; j < cnt; j++) {
            int s = __shfl_sync(0xffffffffu, myel, j);
            if (act) {
                float4 v = h4[s * M4 + lane];
                acc.x += v.x; acc.y += v.y; acc.z += v.z; acc.w += v.w;
            }
        }
    }

    if (MODE == 0) {
        if (act) {
            float4 o;
            o.x = fmaxf(acc.x, 0.f); o.y = fmaxf(acc.y, 0.f);
            o.z = fmaxf(acc.z, 0.f); o.w = fmaxf(acc.w, 0.f);
            ((float4*)out)[w * M4 + lane] = o;
        }
    } else if (MODE == 1) {
        if (act) {
            float di = g_dinv[w];
            float4 b = ((const float4*)bias)[lane];
            float4 o;
            o.x = fmaxf(fmaf(di, acc.x, b.x), 0.f);
            o.y = fmaxf(fmaf(di, acc.y, b.y), 0.f);
            o.z = fmaxf(fmaf(di, acc.z, b.z), 0.f);
            o.w = fmaxf(fmaf(di, acc.w, b.w), 0.f);
            ((float4*)out)[w * M4 + lane] = o;
        }
    } else {
        float di = g_dinv[w];
        float4 v = make_float4(0.f, 0.f, 0.f, 0.f);
        if (act) {
            float4 b = ((const float4*)bias)[lane];
            v.x = fmaf(di, acc.x, b.x); v.y = fmaf(di, acc.y, b.y);
            v.z = fmaf(di, acc.z, b.z); v.w = fmaf(di, acc.w, b.w);
        }
        float m = act ? fmaxf(fmaxf(v.x, v.y), fmaxf(v.z, v.w)) : -3.4e38f;
#pragma unroll
        for (int o2 = 16; o2 > 0; o2 >>= 1)
            m = fmaxf(m, __shfl_xor_sync(0xffffffffu, m, o2));
        float se = act ? (expf(v.x - m) + expf(v.y - m) + expf(v.z - m) + expf(v.w - m)) : 0.f;
#pragma unroll
        for (int o2 = 16; o2 > 0; o2 >>= 1)
            se += __shfl_xor_sync(0xffffffffu, se, o2);
        float lse = m + logf(se);
        if (act) {
            float4 o;
            o.x = v.x - lse; o.y = v.y - lse; o.z = v.z - lse; o.w = v.w - lse;
            ((float4*)out)[w * M4 + lane] = o;
        }
    }
}

extern "C" void kernel_launch(void* const* d_in, const int* in_sizes, int n_in,
                              void* d_out, int out_size)
{
    const float* X     = (const float*)d_in[0];
    const int*   ei    = (const int*)  d_in[1];
    const float* W1    = (const float*)d_in[3];
    const float* b1    = (const float*)d_in[4];
    const float* g1    = (const float*)d_in[5];
    const float* be1   = (const float*)d_in[6];
    const float* W2    = (const float*)d_in[7];
    const float* b2    = (const float*)d_in[8];
    const float* g2    = (const float*)d_in[9];
    const float* be2   = (const float*)d_in[10];
    const float* Wrel  = (const float*)d_in[11];
    const float* Wself = (const float*)d_in[12];
    const float* rb    = (const float*)d_in[13];
    const float* c1W   = (const float*)d_in[14];
    const float* c1b   = (const float*)d_in[15];
    const float* c2W   = (const float*)d_in[16];
    const float* c2b   = (const float*)d_in[17];
    float* out = (float*)d_out;

    const int* src = ei;
    const int* tgt = ei + NE;

    float *Xt, *B1, *B2, *B3, *B4;
    cudaGetSymbolAddress((void**)&Xt, g_Xt);
    cudaGetSymbolAddress((void**)&B1, g_B1);
    cudaGetSymbolAddress((void**)&B2, g_B2);
    cudaGetSymbolAddress((void**)&B3, g_B3);
    cudaGetSymbolAddress((void**)&B4, g_B4);

    // Opt-in large dynamic smem (host-side attribute set; idempotent)
    cudaFuncSetAttribute(gemm_big_kernel,
                         cudaFuncAttributeMaxDynamicSharedMemorySize, 65536);
    cudaFuncSetAttribute(gemm_small_kernel<112, 2>,
                         cudaFuncAttributeMaxDynamicSharedMemorySize, 98048);
    cudaFuncSetAttribute(gemm_small_kernel<112, 3>,
                         cudaFuncAttributeMaxDynamicSharedMemorySize, 98048);
    cudaFuncSetAttribute(gemm_small_kernel<224, 4>,
                         cudaFuncAttributeMaxDynamicSharedMemorySize, 142848);
    cudaFuncSetAttribute(gemm_small_kernel<64, 3>,
                         cudaFuncAttributeMaxDynamicSharedMemorySize, 78848);

    const int GB = (NN + 127) / 128;   // 391
    const int GGATHER = (NN * 32 + 255) / 256;

    // CSR build
    deg_zero_kernel <<<(NN + 255) / 256, 256>>>();
    deg_count_kernel<<<(NE + 255) / 256, 256>>>(tgt);
    scan_kernel     <<<1, 1024>>>();
    fill_kernel     <<<(NE + 255) / 256, 256>>>(src, tgt);

    // X transpose for the big GEMM (covers full XP pad: 1564 * 32 = 50048)
    transpose_kernel<<<dim3(16, 1564), dim3(32, 8)>>>(X);

    // transform: (Linear -> LN -> ReLU) x2
    gemm_big_kernel<<<GB, dim3(14, 16), 65536>>>(Xt, W1, b1, g1, be1, B1);
    gemm_small_kernel<112, 2><<<GB, dim3(14, 16), 98048>>>(
        B1, W2, nullptr, b2, g2, be2, B2, nullptr);

    // RGCN: fused self|rel GEMM, then gather
    gemm_small_kernel<224, 4><<<GB, dim3(28, 16), 142848>>>(
        B2, Wself, Wrel, rb, nullptr, nullptr, B3, B4);
    gather_kernel<25, 0><<<GGATHER, 256>>>(B4, B3, nullptr, B1);

    // GCNConv1
    gemm_small_kernel<112, 3><<<GB, dim3(14, 16), 98048>>>(
        B1, c1W, nullptr, nullptr, nullptr, nullptr, B2, nullptr);
    gather_kernel<25, 1><<<GGATHER, 256>>>(B2, nullptr, c1b, B3);

    // GCNConv2 (->64) + log_softmax
    gemm_small_kernel<64, 3><<<GB, dim3(8, 16), 78848>>>(
        B3, c2W, nullptr, nullptr, nullptr, nullptr, B4, nullptr);
    gather_kernel<16, 2><<<GGATHER, 256>>>(B4, nullptr, c2b, out);
}

// round 6
// speedup vs baseline: 1.8189x; 1.0230x over previous
#include <cuda_runtime.h>
#include <math.h>

#define NN    50000
#define NE    800000
#define D_IN  500
#define D_HID 100
#define D_OUT 64
#define XP    50048   // padded pitch for Xt rows (16B-aligned, covers tile overrun)

// Scratch (static __device__ — no runtime allocation).
__device__ float g_Xt[D_IN * XP];     // transposed X, ~100 MB
__device__ float g_B1[NN * D_HID];
__device__ float g_B2[NN * D_HID];
__device__ float g_B3[NN * D_HID];
__device__ float g_B4[NN * D_HID];
__device__ float g_dinv[NN];
__device__ int   g_deg[NN];
__device__ int   g_off[NN + 1];
__device__ int   g_cur[NN];
__device__ int   g_el[NE];

// ---------------------------------------------------------------------------
// f32x2 packed helpers (Blackwell FFMA2 path)
// ---------------------------------------------------------------------------
__device__ __forceinline__ unsigned long long ffma2(unsigned long long a,
                                                    unsigned long long b,
                                                    unsigned long long c) {
    unsigned long long d;
    asm("fma.rn.f32x2 %0, %1, %2, %3;" : "=l"(d) : "l"(a), "l"(b), "l"(c));
    return d;
}
__device__ __forceinline__ unsigned long long pack2(float x, float y) {
    unsigned long long d;
    asm("mov.b64 %0, {%1, %2};" : "=l"(d)
        : "r"(__float_as_uint(x)), "r"(__float_as_uint(y)));
    return d;
}
__device__ __forceinline__ float2 unpack2(unsigned long long v) {
    unsigned int lo, hi;
    asm("mov.b64 {%0, %1}, %2;" : "=r"(lo), "=r"(hi) : "l"(v));
    float2 r; r.x = __uint_as_float(lo); r.y = __uint_as_float(hi);
    return r;
}
__device__ __forceinline__ unsigned int smem_u32(const void* p) {
    unsigned int a;
    asm("{ .reg .u64 t; cvta.to.shared.u64 t, %1; cvt.u32.u64 %0, t; }"
        : "=r"(a) : "l"(p));
    return a;
}
__device__ __forceinline__ void cp16(unsigned int s, const void* g, int srcsz) {
    asm volatile("cp.async.ca.shared.global [%0], [%1], 16, %2;"
                 :: "r"(s), "l"(g), "r"(srcsz));
}

// ---------------------------------------------------------------------------
// X transpose: g_Xt[k][r] = X[r][k]; rows [NN, XP) zero-filled.
// ---------------------------------------------------------------------------
__global__ void transpose_kernel(const float* __restrict__ X) {
    __shared__ float t[32][33];
    const int kb = blockIdx.x * 32, rb = blockIdx.y * 32;
    const int tx = threadIdx.x, ty = threadIdx.y;
#pragma unroll
    for (int i = 0; i < 32; i += 8) {
        int r = rb + ty + i, k = kb + tx;
        t[ty + i][tx] = (r < NN && k < D_IN) ? X[r * D_IN + k] : 0.f;
    }
    __syncthreads();
#pragma unroll
    for (int i = 0; i < 32; i += 8) {
        int k = kb + ty + i, r = rb + tx;
        if (k < D_IN && r < XP) g_Xt[(size_t)k * XP + r] = t[tx][ty + i];
    }
}

// ---------------------------------------------------------------------------
// CSR construction (4-way ILP on edge kernels)
// ---------------------------------------------------------------------------
__global__ void deg_zero_kernel() {
    int i = blockIdx.x * blockDim.x + threadIdx.x;
    if (i < NN / 4) ((int4*)g_deg)[i] = make_int4(0, 0, 0, 0);
}
__global__ void deg_count_kernel(const int* __restrict__ tgt) {
    int base = (blockIdx.x * blockDim.x + threadIdx.x) * 4;
    if (base + 3 < NE) {
        int4 t = *(const int4*)(tgt + base);
        atomicAdd(&g_deg[t.x], 1);
        atomicAdd(&g_deg[t.y], 1);
        atomicAdd(&g_deg[t.z], 1);
        atomicAdd(&g_deg[t.w], 1);
    }
}
__global__ void scan_kernel() {
    __shared__ int warp_sums[32];
    const int tid = threadIdx.x;
    const int lane = tid & 31, wid = tid >> 5;
    int carry = 0;
    for (int base = 0; base < NN; base += 1024) {
        int i = base + tid;
        int v = (i < NN) ? g_deg[i] : 0;
        int x = v;
#pragma unroll
        for (int d = 1; d < 32; d <<= 1) {
            int t = __shfl_up_sync(0xffffffffu, x, d);
            if (lane >= d) x += t;
        }
        if (lane == 31) warp_sums[wid] = x;
        __syncthreads();
        if (wid == 0) {
            int s = warp_sums[lane];
#pragma unroll
            for (int d = 1; d < 32; d <<= 1) {
                int t = __shfl_up_sync(0xffffffffu, s, d);
                if (lane >= d) s += t;
            }
            warp_sums[lane] = s;
        }
        __syncthreads();
        int warp_prefix = (wid > 0) ? warp_sums[wid - 1] : 0;
        int incl = warp_prefix + x;
        if (i < NN) {
            g_off[i]  = carry + incl - v;
            g_dinv[i] = rsqrtf((float)(v + 1));
            g_cur[i]  = 0;
        }
        carry += warp_sums[31];
        __syncthreads();
    }
    if (tid == 0) g_off[NN] = carry;
}
__global__ void fill_kernel(const int* __restrict__ src, const int* __restrict__ tgt) {
    int base = (blockIdx.x * blockDim.x + threadIdx.x) * 4;
    if (base + 3 < NE) {
        int4 t = *(const int4*)(tgt + base);
        int4 s = *(const int4*)(src + base);
        int p0 = g_off[t.x] + atomicAdd(&g_cur[t.x], 1);
        int p1 = g_off[t.y] + atomicAdd(&g_cur[t.y], 1);
        int p2 = g_off[t.z] + atomicAdd(&g_cur[t.z], 1);
        int p3 = g_off[t.w] + atomicAdd(&g_cur[t.w], 1);
        g_el[p0] = s.x; g_el[p1] = s.y; g_el[p2] = s.z; g_el[p3] = s.w;
    }
}

// ---------------------------------------------------------------------------
// Big GEMM (K=500): C = Xt^T @ W1 + b1 -> LayerNorm -> ReLU
// FFMA2 + 3-stage cp.async pipeline. BM=128, BK=32, block (14,16)=224.
// ---------------------------------------------------------------------------
__global__ void __launch_bounds__(224)
gemm_big_kernel(const float* __restrict__ Xt,
                const float* __restrict__ W,
                const float* __restrict__ bias,
                const float* __restrict__ gamma,
                const float* __restrict__ beta,
                float* __restrict__ out)
{
    extern __shared__ float sm[];
    float* sA = sm;             // 3 x 32 x 128
    float* sW = sm + 12288;     // 3 x 32 x 128
    const int tx = threadIdx.x, ty = threadIdx.y;
    const int tid = ty * 14 + tx;
    const int r0 = blockIdx.x * 128;
    const int NT = 16;          // 500 -> 16 tiles of 32 (zero-padded tail)

    unsigned long long acc[4][8];
#pragma unroll
    for (int p = 0; p < 4; p++)
#pragma unroll
        for (int c = 0; c < 8; c++) acc[p][c] = 0ULL;

    auto load_tile = [&](int t, int s) {
        const int k0 = t * 32;
        float* dA = sA + s * 4096;
        float* dW = sW + s * 4096;
        for (int i = tid; i < 1024; i += 224) {
            int kk = i >> 5, rq = i & 31;
            int gk = k0 + kk;
            int gka = (gk < D_IN) ? gk : 0;
            cp16(smem_u32(dA + kk * 128 + rq * 4),
                 Xt + (size_t)gka * XP + r0 + rq * 4,
                 (gk < D_IN) ? 16 : 0);
        }
        for (int i = tid; i < 896; i += 224) {
            int kk = i / 28, c = (i % 28) * 4;
            int gk = k0 + kk;
            int gka = (gk < D_IN) ? gk : 0;
            int ca  = (c < D_HID) ? c : 0;
            cp16(smem_u32(dW + kk * 128 + c),
                 W + gka * D_HID + ca,
                 (gk < D_IN && c < D_HID) ? 16 : 0);
        }
    };

    load_tile(0, 0);
    asm volatile("cp.async.commit_group;" ::: "memory");
    load_tile(1, 1);
    asm volatile("cp.async.commit_group;" ::: "memory");

    for (int t = 0; t < NT; t++) {
        if (t + 2 < NT) {
            load_tile(t + 2, (t + 2) % 3);
            asm volatile("cp.async.commit_group;" ::: "memory");
            asm volatile("cp.async.wait_group 2;" ::: "memory");
        } else if (t + 1 < NT) {
            asm volatile("cp.async.wait_group 1;" ::: "memory");
        } else {
            asm volatile("cp.async.wait_group 0;" ::: "memory");
        }
        __syncthreads();
        const float* cA = sA + (t % 3) * 4096;
        const float* cW = sW + (t % 3) * 4096;
#pragma unroll 8
        for (int kk = 0; kk < 32; kk++) {
            float4 a0 = *(const float4*)(cA + kk * 128 + ty * 4);
            float4 a1 = *(const float4*)(cA + kk * 128 + 64 + ty * 4);
            float4 w0 = *(const float4*)(cW + kk * 128 + tx * 4);
            float4 w1 = *(const float4*)(cW + kk * 128 + 56 + tx * 4);
            unsigned long long ap[4] = {
                pack2(a0.x, a0.y), pack2(a0.z, a0.w),
                pack2(a1.x, a1.y), pack2(a1.z, a1.w)};
            unsigned long long wd[8] = {
                pack2(w0.x, w0.x), pack2(w0.y, w0.y), pack2(w0.z, w0.z), pack2(w0.w, w0.w),
                pack2(w1.x, w1.x), pack2(w1.y, w1.y), pack2(w1.z, w1.z), pack2(w1.w, w1.w)};
#pragma unroll
            for (int p = 0; p < 4; p++)
#pragma unroll
                for (int c = 0; c < 8; c++)
                    acc[p][c] = ffma2(ap[p], wd[c], acc[p][c]);
        }
        __syncthreads();
    }

    // Epilogue: bias + LayerNorm + ReLU (reuse smem as sC[128][100])
    float* sC = sm;
#pragma unroll
    for (int p = 0; p < 4; p++) {
        int lr = (p < 2) ? (ty * 4 + 2 * p) : (64 + ty * 4 + 2 * (p - 2));
#pragma unroll
        for (int h = 0; h < 2; h++) {
#pragma unroll
            for (int j = 0; j < 4; j++) {
                int c = (h ? 56 : 0) + tx * 4 + j;
                if (c < D_HID) {
                    float2 v = unpack2(acc[p][h * 4 + j]);
                    float b = bias[c];
                    sC[lr * D_HID + c]       = v.x + b;
                    sC[(lr + 1) * D_HID + c] = v.y + b;
                }
            }
        }
    }
    __syncthreads();
    const int wid = tid >> 5, lane = tid & 31;
    for (int r = wid; r < 128; r += 7) {
        int row = r0 + r;
        float vals[4];
        float s = 0.f, sq = 0.f;
#pragma unroll
        for (int q = 0; q < 4; q++) {
            int c = lane + 32 * q;
            float v = (c < D_HID) ? sC[r * D_HID + c] : 0.f;
            vals[q] = v; s += v; sq += v * v;
        }
#pragma unroll
        for (int o2 = 16; o2 > 0; o2 >>= 1) {
            s  += __shfl_xor_sync(0xffffffffu, s,  o2);
            sq += __shfl_xor_sync(0xffffffffu, sq, o2);
        }
        float mean = s / D_HID;
        float var  = sq / D_HID - mean * mean;
        float rstd = rsqrtf(var + 1e-5f);
        if (row < NN) {
#pragma unroll
            for (int q = 0; q < 4; q++) {
                int c = lane + 32 * q;
                if (c < D_HID)
                    out[row * D_HID + c] =
                        fmaxf((vals[q] - mean) * rstd * gamma[c] + beta[c], 0.f);
            }
        }
    }
}

// ---------------------------------------------------------------------------
// Small GEMM (K=100, whole K in smem), FFMA2.
// NPAD: 112 (M=100), 224 (dual 100+100), 64 (M=64). Block (NPAD/8, 16).
// EPI: 2 = +bias,LN,ReLU | 3 = *dinv[row] | 4 = dual: out=A@Wa+rb, out2=A@Wb
// ---------------------------------------------------------------------------
template<int NPAD, int EPI>
__global__ void __launch_bounds__((NPAD/8)*16)
gemm_small_kernel(const float* __restrict__ A,
                  const float* __restrict__ Wa,
                  const float* __restrict__ Wb,
                  const float* __restrict__ bias,
                  const float* __restrict__ gamma,
                  const float* __restrict__ beta,
                  float* __restrict__ out,
                  float* __restrict__ out2)
{
    constexpr int TX = NPAD / 8, BLK = TX * 16, OFF1 = NPAD / 2;
    constexpr int KK = 100;
    constexpr int M = (NPAD == 64) ? 64 : 100;
    extern __shared__ float sm[];
    float* sA = sm;               // 128 x 104
    float* sW = sm + 128 * 104;   // 100 x NPAD
    const int tx = threadIdx.x, ty = threadIdx.y;
    const int tid = ty * TX + tx;
    const int r0 = blockIdx.x * 128;

    for (int i = tid; i < 128 * 25; i += BLK) {
        int r = i / 25, kq = i % 25;
        int row = r0 + r;
        float4 v = make_float4(0.f, 0.f, 0.f, 0.f);
        if (row < NN) v = *(const float4*)(A + row * 100 + kq * 4);
        *(float4*)(sA + r * 104 + kq * 4) = v;
    }
    for (int i = tid; i < KK * (NPAD / 4); i += BLK) {
        int kk = i / (NPAD / 4), c = (i % (NPAD / 4)) * 4;
        float4 v = make_float4(0.f, 0.f, 0.f, 0.f);
        if (EPI == 4) {
            if (c < 100)                  v = *(const float4*)(Wa + kk * 100 + c);
            else if (c >= 112 && c < 212) v = *(const float4*)(Wb + kk * 100 + (c - 112));
        } else {
            if (c < M) v = *(const float4*)(Wa + kk * M + c);
        }
        *(float4*)(sW + kk * NPAD + c) = v;
    }
    __syncthreads();

    unsigned long long acc[4][8];
#pragma unroll
    for (int p = 0; p < 4; p++)
#pragma unroll
        for (int c = 0; c < 8; c++) acc[p][c] = 0ULL;

    const float* a0p = sA + (ty * 4) * 104;
    const float* a1p = sA + (64 + ty * 4) * 104;
#pragma unroll 4
    for (int kk = 0; kk < KK; kk++) {
        unsigned long long ap[4] = {
            pack2(a0p[kk], a0p[104 + kk]),
            pack2(a0p[208 + kk], a0p[312 + kk]),
            pack2(a1p[kk], a1p[104 + kk]),
            pack2(a1p[208 + kk], a1p[312 + kk])};
        float4 w0 = *(const float4*)(sW + kk * NPAD + tx * 4);
        float4 w1 = *(const float4*)(sW + kk * NPAD + OFF1 + tx * 4);
        unsigned long long wd[8] = {
            pack2(w0.x, w0.x), pack2(w0.y, w0.y), pack2(w0.z, w0.z), pack2(w0.w, w0.w),
            pack2(w1.x, w1.x), pack2(w1.y, w1.y), pack2(w1.z, w1.z), pack2(w1.w, w1.w)};
#pragma unroll
        for (int p = 0; p < 4; p++)
#pragma unroll
            for (int c = 0; c < 8; c++)
                acc[p][c] = ffma2(ap[p], wd[c], acc[p][c]);
    }

    if (EPI == 2) {
        __syncthreads();
        float* sC = sm;
#pragma unroll
        for (int p = 0; p < 4; p++) {
            int lr = (p < 2) ? (ty * 4 + 2 * p) : (64 + ty * 4 + 2 * (p - 2));
#pragma unroll
            for (int h = 0; h < 2; h++) {
#pragma unroll
                for (int j = 0; j < 4; j++) {
                    int c = (h ? OFF1 : 0) + tx * 4 + j;
                    if (c < M) {
                        float2 v = unpack2(acc[p][h * 4 + j]);
                        float b = bias[c];
                        sC[lr * M + c]       = v.x + b;
                        sC[(lr + 1) * M + c] = v.y + b;
                    }
                }
            }
        }
        __syncthreads();
        const int wid = tid >> 5, lane = tid & 31;
        for (int r = wid; r < 128; r += BLK / 32) {
            int row = r0 + r;
            float vals[4];
            float s = 0.f, sq = 0.f;
#pragma unroll
            for (int q = 0; q < 4; q++) {
                int c = lane + 32 * q;
                float v = (c < M) ? sC[r * M + c] : 0.f;
                vals[q] = v; s += v; sq += v * v;
            }
#pragma unroll
            for (int o2 = 16; o2 > 0; o2 >>= 1) {
                s  += __shfl_xor_sync(0xffffffffu, s,  o2);
                sq += __shfl_xor_sync(0xffffffffu, sq, o2);
            }
            float mean = s / M;
            float var  = sq / M - mean * mean;
            float rstd = rsqrtf(var + 1e-5f);
            if (row < NN) {
#pragma unroll
                for (int q = 0; q < 4; q++) {
                    int c = lane + 32 * q;
                    if (c < M)
                        out[row * M + c] =
                            fmaxf((vals[q] - mean) * rstd * gamma[c] + beta[c], 0.f);
                }
            }
        }
    } else if (EPI == 3) {
#pragma unroll
        for (int p = 0; p < 4; p++) {
            int rl = r0 + ((p < 2) ? (ty * 4 + 2 * p) : (64 + ty * 4 + 2 * (p - 2)));
            float dl = (rl < NN)     ? g_dinv[rl]     : 0.f;
            float dh = (rl + 1 < NN) ? g_dinv[rl + 1] : 0.f;
#pragma unroll
            for (int h = 0; h < 2; h++) {
                int c0 = (h ? OFF1 : 0) + tx * 4;
                if (c0 + 3 >= M) continue;
                float2 v0 = unpack2(acc[p][h * 4 + 0]);
                float2 v1 = unpack2(acc[p][h * 4 + 1]);
                float2 v2 = unpack2(acc[p][h * 4 + 2]);
                float2 v3 = unpack2(acc[p][h * 4 + 3]);
                if (rl < NN) {
                    float4 o = make_float4(dl * v0.x, dl * v1.x, dl * v2.x, dl * v3.x);
                    *(float4*)(out + rl * M + c0) = o;
                }
                if (rl + 1 < NN) {
                    float4 o = make_float4(dh * v0.y, dh * v1.y, dh * v2.y, dh * v3.y);
                    *(float4*)(out + (rl + 1) * M + c0) = o;
                }
            }
        }
    } else {  // EPI == 4: dual output, bias on first half
#pragma unroll
        for (int p = 0; p < 4; p++) {
            int rl = r0 + ((p < 2) ? (ty * 4 + 2 * p) : (64 + ty * 4 + 2 * (p - 2)));
            int c0 = tx * 4;
            if (c0 + 3 < 100) {
                float2 v0 = unpack2(acc[p][0]);
                float2 v1 = unpack2(acc[p][1]);
                float2 v2 = unpack2(acc[p][2]);
                float2 v3 = unpack2(acc[p][3]);
                float4 b = *(const float4*)(bias + c0);
                if (rl < NN)
                    *(float4*)(out + rl * 100 + c0) =
                        make_float4(v0.x + b.x, v1.x + b.y, v2.x + b.z, v3.x + b.w);
                if (rl + 1 < NN)
                    *(float4*)(out + (rl + 1) * 100 + c0) =
                        make_float4(v0.y + b.x, v1.y + b.y, v2.y + b.z, v3.y + b.w);
                float2 u0 = unpack2(acc[p][4]);
                float2 u1 = unpack2(acc[p][5]);
                float2 u2 = unpack2(acc[p][6]);
                float2 u3 = unpack2(acc[p][7]);
                if (rl < NN)
                    *(float4*)(out2 + rl * 100 + c0) = make_float4(u0.x, u1.x, u2.x, u3.x);
                if (rl + 1 < NN)
                    *(float4*)(out2 + (rl + 1) * 100 + c0) = make_float4(u0.y, u1.y, u2.y, u3.y);
            }
        }
    }
}

// ---------------------------------------------------------------------------
// Gather aggregation (warp per node), 2-way edge ILP.
// MODE 0: out = relu(self[n] + sum h[s])                       (RGCN)
// MODE 1: out = relu(dinv[n]*(h[n] + sum h[s]) + bias)         (GCNConv1)
// MODE 2: out = log_softmax(dinv[n]*(h[n] + sum h[s]) + bias)  (GCNConv2)
// ---------------------------------------------------------------------------
template<int M4, int MODE>
__global__ void gather_kernel(const float* __restrict__ h,
                              const float* __restrict__ self,
                              const float* __restrict__ bias,
                              float* __restrict__ out)
{
    int w = (blockIdx.x * blockDim.x + threadIdx.x) >> 5;
    if (w >= NN) return;
    const int lane = threadIdx.x & 31;
    const bool act = lane < M4;
    const float4* h4 = (const float4*)h;

    float4 acc  = make_float4(0.f, 0.f, 0.f, 0.f);
    float4 acc2 = make_float4(0.f, 0.f, 0.f, 0.f);
    if (act) {
        if (MODE == 0) acc = ((const float4*)self)[w * M4 + lane];
        else           acc = h4[w * M4 + lane];
    }

    const int off = g_off[w];
    const int dg  = g_off[w + 1] - off;
    for (int base = 0; base < dg; base += 32) {
        int idx = base + lane;
        int myel = (idx < dg) ? g_el[off + idx] : 0;
        int cnt = dg - base; if (cnt > 32) cnt = 32;
        int j = 0;
        for (; j + 1 < cnt; j += 2) {
            int s0 = __shfl_sync(0xffffffffu, myel, j);
            int s1 = __shfl_sync(0xffffffffu, myel, j + 1);
            if (act) {
                float4 v0 = h4[s0 * M4 + lane];
                float4 v1 = h4[s1 * M4 + lane];
                acc.x  += v0.x; acc.y  += v0.y; acc.z  += v0.z; acc.w  += v0.w;
                acc2.x += v1.x; acc2.y += v1.y; acc2.z += v1.z; acc2.w += v1.w;
            }
        }
        if (j < cnt) {
            int s0 = __shfl_sync(0xffffffffu, myel, j);
            if (act) {
                float4 v0 = h4[s0 * M4 + lane];
                acc.x += v0.x; acc.y += v0.y; acc.z += v0.z; acc.w += v0.w;
            }
        }
    }
    acc.x += acc2.x; acc.y += acc2.y; acc.z += acc2.z; acc.w += acc2.w;

    if (MODE == 0) {
        if (act) {
            float4 o;
            o.x = fmaxf(acc.x, 0.f); o.y = fmaxf(acc.y, 0.f);
            o.z = fmaxf(acc.z, 0.f); o.w = fmaxf(acc.w, 0.f);
            ((float4*)out)[w * M4 + lane] = o;
        }
    } else if (MODE == 1) {
        if (act) {
            float di = g_dinv[w];
            float4 b = ((const float4*)bias)[lane];
            float4 o;
            o.x = fmaxf(fmaf(di, acc.x, b.x), 0.f);
            o.y = fmaxf(fmaf(di, acc.y, b.y), 0.f);
            o.z = fmaxf(fmaf(di, acc.z, b.z), 0.f);
            o.w = fmaxf(fmaf(di, acc.w, b.w), 0.f);
            ((float4*)out)[w * M4 + lane] = o;
        }
    } else {
        float di = g_dinv[w];
        float4 v = make_float4(0.f, 0.f, 0.f, 0.f);
        if (act) {
            float4 b = ((const float4*)bias)[lane];
            v.x = fmaf(di, acc.x, b.x); v.y = fmaf(di, acc.y, b.y);
            v.z = fmaf(di, acc.z, b.z); v.w = fmaf(di, acc.w, b.w);
        }
        float m = act ? fmaxf(fmaxf(v.x, v.y), fmaxf(v.z, v.w)) : -3.4e38f;
#pragma unroll
        for (int o2 = 16; o2 > 0; o2 >>= 1)
            m = fmaxf(m, __shfl_xor_sync(0xffffffffu, m, o2));
        float se = act ? (expf(v.x - m) + expf(v.y - m) + expf(v.z - m) + expf(v.w - m)) : 0.f;
#pragma unroll
        for (int o2 = 16; o2 > 0; o2 >>= 1)
            se += __shfl_xor_sync(0xffffffffu, se, o2);
        float lse = m + logf(se);
        if (act) {
            float4 o;
            o.x = v.x - lse; o.y = v.y - lse; o.z = v.z - lse; o.w = v.w - lse;
            ((float4*)out)[w * M4 + lane] = o;
        }
    }
}

extern "C" void kernel_launch(void* const* d_in, const int* in_sizes, int n_in,
                              void* d_out, int out_size)
{
    const float* X     = (const float*)d_in[0];
    const int*   ei    = (const int*)  d_in[1];
    const float* W1    = (const float*)d_in[3];
    const float* b1    = (const float*)d_in[4];
    const float* g1    = (const float*)d_in[5];
    const float* be1   = (const float*)d_in[6];
    const float* W2    = (const float*)d_in[7];
    const float* b2    = (const float*)d_in[8];
    const float* g2    = (const float*)d_in[9];
    const float* be2   = (const float*)d_in[10];
    const float* Wrel  = (const float*)d_in[11];
    const float* Wself = (const float*)d_in[12];
    const float* rb    = (const float*)d_in[13];
    const float* c1W   = (const float*)d_in[14];
    const float* c1b   = (const float*)d_in[15];
    const float* c2W   = (const float*)d_in[16];
    const float* c2b   = (const float*)d_in[17];
    float* out = (float*)d_out;

    const int* src = ei;
    const int* tgt = ei + NE;

    float *Xt, *B1, *B2, *B3, *B4;
    cudaGetSymbolAddress((void**)&Xt, g_Xt);
    cudaGetSymbolAddress((void**)&B1, g_B1);
    cudaGetSymbolAddress((void**)&B2, g_B2);
    cudaGetSymbolAddress((void**)&B3, g_B3);
    cudaGetSymbolAddress((void**)&B4, g_B4);

    // Opt-in large dynamic smem (host-side attribute set; idempotent)
    cudaFuncSetAttribute(gemm_big_kernel,
                         cudaFuncAttributeMaxDynamicSharedMemorySize, 98304);
    cudaFuncSetAttribute(gemm_small_kernel<112, 2>,
                         cudaFuncAttributeMaxDynamicSharedMemorySize, 98048);
    cudaFuncSetAttribute(gemm_small_kernel<112, 3>,
                         cudaFuncAttributeMaxDynamicSharedMemorySize, 98048);
    cudaFuncSetAttribute(gemm_small_kernel<224, 4>,
                         cudaFuncAttributeMaxDynamicSharedMemorySize, 142848);
    cudaFuncSetAttribute(gemm_small_kernel<64, 3>,
                         cudaFuncAttributeMaxDynamicSharedMemorySize, 78848);

    const int GB = (NN + 127) / 128;   // 391
    const int GGATHER = (NN * 32 + 255) / 256;

    // CSR build
    deg_zero_kernel <<<(NN / 4 + 255) / 256, 256>>>();
    deg_count_kernel<<<(NE / 4 + 255) / 256, 256>>>(tgt);
    scan_kernel     <<<1, 1024>>>();
    fill_kernel     <<<(NE / 4 + 255) / 256, 256>>>(src, tgt);

    // X transpose for the big GEMM (covers full XP pad: 1564 * 32 = 50048)
    transpose_kernel<<<dim3(16, 1564), dim3(32, 8)>>>(X);

    // transform: (Linear -> LN -> ReLU) x2
    gemm_big_kernel<<<GB, dim3(14, 16), 98304>>>(Xt, W1, b1, g1, be1, B1);
    gemm_small_kernel<112, 2><<<GB, dim3(14, 16), 98048>>>(
        B1, W2, nullptr, b2, g2, be2, B2, nullptr);

    // RGCN: fused self|rel GEMM, then gather
    gemm_small_kernel<224, 4><<<GB, dim3(28, 16), 142848>>>(
        B2, Wself, Wrel, rb, nullptr, nullptr, B3, B4);
    gather_kernel<25, 0><<<GGATHER, 256>>>(B4, B3, nullptr, B1);

    // GCNConv1
    gemm_small_kernel<112, 3><<<GB, dim3(14, 16), 98048>>>(
        B1, c1W, nullptr, nullptr, nullptr, nullptr, B2, nullptr);
    gather_kernel<25, 1><<<GGATHER, 256>>>(B2, nullptr, c1b, B3);

    // GCNConv2 (->64) + log_softmax
    gemm_small_kernel<64, 3><<<GB, dim3(8, 16), 78848>>>(
        B3, c2W, nullptr, nullptr, nullptr, nullptr, B4, nullptr);
    gather_kernel<16, 2><<<GGATHER, 256>>>(B4, nullptr, c2b, out);
}

// round 7
// speedup vs baseline: 1.8599x; 1.0225x over previous
#include <cuda_runtime.h>
#include <math.h>

#define NN    50000
#define NE    800000
#define D_IN  500
#define D_HID 100
#define D_OUT 64

// Scratch (static __device__ — no runtime allocation).
__device__ float g_B1[NN * D_HID];
__device__ float g_B2[NN * D_HID];
__device__ float g_B3[NN * D_HID];
__device__ float g_B4[NN * D_HID];
__device__ float g_dinv[NN];
__device__ int   g_deg[NN];
__device__ int   g_off[NN + 1];
__device__ int   g_cur[NN];
__device__ int   g_el[NE];

// ---------------------------------------------------------------------------
// f32x2 packed helpers (Blackwell FFMA2 path)
// ---------------------------------------------------------------------------
__device__ __forceinline__ unsigned long long ffma2(unsigned long long a,
                                                    unsigned long long b,
                                                    unsigned long long c) {
    unsigned long long d;
    asm("fma.rn.f32x2 %0, %1, %2, %3;" : "=l"(d) : "l"(a), "l"(b), "l"(c));
    return d;
}
__device__ __forceinline__ unsigned long long dup2(float x) {
    unsigned long long d;
    asm("mov.b64 %0, {%1, %1};" : "=l"(d) : "r"(__float_as_uint(x)));
    return d;
}
__device__ __forceinline__ float2 unpack2(unsigned long long v) {
    unsigned int lo, hi;
    asm("mov.b64 {%0, %1}, %2;" : "=r"(lo), "=r"(hi) : "l"(v));
    float2 r; r.x = __uint_as_float(lo); r.y = __uint_as_float(hi);
    return r;
}
__device__ __forceinline__ unsigned int smem_u32(const void* p) {
    unsigned int a;
    asm("{ .reg .u64 t; cvta.to.shared.u64 t, %1; cvt.u32.u64 %0, t; }"
        : "=r"(a) : "l"(p));
    return a;
}
__device__ __forceinline__ void cp16(unsigned int s, const void* g, int srcsz) {
    asm volatile("cp.async.ca.shared.global [%0], [%1], 16, %2;"
                 :: "r"(s), "l"(g), "r"(srcsz));
}

// ---------------------------------------------------------------------------
// CSR construction
// ---------------------------------------------------------------------------
__global__ void deg_zero_kernel() {
    int i = blockIdx.x * blockDim.x + threadIdx.x;
    if (i < NN / 4) ((int4*)g_deg)[i] = make_int4(0, 0, 0, 0);
}
__global__ void deg_count_kernel(const int* __restrict__ tgt) {
    int base = (blockIdx.x * blockDim.x + threadIdx.x) * 4;
    if (base + 3 < NE) {
        int4 t = *(const int4*)(tgt + base);
        atomicAdd(&g_deg[t.x], 1);
        atomicAdd(&g_deg[t.y], 1);
        atomicAdd(&g_deg[t.z], 1);
        atomicAdd(&g_deg[t.w], 1);
    }
}
__global__ void scan_kernel() {
    __shared__ int warp_sums[32];
    const int tid = threadIdx.x;
    const int lane = tid & 31, wid = tid >> 5;
    int carry = 0;
    for (int base = 0; base < NN; base += 1024) {
        int i = base + tid;
        int v = (i < NN) ? g_deg[i] : 0;
        int x = v;
#pragma unroll
        for (int d = 1; d < 32; d <<= 1) {
            int t = __shfl_up_sync(0xffffffffu, x, d);
            if (lane >= d) x += t;
        }
        if (lane == 31) warp_sums[wid] = x;
        __syncthreads();
        if (wid == 0) {
            int s = warp_sums[lane];
#pragma unroll
            for (int d = 1; d < 32; d <<= 1) {
                int t = __shfl_up_sync(0xffffffffu, s, d);
                if (lane >= d) s += t;
            }
            warp_sums[lane] = s;
        }
        __syncthreads();
        int warp_prefix = (wid > 0) ? warp_sums[wid - 1] : 0;
        int incl = warp_prefix + x;
        if (i < NN) {
            g_off[i]  = carry + incl - v;
            g_dinv[i] = rsqrtf((float)(v + 1));
            g_cur[i]  = 0;
        }
        carry += warp_sums[31];
        __syncthreads();
    }
    if (tid == 0) g_off[NN] = carry;
}
__global__ void fill_kernel(const int* __restrict__ src, const int* __restrict__ tgt) {
    int base = (blockIdx.x * blockDim.x + threadIdx.x) * 4;
    if (base + 3 < NE) {
        int4 t = *(const int4*)(tgt + base);
        int4 s = *(const int4*)(src + base);
        int p0 = g_off[t.x] + atomicAdd(&g_cur[t.x], 1);
        int p1 = g_off[t.y] + atomicAdd(&g_cur[t.y], 1);
        int p2 = g_off[t.z] + atomicAdd(&g_cur[t.z], 1);
        int p3 = g_off[t.w] + atomicAdd(&g_cur[t.w], 1);
        g_el[p0] = s.x; g_el[p1] = s.y; g_el[p2] = s.z; g_el[p3] = s.w;
    }
}

// ---------------------------------------------------------------------------
// Big GEMM (K=500): C = X @ W1 + b1 -> LayerNorm -> ReLU
// Row-major A direct from X via cp.async (NO transpose). f32x2 pairs on N.
// BM=128, BK=32, block (14,16)=224, 3-stage pipeline.
// sA pitch 36 (bank-staggered), sW pitch 112.
// ---------------------------------------------------------------------------
__global__ void __launch_bounds__(224)
gemm_big_kernel(const float* __restrict__ X,
                const float* __restrict__ W,
                const float* __restrict__ bias,
                const float* __restrict__ gamma,
                const float* __restrict__ beta,
                float* __restrict__ out)
{
    constexpr int AP = 36;    // sA row pitch (floats)
    constexpr int ASZ = 128 * AP;      // 4608
    constexpr int WSZ = 32 * 112;      // 3584
    extern __shared__ float sm[];
    float* sA = sm;                    // 3 stages x 4608
    float* sW = sm + 3 * ASZ;          // 3 stages x 3584
    const int tx = threadIdx.x, ty = threadIdx.y;
    const int tid = ty * 14 + tx;
    const int r0 = blockIdx.x * 128;
    const int NT = 16;                 // ceil(500/32)

    unsigned long long acc[8][4];
#pragma unroll
    for (int j = 0; j < 8; j++)
#pragma unroll
        for (int c = 0; c < 4; c++) acc[j][c] = 0ULL;

    auto load_tile = [&](int t, int s) {
        const int k0 = t * 32;
        float* dA = sA + s * ASZ;
        float* dW = sW + s * WSZ;
        // A: 128 rows x 8 chunks of 16B from row-major X
        for (int i = tid; i < 1024; i += 224) {
            int r = i >> 3, ch = i & 7;
            int row = r0 + r;
            int gk0 = k0 + ch * 4;
            bool ok = (row < NN) && (gk0 < D_IN);
            int rowa = ok ? row : 0;
            int gka  = ok ? gk0 : 0;
            cp16(smem_u32(dA + r * AP + ch * 4),
                 X + (size_t)rowa * D_IN + gka, ok ? 16 : 0);
        }
        // W: 32 rows x 28 chunks of 16B (cols 0..111, valid 0..99)
        for (int i = tid; i < 896; i += 224) {
            int kk = i / 28, c = (i % 28) * 4;
            int gk = k0 + kk;
            bool ok = (gk < D_IN) && (c < D_HID);
            int gka = ok ? gk : 0;
            int ca  = ok ? c : 0;
            cp16(smem_u32(dW + kk * 112 + c),
                 W + gka * D_HID + ca, ok ? 16 : 0);
        }
    };

    load_tile(0, 0);
    asm volatile("cp.async.commit_group;" ::: "memory");
    load_tile(1, 1);
    asm volatile("cp.async.commit_group;" ::: "memory");

    for (int t = 0; t < NT; t++) {
        if (t + 2 < NT) {
            load_tile(t + 2, (t + 2) % 3);
            asm volatile("cp.async.commit_group;" ::: "memory");
            asm volatile("cp.async.wait_group 2;" ::: "memory");
        } else if (t + 1 < NT) {
            asm volatile("cp.async.wait_group 1;" ::: "memory");
        } else {
            asm volatile("cp.async.wait_group 0;" ::: "memory");
        }
        __syncthreads();
        const float* cA = sA + (t % 3) * ASZ;
        const float* cW = sW + (t % 3) * WSZ;
        const float* aB  = cA + (ty * 4) * AP;
        const float* aB2 = cA + (64 + ty * 4) * AP;
#pragma unroll 4
        for (int kk = 0; kk < 32; kk++) {
            unsigned long long ad[8];
            ad[0] = dup2(aB [0 * AP + kk]);
            ad[1] = dup2(aB [1 * AP + kk]);
            ad[2] = dup2(aB [2 * AP + kk]);
            ad[3] = dup2(aB [3 * AP + kk]);
            ad[4] = dup2(aB2[0 * AP + kk]);
            ad[5] = dup2(aB2[1 * AP + kk]);
            ad[6] = dup2(aB2[2 * AP + kk]);
            ad[7] = dup2(aB2[3 * AP + kk]);
            ulonglong2 w0 = *(const ulonglong2*)(cW + kk * 112 + tx * 4);
            ulonglong2 w1 = *(const ulonglong2*)(cW + kk * 112 + 56 + tx * 4);
#pragma unroll
            for (int j = 0; j < 8; j++) {
                acc[j][0] = ffma2(ad[j], w0.x, acc[j][0]);
                acc[j][1] = ffma2(ad[j], w0.y, acc[j][1]);
                acc[j][2] = ffma2(ad[j], w1.x, acc[j][2]);
                acc[j][3] = ffma2(ad[j], w1.y, acc[j][3]);
            }
        }
        __syncthreads();
    }

    // Epilogue: bias + LayerNorm + ReLU. sC[128][100] reuses smem.
    float* sC = sm;
#pragma unroll
    for (int j = 0; j < 8; j++) {
        int lr = (j < 4) ? (ty * 4 + j) : (64 + ty * 4 + (j - 4));
        int c0 = tx * 4;
        float2 p0 = unpack2(acc[j][0]);
        float2 p1 = unpack2(acc[j][1]);
        sC[lr * D_HID + c0 + 0] = p0.x + bias[c0 + 0];
        sC[lr * D_HID + c0 + 1] = p0.y + bias[c0 + 1];
        sC[lr * D_HID + c0 + 2] = p1.x + bias[c0 + 2];
        sC[lr * D_HID + c0 + 3] = p1.y + bias[c0 + 3];
        int c1 = 56 + tx * 4;
        if (c1 + 3 < D_HID) {
            float2 p2 = unpack2(acc[j][2]);
            float2 p3 = unpack2(acc[j][3]);
            sC[lr * D_HID + c1 + 0] = p2.x + bias[c1 + 0];
            sC[lr * D_HID + c1 + 1] = p2.y + bias[c1 + 1];
            sC[lr * D_HID + c1 + 2] = p3.x + bias[c1 + 2];
            sC[lr * D_HID + c1 + 3] = p3.y + bias[c1 + 3];
        }
    }
    __syncthreads();
    const int wid = tid >> 5, lane = tid & 31;
    for (int r = wid; r < 128; r += 7) {
        int row = r0 + r;
        float vals[4];
        float s = 0.f, sq = 0.f;
#pragma unroll
        for (int q = 0; q < 4; q++) {
            int c = lane + 32 * q;
            float v = (c < D_HID) ? sC[r * D_HID + c] : 0.f;
            vals[q] = v; s += v; sq += v * v;
        }
#pragma unroll
        for (int o2 = 16; o2 > 0; o2 >>= 1) {
            s  += __shfl_xor_sync(0xffffffffu, s,  o2);
            sq += __shfl_xor_sync(0xffffffffu, sq, o2);
        }
        float mean = s / D_HID;
        float var  = sq / D_HID - mean * mean;
        float rstd = rsqrtf(var + 1e-5f);
        if (row < NN) {
#pragma unroll
            for (int q = 0; q < 4; q++) {
                int c = lane + 32 * q;
                if (c < D_HID)
                    out[row * D_HID + c] =
                        fmaxf((vals[q] - mean) * rstd * gamma[c] + beta[c], 0.f);
            }
        }
    }
}

// ---------------------------------------------------------------------------
// Small GEMM (K=100, whole K in smem), f32x2 pairs on N.
// NPAD: 112 (M=100), 224 (dual 100+100), 64 (M=64). Block (NPAD/8, 16).
// EPI: 2 = +bias,LN,ReLU | 3 = *dinv[row] | 4 = dual: out=A@Wa+rb, out2=A@Wb
// ---------------------------------------------------------------------------
template<int NPAD, int EPI>
__global__ void __launch_bounds__((NPAD/8)*16)
gemm_small_kernel(const float* __restrict__ A,
                  const float* __restrict__ Wa,
                  const float* __restrict__ Wb,
                  const float* __restrict__ bias,
                  const float* __restrict__ gamma,
                  const float* __restrict__ beta,
                  float* __restrict__ out,
                  float* __restrict__ out2)
{
    constexpr int TX = NPAD / 8, BLK = TX * 16, OFF1 = NPAD / 2;
    constexpr int KK = 100;
    constexpr int M = (NPAD == 64) ? 64 : 100;
    constexpr int AP = 108;   // sA pitch (bank-staggered, 16B-aligned)
    extern __shared__ float sm[];
    float* sA = sm;                // 128 x 108
    float* sW = sm + 128 * AP;     // 100 x NPAD
    const int tx = threadIdx.x, ty = threadIdx.y;
    const int tid = ty * TX + tx;
    const int r0 = blockIdx.x * 128;

    for (int i = tid; i < 128 * 25; i += BLK) {
        int r = i / 25, kq = i % 25;
        int row = r0 + r;
        float4 v = make_float4(0.f, 0.f, 0.f, 0.f);
        if (row < NN) v = *(const float4*)(A + row * 100 + kq * 4);
        *(float4*)(sA + r * AP + kq * 4) = v;
    }
    for (int i = tid; i < KK * (NPAD / 4); i += BLK) {
        int kk = i / (NPAD / 4), c = (i % (NPAD / 4)) * 4;
        float4 v = make_float4(0.f, 0.f, 0.f, 0.f);
        if (EPI == 4) {
            if (c < 100)                  v = *(const float4*)(Wa + kk * 100 + c);
            else if (c >= 112 && c < 212) v = *(const float4*)(Wb + kk * 100 + (c - 112));
        } else {
            if (c < M) v = *(const float4*)(Wa + kk * M + c);
        }
        *(float4*)(sW + kk * NPAD + c) = v;
    }
    __syncthreads();

    unsigned long long acc[8][4];
#pragma unroll
    for (int j = 0; j < 8; j++)
#pragma unroll
        for (int c = 0; c < 4; c++) acc[j][c] = 0ULL;

    const float* aB  = sA + (ty * 4) * AP;
    const float* aB2 = sA + (64 + ty * 4) * AP;
#pragma unroll 2
    for (int kk = 0; kk < KK; kk++) {
        unsigned long long ad[8];
        ad[0] = dup2(aB [0 * AP + kk]);
        ad[1] = dup2(aB [1 * AP + kk]);
        ad[2] = dup2(aB [2 * AP + kk]);
        ad[3] = dup2(aB [3 * AP + kk]);
        ad[4] = dup2(aB2[0 * AP + kk]);
        ad[5] = dup2(aB2[1 * AP + kk]);
        ad[6] = dup2(aB2[2 * AP + kk]);
        ad[7] = dup2(aB2[3 * AP + kk]);
        ulonglong2 w0 = *(const ulonglong2*)(sW + kk * NPAD + tx * 4);
        ulonglong2 w1 = *(const ulonglong2*)(sW + kk * NPAD + OFF1 + tx * 4);
#pragma unroll
        for (int j = 0; j < 8; j++) {
            acc[j][0] = ffma2(ad[j], w0.x, acc[j][0]);
            acc[j][1] = ffma2(ad[j], w0.y, acc[j][1]);
            acc[j][2] = ffma2(ad[j], w1.x, acc[j][2]);
            acc[j][3] = ffma2(ad[j], w1.y, acc[j][3]);
        }
    }

    if (EPI == 2) {
        __syncthreads();
        float* sC = sm;
#pragma unroll
        for (int j = 0; j < 8; j++) {
            int lr = (j < 4) ? (ty * 4 + j) : (64 + ty * 4 + (j - 4));
            int c0 = tx * 4;
            if (c0 + 3 < M) {
                float2 p0 = unpack2(acc[j][0]);
                float2 p1 = unpack2(acc[j][1]);
                sC[lr * M + c0 + 0] = p0.x + bias[c0 + 0];
                sC[lr * M + c0 + 1] = p0.y + bias[c0 + 1];
                sC[lr * M + c0 + 2] = p1.x + bias[c0 + 2];
                sC[lr * M + c0 + 3] = p1.y + bias[c0 + 3];
            }
            int c1 = OFF1 + tx * 4;
            if (c1 + 3 < M) {
                float2 p2 = unpack2(acc[j][2]);
                float2 p3 = unpack2(acc[j][3]);
                sC[lr * M + c1 + 0] = p2.x + bias[c1 + 0];
                sC[lr * M + c1 + 1] = p2.y + bias[c1 + 1];
                sC[lr * M + c1 + 2] = p3.x + bias[c1 + 2];
                sC[lr * M + c1 + 3] = p3.y + bias[c1 + 3];
            }
        }
        __syncthreads();
        const int wid = tid >> 5, lane = tid & 31;
        for (int r = wid; r < 128; r += BLK / 32) {
            int row = r0 + r;
            float vals[4];
            float s = 0.f, sq = 0.f;
#pragma unroll
            for (int q = 0; q < 4; q++) {
                int c = lane + 32 * q;
                float v = (c < M) ? sC[r * M + c] : 0.f;
                vals[q] = v; s += v; sq += v * v;
            }
#pragma unroll
            for (int o2 = 16; o2 > 0; o2 >>= 1) {
                s  += __shfl_xor_sync(0xffffffffu, s,  o2);
                sq += __shfl_xor_sync(0xffffffffu, sq, o2);
            }
            float mean = s / M;
            float var  = sq / M - mean * mean;
            float rstd = rsqrtf(var + 1e-5f);
            if (row < NN) {
#pragma unroll
                for (int q = 0; q < 4; q++) {
                    int c = lane + 32 * q;
                    if (c < M)
                        out[row * M + c] =
                            fmaxf((vals[q] - mean) * rstd * gamma[c] + beta[c], 0.f);
                }
            }
        }
    } else if (EPI == 3) {
#pragma unroll
        for (int j = 0; j < 8; j++) {
            int row = r0 + ((j < 4) ? (ty * 4 + j) : (64 + ty * 4 + (j - 4)));
            if (row >= NN) continue;
            float di = g_dinv[row];
            int c0 = tx * 4;
            if (c0 + 3 < M) {
                float2 p0 = unpack2(acc[j][0]);
                float2 p1 = unpack2(acc[j][1]);
                *(float4*)(out + row * M + c0) =
                    make_float4(di * p0.x, di * p0.y, di * p1.x, di * p1.y);
            }
            int c1 = OFF1 + tx * 4;
            if (c1 + 3 < M) {
                float2 p2 = unpack2(acc[j][2]);
                float2 p3 = unpack2(acc[j][3]);
                *(float4*)(out + row * M + c1) =
                    make_float4(di * p2.x, di * p2.y, di * p3.x, di * p3.y);
            }
        }
    } else {  // EPI == 4: dual output (NPAD=224), bias on first half
#pragma unroll
        for (int j = 0; j < 8; j++) {
            int row = r0 + ((j < 4) ? (ty * 4 + j) : (64 + ty * 4 + (j - 4)));
            if (row >= NN) continue;
            int c0 = tx * 4;
            if (c0 + 3 < 100) {
                float2 p0 = unpack2(acc[j][0]);
                float2 p1 = unpack2(acc[j][1]);
                float4 b = *(const float4*)(bias + c0);
                *(float4*)(out + row * 100 + c0) =
                    make_float4(p0.x + b.x, p0.y + b.y, p1.x + b.z, p1.y + b.w);
                float2 q0 = unpack2(acc[j][2]);
                float2 q1 = unpack2(acc[j][3]);
                *(float4*)(out2 + row * 100 + c0) =
                    make_float4(q0.x, q0.y, q1.x, q1.y);
            }
        }
    }
}

// ---------------------------------------------------------------------------
// Gather aggregation (warp per node), 4-way edge ILP.
// MODE 0: out = relu(self[n] + sum h[s])                       (RGCN)
// MODE 1: out = relu(dinv[n]*(h[n] + sum h[s]) + bias)         (GCNConv1)
// MODE 2: out = log_softmax(dinv[n]*(h[n] + sum h[s]) + bias)  (GCNConv2)
// ---------------------------------------------------------------------------
template<int M4, int MODE>
__global__ void gather_kernel(const float* __restrict__ h,
                              const float* __restrict__ self,
                              const float* __restrict__ bias,
                              float* __restrict__ out)
{
    int w = (blockIdx.x * blockDim.x + threadIdx.x) >> 5;
    if (w >= NN) return;
    const int lane = threadIdx.x & 31;
    const bool act = lane < M4;
    const float4* h4 = (const float4*)h;

    float4 a0 = make_float4(0.f, 0.f, 0.f, 0.f);
    float4 a1 = a0, a2 = a0, a3 = a0;
    if (act) {
        if (MODE == 0) a0 = ((const float4*)self)[w * M4 + lane];
        else           a0 = h4[w * M4 + lane];
    }

    const int off = g_off[w];
    const int dg  = g_off[w + 1] - off;
    for (int base = 0; base < dg; base += 32) {
        int idx = base + lane;
        int myel = (idx < dg) ? g_el[off + idx] : 0;
        int cnt = dg - base; if (cnt > 32) cnt = 32;
        int j = 0;
        for (; j + 3 < cnt; j += 4) {
            int s0 = __shfl_sync(0xffffffffu, myel, j);
            int s1 = __shfl_sync(0xffffffffu, myel, j + 1);
            int s2 = __shfl_sync(0xffffffffu, myel, j + 2);
            int s3 = __shfl_sync(0xffffffffu, myel, j + 3);
            if (act) {
                float4 v0 = h4[s0 * M4 + lane];
                float4 v1 = h4[s1 * M4 + lane];
                float4 v2 = h4[s2 * M4 + lane];
                float4 v3 = h4[s3 * M4 + lane];
                a0.x += v0.x; a0.y += v0.y; a0.z += v0.z; a0.w += v0.w;
                a1.x += v1.x; a1.y += v1.y; a1.z += v1.z; a1.w += v1.w;
                a2.x += v2.x; a2.y += v2.y; a2.z += v2.z; a2.w += v2.w;
                a3.x += v3.x; a3.y += v3.y; a3.z += v3.z; a3.w += v3.w;
            }
        }
        for (; j < cnt; j++) {
            int s0 = __shfl_sync(0xffffffffu, myel, j);
            if (act) {
                float4 v0 = h4[s0 * M4 + lane];
                a0.x += v0.x; a0.y += v0.y; a0.z += v0.z; a0.w += v0.w;
            }
        }
    }
    float4 acc;
    acc.x = (a0.x + a1.x) + (a2.x + a3.x);
    acc.y = (a0.y + a1.y) + (a2.y + a3.y);
    acc.z = (a0.z + a1.z) + (a2.z + a3.z);
    acc.w = (a0.w + a1.w) + (a2.w + a3.w);

    if (MODE == 0) {
        if (act) {
            float4 o;
            o.x = fmaxf(acc.x, 0.f); o.y = fmaxf(acc.y, 0.f);
            o.z = fmaxf(acc.z, 0.f); o.w = fmaxf(acc.w, 0.f);
            ((float4*)out)[w * M4 + lane] = o;
        }
    } else if (MODE == 1) {
        if (act) {
            float di = g_dinv[w];
            float4 b = ((const float4*)bias)[lane];
            float4 o;
            o.x = fmaxf(fmaf(di, acc.x, b.x), 0.f);
            o.y = fmaxf(fmaf(di, acc.y, b.y), 0.f);
            o.z = fmaxf(fmaf(di, acc.z, b.z), 0.f);
            o.w = fmaxf(fmaf(di, acc.w, b.w), 0.f);
            ((float4*)out)[w * M4 + lane] = o;
        }
    } else {
        float di = g_dinv[w];
        float4 v = make_float4(0.f, 0.f, 0.f, 0.f);
        if (act) {
            float4 b = ((const float4*)bias)[lane];
            v.x = fmaf(di, acc.x, b.x); v.y = fmaf(di, acc.y, b.y);
            v.z = fmaf(di, acc.z, b.z); v.w = fmaf(di, acc.w, b.w);
        }
        float m = act ? fmaxf(fmaxf(v.x, v.y), fmaxf(v.z, v.w)) : -3.4e38f;
#pragma unroll
        for (int o2 = 16; o2 > 0; o2 >>= 1)
            m = fmaxf(m, __shfl_xor_sync(0xffffffffu, m, o2));
        float se = act ? (expf(v.x - m) + expf(v.y - m) + expf(v.z - m) + expf(v.w - m)) : 0.f;
#pragma unroll
        for (int o2 = 16; o2 > 0; o2 >>= 1)
            se += __shfl_xor_sync(0xffffffffu, se, o2);
        float lse = m + logf(se);
        if (act) {
            float4 o;
            o.x = v.x - lse; o.y = v.y - lse; o.z = v.z - lse; o.w = v.w - lse;
            ((float4*)out)[w * M4 + lane] = o;
        }
    }
}

extern "C" void kernel_launch(void* const* d_in, const int* in_sizes, int n_in,
                              void* d_out, int out_size)
{
    const float* X     = (const float*)d_in[0];
    const int*   ei    = (const int*)  d_in[1];
    const float* W1    = (const float*)d_in[3];
    const float* b1    = (const float*)d_in[4];
    const float* g1    = (const float*)d_in[5];
    const float* be1   = (const float*)d_in[6];
    const float* W2    = (const float*)d_in[7];
    const float* b2    = (const float*)d_in[8];
    const float* g2    = (const float*)d_in[9];
    const float* be2   = (const float*)d_in[10];
    const float* Wrel  = (const float*)d_in[11];
    const float* Wself = (const float*)d_in[12];
    const float* rb    = (const float*)d_in[13];
    const float* c1W   = (const float*)d_in[14];
    const float* c1b   = (const float*)d_in[15];
    const float* c2W   = (const float*)d_in[16];
    const float* c2b   = (const float*)d_in[17];
    float* out = (float*)d_out;

    const int* src = ei;
    const int* tgt = ei + NE;

    float *B1, *B2, *B3, *B4;
    cudaGetSymbolAddress((void**)&B1, g_B1);
    cudaGetSymbolAddress((void**)&B2, g_B2);
    cudaGetSymbolAddress((void**)&B3, g_B3);
    cudaGetSymbolAddress((void**)&B4, g_B4);

    // Dynamic smem sizes
    const int SM_BIG  = 3 * (128 * 36 + 32 * 112) * 4;          // 98304
    const int SM_112  = (128 * 108 + 100 * 112) * 4;            // 100096
    const int SM_224  = (128 * 108 + 100 * 224) * 4;            // 144896
    const int SM_64   = (128 * 108 + 100 * 64) * 4;             // 80896

    cudaFuncSetAttribute(gemm_big_kernel,
                         cudaFuncAttributeMaxDynamicSharedMemorySize, SM_BIG);
    cudaFuncSetAttribute(gemm_small_kernel<112, 2>,
                         cudaFuncAttributeMaxDynamicSharedMemorySize, SM_112);
    cudaFuncSetAttribute(gemm_small_kernel<112, 3>,
                         cudaFuncAttributeMaxDynamicSharedMemorySize, SM_112);
    cudaFuncSetAttribute(gemm_small_kernel<224, 4>,
                         cudaFuncAttributeMaxDynamicSharedMemorySize, SM_224);
    cudaFuncSetAttribute(gemm_small_kernel<64, 3>,
                         cudaFuncAttributeMaxDynamicSharedMemorySize, SM_64);

    const int GB = (NN + 127) / 128;   // 391
    const int GGATHER = (NN * 32 + 255) / 256;

    // CSR build
    deg_zero_kernel <<<(NN / 4 + 255) / 256, 256>>>();
    deg_count_kernel<<<(NE / 4 + 255) / 256, 256>>>(tgt);
    scan_kernel     <<<1, 1024>>>();
    fill_kernel     <<<(NE / 4 + 255) / 256, 256>>>(src, tgt);

    // transform: (Linear -> LN -> ReLU) x2   (no transpose needed)
    gemm_big_kernel<<<GB, dim3(14, 16), SM_BIG>>>(X, W1, b1, g1, be1, B1);
    gemm_small_kernel<112, 2><<<GB, dim3(14, 16), SM_112>>>(
        B1, W2, nullptr, b2, g2, be2, B2, nullptr);

    // RGCN: fused self|rel GEMM, then gather
    gemm_small_kernel<224, 4><<<GB, dim3(28, 16), SM_224>>>(
        B2, Wself, Wrel, rb, nullptr, nullptr, B3, B4);
    gather_kernel<25, 0><<<GGATHER, 256>>>(B4, B3, nullptr, B1);

    // GCNConv1
    gemm_small_kernel<112, 3><<<GB, dim3(14, 16), SM_112>>>(
        B1, c1W, nullptr, nullptr, nullptr, nullptr, B2, nullptr);
    gather_kernel<25, 1><<<GGATHER, 256>>>(B2, nullptr, c1b, B3);

    // GCNConv2 (->64) + log_softmax
    gemm_small_kernel<64, 3><<<GB, dim3(8, 16), SM_64>>>(
        B3, c2W, nullptr, nullptr, nullptr, nullptr, B4, nullptr);
    gather_kernel<16, 2><<<GGATHER, 256>>>(B4, nullptr, c2b, out);
}

// round 8
// speedup vs baseline: 2.0054x; 1.0782x over previous
#include <cuda_runtime.h>
#include <math.h>

#define NN    50000
#define NE    800000
#define D_IN  500
#define D_HID 100
#define D_OUT 64

// Scratch (static __device__ — no runtime allocation).
__device__ float g_B1[NN * D_HID];
__device__ float g_B2[NN * D_HID];
__device__ float g_B3[NN * D_HID];
__device__ float g_B4[NN * D_HID];
__device__ float g_dinv[NN];
__device__ int   g_deg[NN];
__device__ int   g_off[NN + 1];
__device__ int   g_cur[NN];
__device__ int   g_el[NE];

// ---------------------------------------------------------------------------
// f32x2 packed helpers (Blackwell FFMA2 path)
// ---------------------------------------------------------------------------
__device__ __forceinline__ unsigned long long ffma2(unsigned long long a,
                                                    unsigned long long b,
                                                    unsigned long long c) {
    unsigned long long d;
    asm("fma.rn.f32x2 %0, %1, %2, %3;" : "=l"(d) : "l"(a), "l"(b), "l"(c));
    return d;
}
__device__ __forceinline__ unsigned long long dup2(float x) {
    unsigned long long d;
    asm("mov.b64 %0, {%1, %1};" : "=l"(d) : "r"(__float_as_uint(x)));
    return d;
}
__device__ __forceinline__ float2 unpack2(unsigned long long v) {
    unsigned int lo, hi;
    asm("mov.b64 {%0, %1}, %2;" : "=r"(lo), "=r"(hi) : "l"(v));
    float2 r; r.x = __uint_as_float(lo); r.y = __uint_as_float(hi);
    return r;
}
__device__ __forceinline__ unsigned int smem_u32(const void* p) {
    unsigned int a;
    asm("{ .reg .u64 t; cvta.to.shared.u64 t, %1; cvt.u32.u64 %0, t; }"
        : "=r"(a) : "l"(p));
    return a;
}
__device__ __forceinline__ void cp16(unsigned int s, const void* g, int srcsz) {
    asm volatile("cp.async.ca.shared.global [%0], [%1], 16, %2;"
                 :: "r"(s), "l"(g), "r"(srcsz));
}

// ---------------------------------------------------------------------------
// CSR construction
// ---------------------------------------------------------------------------
__global__ void deg_zero_kernel() {
    int i = blockIdx.x * blockDim.x + threadIdx.x;
    if (i < NN / 4) ((int4*)g_deg)[i] = make_int4(0, 0, 0, 0);
}
__global__ void deg_count_kernel(const int* __restrict__ tgt) {
    int base = (blockIdx.x * blockDim.x + threadIdx.x) * 4;
    if (base + 3 < NE) {
        int4 t = *(const int4*)(tgt + base);
        atomicAdd(&g_deg[t.x], 1);
        atomicAdd(&g_deg[t.y], 1);
        atomicAdd(&g_deg[t.z], 1);
        atomicAdd(&g_deg[t.w], 1);
    }
}
__global__ void scan_kernel() {
    __shared__ int warp_sums[32];
    const int tid = threadIdx.x;
    const int lane = tid & 31, wid = tid >> 5;
    int carry = 0;
    for (int base = 0; base < NN; base += 1024) {
        int i = base + tid;
        int v = (i < NN) ? g_deg[i] : 0;
        int x = v;
#pragma unroll
        for (int d = 1; d < 32; d <<= 1) {
            int t = __shfl_up_sync(0xffffffffu, x, d);
            if (lane >= d) x += t;
        }
        if (lane == 31) warp_sums[wid] = x;
        __syncthreads();
        if (wid == 0) {
            int s = warp_sums[lane];
#pragma unroll
            for (int d = 1; d < 32; d <<= 1) {
                int t = __shfl_up_sync(0xffffffffu, s, d);
                if (lane >= d) s += t;
            }
            warp_sums[lane] = s;
        }
        __syncthreads();
        int warp_prefix = (wid > 0) ? warp_sums[wid - 1] : 0;
        int incl = warp_prefix + x;
        if (i < NN) {
            g_off[i]  = carry + incl - v;
            g_dinv[i] = rsqrtf((float)(v + 1));
            g_cur[i]  = 0;
        }
        carry += warp_sums[31];
        __syncthreads();
    }
    if (tid == 0) g_off[NN] = carry;
}
__global__ void fill_kernel(const int* __restrict__ src, const int* __restrict__ tgt) {
    int base = (blockIdx.x * blockDim.x + threadIdx.x) * 4;
    if (base + 3 < NE) {
        int4 t = *(const int4*)(tgt + base);
        int4 s = *(const int4*)(src + base);
        int p0 = g_off[t.x] + atomicAdd(&g_cur[t.x], 1);
        int p1 = g_off[t.y] + atomicAdd(&g_cur[t.y], 1);
        int p2 = g_off[t.z] + atomicAdd(&g_cur[t.z], 1);
        int p3 = g_off[t.w] + atomicAdd(&g_cur[t.w], 1);
        g_el[p0] = s.x; g_el[p1] = s.y; g_el[p2] = s.z; g_el[p3] = s.w;
    }
}

// ---------------------------------------------------------------------------
// Big GEMM (K=500): C = X @ W1 + b1 -> LayerNorm -> ReLU
// Row-major A direct from X via cp.async. f32x2 pairs on N.
// BM=128, BK=32, block (14,16)=224, 3-stage pipeline. Vectorized A LDS (k4).
// ---------------------------------------------------------------------------
__global__ void __launch_bounds__(224)
gemm_big_kernel(const float* __restrict__ X,
                const float* __restrict__ W,
                const float* __restrict__ bias,
                const float* __restrict__ gamma,
                const float* __restrict__ beta,
                float* __restrict__ out)
{
    constexpr int AP = 36;    // sA row pitch (floats)
    constexpr int ASZ = 128 * AP;      // 4608
    constexpr int WSZ = 32 * 112;      // 3584
    extern __shared__ float sm[];
    float* sA = sm;                    // 3 stages x 4608
    float* sW = sm + 3 * ASZ;          // 3 stages x 3584
    const int tx = threadIdx.x, ty = threadIdx.y;
    const int tid = ty * 14 + tx;
    const int r0 = blockIdx.x * 128;
    const int NT = 16;                 // ceil(500/32)

    unsigned long long acc[8][4];
#pragma unroll
    for (int j = 0; j < 8; j++)
#pragma unroll
        for (int c = 0; c < 4; c++) acc[j][c] = 0ULL;

    auto load_tile = [&](int t, int s) {
        const int k0 = t * 32;
        float* dA = sA + s * ASZ;
        float* dW = sW + s * WSZ;
        for (int i = tid; i < 1024; i += 224) {
            int r = i >> 3, ch = i & 7;
            int row = r0 + r;
            int gk0 = k0 + ch * 4;
            bool ok = (row < NN) && (gk0 < D_IN);
            int rowa = ok ? row : 0;
            int gka  = ok ? gk0 : 0;
            cp16(smem_u32(dA + r * AP + ch * 4),
                 X + (size_t)rowa * D_IN + gka, ok ? 16 : 0);
        }
        for (int i = tid; i < 896; i += 224) {
            int kk = i / 28, c = (i % 28) * 4;
            int gk = k0 + kk;
            bool ok = (gk < D_IN) && (c < D_HID);
            int gka = ok ? gk : 0;
            int ca  = ok ? c : 0;
            cp16(smem_u32(dW + kk * 112 + c),
                 W + gka * D_HID + ca, ok ? 16 : 0);
        }
    };

    load_tile(0, 0);
    asm volatile("cp.async.commit_group;" ::: "memory");
    load_tile(1, 1);
    asm volatile("cp.async.commit_group;" ::: "memory");

    for (int t = 0; t < NT; t++) {
        if (t + 2 < NT) {
            load_tile(t + 2, (t + 2) % 3);
            asm volatile("cp.async.commit_group;" ::: "memory");
            asm volatile("cp.async.wait_group 2;" ::: "memory");
        } else if (t + 1 < NT) {
            asm volatile("cp.async.wait_group 1;" ::: "memory");
        } else {
            asm volatile("cp.async.wait_group 0;" ::: "memory");
        }
        __syncthreads();
        const float* cA = sA + (t % 3) * ASZ;
        const float* cW = sW + (t % 3) * WSZ;
        const float* aB  = cA + (ty * 4) * AP;
        const float* aB2 = cA + (64 + ty * 4) * AP;
#pragma unroll
        for (int k4 = 0; k4 < 32; k4 += 4) {
            float4 av[8];
#pragma unroll
            for (int j = 0; j < 4; j++) {
                av[j]     = *(const float4*)(aB  + j * AP + k4);
                av[j + 4] = *(const float4*)(aB2 + j * AP + k4);
            }
            const float* af = (const float*)av;
#pragma unroll
            for (int kk = 0; kk < 4; kk++) {
                ulonglong2 w0 = *(const ulonglong2*)(cW + (k4 + kk) * 112 + tx * 4);
                ulonglong2 w1 = *(const ulonglong2*)(cW + (k4 + kk) * 112 + 56 + tx * 4);
#pragma unroll
                for (int j = 0; j < 8; j++) {
                    unsigned long long ad = dup2(af[j * 4 + kk]);
                    acc[j][0] = ffma2(ad, w0.x, acc[j][0]);
                    acc[j][1] = ffma2(ad, w0.y, acc[j][1]);
                    acc[j][2] = ffma2(ad, w1.x, acc[j][2]);
                    acc[j][3] = ffma2(ad, w1.y, acc[j][3]);
                }
            }
        }
        __syncthreads();
    }

    // Epilogue: bias + LayerNorm + ReLU. sC[128][100] reuses smem.
    float* sC = sm;
#pragma unroll
    for (int j = 0; j < 8; j++) {
        int lr = (j < 4) ? (ty * 4 + j) : (64 + ty * 4 + (j - 4));
        int c0 = tx * 4;
        float2 p0 = unpack2(acc[j][0]);
        float2 p1 = unpack2(acc[j][1]);
        sC[lr * D_HID + c0 + 0] = p0.x + bias[c0 + 0];
        sC[lr * D_HID + c0 + 1] = p0.y + bias[c0 + 1];
        sC[lr * D_HID + c0 + 2] = p1.x + bias[c0 + 2];
        sC[lr * D_HID + c0 + 3] = p1.y + bias[c0 + 3];
        int c1 = 56 + tx * 4;
        if (c1 + 3 < D_HID) {
            float2 p2 = unpack2(acc[j][2]);
            float2 p3 = unpack2(acc[j][3]);
            sC[lr * D_HID + c1 + 0] = p2.x + bias[c1 + 0];
            sC[lr * D_HID + c1 + 1] = p2.y + bias[c1 + 1];
            sC[lr * D_HID + c1 + 2] = p3.x + bias[c1 + 2];
            sC[lr * D_HID + c1 + 3] = p3.y + bias[c1 + 3];
        }
    }
    __syncthreads();
    const int wid = tid >> 5, lane = tid & 31;
    for (int r = wid; r < 128; r += 7) {
        int row = r0 + r;
        float vals[4];
        float s = 0.f, sq = 0.f;
#pragma unroll
        for (int q = 0; q < 4; q++) {
            int c = lane + 32 * q;
            float v = (c < D_HID) ? sC[r * D_HID + c] : 0.f;
            vals[q] = v; s += v; sq += v * v;
        }
#pragma unroll
        for (int o2 = 16; o2 > 0; o2 >>= 1) {
            s  += __shfl_xor_sync(0xffffffffu, s,  o2);
            sq += __shfl_xor_sync(0xffffffffu, sq, o2);
        }
        float mean = s / D_HID;
        float var  = sq / D_HID - mean * mean;
        float rstd = rsqrtf(var + 1e-5f);
        if (row < NN) {
#pragma unroll
            for (int q = 0; q < 4; q++) {
                int c = lane + 32 * q;
                if (c < D_HID)
                    out[row * D_HID + c] =
                        fmaxf((vals[q] - mean) * rstd * gamma[c] + beta[c], 0.f);
            }
        }
    }
}

// ---------------------------------------------------------------------------
// Small GEMM (K=100, whole K in smem), f32x2 pairs on N, vectorized A LDS.
// NPAD: 112 (M=100), 224 (dual 100+100), 64 (M=64). Block (NPAD/8, 16).
// EPI: 2 = +bias,LN,ReLU | 3 = *dinv[row] | 4 = dual: out=A@Wa+rb, out2=A@Wb
// ---------------------------------------------------------------------------
template<int NPAD, int EPI>
__global__ void __launch_bounds__((NPAD/8)*16)
gemm_small_kernel(const float* __restrict__ A,
                  const float* __restrict__ Wa,
                  const float* __restrict__ Wb,
                  const float* __restrict__ bias,
                  const float* __restrict__ gamma,
                  const float* __restrict__ beta,
                  float* __restrict__ out,
                  float* __restrict__ out2)
{
    constexpr int TX = NPAD / 8, BLK = TX * 16, OFF1 = NPAD / 2;
    constexpr int KK = 100;
    constexpr int M = (NPAD == 64) ? 64 : 100;
    constexpr int AP = 108;   // sA pitch
    extern __shared__ float sm[];
    float* sA = sm;                // 128 x 108
    float* sW = sm + 128 * AP;     // 100 x NPAD
    const int tx = threadIdx.x, ty = threadIdx.y;
    const int tid = ty * TX + tx;
    const int r0 = blockIdx.x * 128;

    for (int i = tid; i < 128 * 25; i += BLK) {
        int r = i / 25, kq = i % 25;
        int row = r0 + r;
        float4 v = make_float4(0.f, 0.f, 0.f, 0.f);
        if (row < NN) v = *(const float4*)(A + row * 100 + kq * 4);
        *(float4*)(sA + r * AP + kq * 4) = v;
    }
    for (int i = tid; i < KK * (NPAD / 4); i += BLK) {
        int kk = i / (NPAD / 4), c = (i % (NPAD / 4)) * 4;
        float4 v = make_float4(0.f, 0.f, 0.f, 0.f);
        if (EPI == 4) {
            if (c < 100)                  v = *(const float4*)(Wa + kk * 100 + c);
            else if (c >= 112 && c < 212) v = *(const float4*)(Wb + kk * 100 + (c - 112));
        } else {
            if (c < M) v = *(const float4*)(Wa + kk * M + c);
        }
        *(float4*)(sW + kk * NPAD + c) = v;
    }
    __syncthreads();

    unsigned long long acc[8][4];
#pragma unroll
    for (int j = 0; j < 8; j++)
#pragma unroll
        for (int c = 0; c < 4; c++) acc[j][c] = 0ULL;

    const float* aB  = sA + (ty * 4) * AP;
    const float* aB2 = sA + (64 + ty * 4) * AP;
#pragma unroll 5
    for (int k4 = 0; k4 < KK; k4 += 4) {
        float4 av[8];
#pragma unroll
        for (int j = 0; j < 4; j++) {
            av[j]     = *(const float4*)(aB  + j * AP + k4);
            av[j + 4] = *(const float4*)(aB2 + j * AP + k4);
        }
        const float* af = (const float*)av;
#pragma unroll
        for (int kk = 0; kk < 4; kk++) {
            ulonglong2 w0 = *(const ulonglong2*)(sW + (k4 + kk) * NPAD + tx * 4);
            ulonglong2 w1 = *(const ulonglong2*)(sW + (k4 + kk) * NPAD + OFF1 + tx * 4);
#pragma unroll
            for (int j = 0; j < 8; j++) {
                unsigned long long ad = dup2(af[j * 4 + kk]);
                acc[j][0] = ffma2(ad, w0.x, acc[j][0]);
                acc[j][1] = ffma2(ad, w0.y, acc[j][1]);
                acc[j][2] = ffma2(ad, w1.x, acc[j][2]);
                acc[j][3] = ffma2(ad, w1.y, acc[j][3]);
            }
        }
    }

    if (EPI == 2) {
        __syncthreads();
        float* sC = sm;
#pragma unroll
        for (int j = 0; j < 8; j++) {
            int lr = (j < 4) ? (ty * 4 + j) : (64 + ty * 4 + (j - 4));
            int c0 = tx * 4;
            if (c0 + 3 < M) {
                float2 p0 = unpack2(acc[j][0]);
                float2 p1 = unpack2(acc[j][1]);
                sC[lr * M + c0 + 0] = p0.x + bias[c0 + 0];
                sC[lr * M + c0 + 1] = p0.y + bias[c0 + 1];
                sC[lr * M + c0 + 2] = p1.x + bias[c0 + 2];
                sC[lr * M + c0 + 3] = p1.y + bias[c0 + 3];
            }
            int c1 = OFF1 + tx * 4;
            if (c1 + 3 < M) {
                float2 p2 = unpack2(acc[j][2]);
                float2 p3 = unpack2(acc[j][3]);
                sC[lr * M + c1 + 0] = p2.x + bias[c1 + 0];
                sC[lr * M + c1 + 1] = p2.y + bias[c1 + 1];
                sC[lr * M + c1 + 2] = p3.x + bias[c1 + 2];
                sC[lr * M + c1 + 3] = p3.y + bias[c1 + 3];
            }
        }
        __syncthreads();
        const int wid = tid >> 5, lane = tid & 31;
        for (int r = wid; r < 128; r += BLK / 32) {
            int row = r0 + r;
            float vals[4];
            float s = 0.f, sq = 0.f;
#pragma unroll
            for (int q = 0; q < 4; q++) {
                int c = lane + 32 * q;
                float v = (c < M) ? sC[r * M + c] : 0.f;
                vals[q] = v; s += v; sq += v * v;
            }
#pragma unroll
            for (int o2 = 16; o2 > 0; o2 >>= 1) {
                s  += __shfl_xor_sync(0xffffffffu, s,  o2);
                sq += __shfl_xor_sync(0xffffffffu, sq, o2);
            }
            float mean = s / M;
            float var  = sq / M - mean * mean;
            float rstd = rsqrtf(var + 1e-5f);
            if (row < NN) {
#pragma unroll
                for (int q = 0; q < 4; q++) {
                    int c = lane + 32 * q;
                    if (c < M)
                        out[row * M + c] =
                            fmaxf((vals[q] - mean) * rstd * gamma[c] + beta[c], 0.f);
                }
            }
        }
    } else if (EPI == 3) {
#pragma unroll
        for (int j = 0; j < 8; j++) {
            int row = r0 + ((j < 4) ? (ty * 4 + j) : (64 + ty * 4 + (j - 4)));
            if (row >= NN) continue;
            float di = g_dinv[row];
            int c0 = tx * 4;
            if (c0 + 3 < M) {
                float2 p0 = unpack2(acc[j][0]);
                float2 p1 = unpack2(acc[j][1]);
                *(float4*)(out + row * M + c0) =
                    make_float4(di * p0.x, di * p0.y, di * p1.x, di * p1.y);
            }
            int c1 = OFF1 + tx * 4;
            if (c1 + 3 < M) {
                float2 p2 = unpack2(acc[j][2]);
                float2 p3 = unpack2(acc[j][3]);
                *(float4*)(out + row * M + c1) =
                    make_float4(di * p2.x, di * p2.y, di * p3.x, di * p3.y);
            }
        }
    } else {  // EPI == 4: dual output (NPAD=224), bias on first half
#pragma unroll
        for (int j = 0; j < 8; j++) {
            int row = r0 + ((j < 4) ? (ty * 4 + j) : (64 + ty * 4 + (j - 4)));
            if (row >= NN) continue;
            int c0 = tx * 4;
            if (c0 + 3 < 100) {
                float2 p0 = unpack2(acc[j][0]);
                float2 p1 = unpack2(acc[j][1]);
                float4 b = *(const float4*)(bias + c0);
                *(float4*)(out + row * 100 + c0) =
                    make_float4(p0.x + b.x, p0.y + b.y, p1.x + b.z, p1.y + b.w);
                float2 q0 = unpack2(acc[j][2]);
                float2 q1 = unpack2(acc[j][3]);
                *(float4*)(out2 + row * 100 + c0) =
                    make_float4(q0.x, q0.y, q1.x, q1.y);
            }
        }
    }
}

// ---------------------------------------------------------------------------
// Gather aggregation (warp per node), 4-way edge ILP. (unchanged)
// ---------------------------------------------------------------------------
template<int M4, int MODE>
__global__ void gather_kernel(const float* __restrict__ h,
                              const float* __restrict__ self,
                              const float* __restrict__ bias,
                              float* __restrict__ out)
{
    int w = (blockIdx.x * blockDim.x + threadIdx.x) >> 5;
    if (w >= NN) return;
    const int lane = threadIdx.x & 31;
    const bool act = lane < M4;
    const float4* h4 = (const float4*)h;

    float4 a0 = make_float4(0.f, 0.f, 0.f, 0.f);
    float4 a1 = a0, a2 = a0, a3 = a0;
    if (act) {
        if (MODE == 0) a0 = ((const float4*)self)[w * M4 + lane];
        else           a0 = h4[w * M4 + lane];
    }

    const int off = g_off[w];
    const int dg  = g_off[w + 1] - off;
    for (int base = 0; base < dg; base += 32) {
        int idx = base + lane;
        int myel = (idx < dg) ? g_el[off + idx] : 0;
        int cnt = dg - base; if (cnt > 32) cnt = 32;
        int j = 0;
        for (; j + 3 < cnt; j += 4) {
            int s0 = __shfl_sync(0xffffffffu, myel, j);
            int s1 = __shfl_sync(0xffffffffu, myel, j + 1);
            int s2 = __shfl_sync(0xffffffffu, myel, j + 2);
            int s3 = __shfl_sync(0xffffffffu, myel, j + 3);
            if (act) {
                float4 v0 = h4[s0 * M4 + lane];
                float4 v1 = h4[s1 * M4 + lane];
                float4 v2 = h4[s2 * M4 + lane];
                float4 v3 = h4[s3 * M4 + lane];
                a0.x += v0.x; a0.y += v0.y; a0.z += v0.z; a0.w += v0.w;
                a1.x += v1.x; a1.y += v1.y; a1.z += v1.z; a1.w += v1.w;
                a2.x += v2.x; a2.y += v2.y; a2.z += v2.z; a2.w += v2.w;
                a3.x += v3.x; a3.y += v3.y; a3.z += v3.z; a3.w += v3.w;
            }
        }
        for (; j < cnt; j++) {
            int s0 = __shfl_sync(0xffffffffu, myel, j);
            if (act) {
                float4 v0 = h4[s0 * M4 + lane];
                a0.x += v0.x; a0.y += v0.y; a0.z += v0.z; a0.w += v0.w;
            }
        }
    }
    float4 acc;
    acc.x = (a0.x + a1.x) + (a2.x + a3.x);
    acc.y = (a0.y + a1.y) + (a2.y + a3.y);
    acc.z = (a0.z + a1.z) + (a2.z + a3.z);
    acc.w = (a0.w + a1.w) + (a2.w + a3.w);

    if (MODE == 0) {
        if (act) {
            float4 o;
            o.x = fmaxf(acc.x, 0.f); o.y = fmaxf(acc.y, 0.f);
            o.z = fmaxf(acc.z, 0.f); o.w = fmaxf(acc.w, 0.f);
            ((float4*)out)[w * M4 + lane] = o;
        }
    } else if (MODE == 1) {
        if (act) {
            float di = g_dinv[w];
            float4 b = ((const float4*)bias)[lane];
            float4 o;
            o.x = fmaxf(fmaf(di, acc.x, b.x), 0.f);
            o.y = fmaxf(fmaf(di, acc.y, b.y), 0.f);
            o.z = fmaxf(fmaf(di, acc.z, b.z), 0.f);
            o.w = fmaxf(fmaf(di, acc.w, b.w), 0.f);
            ((float4*)out)[w * M4 + lane] = o;
        }
    } else {
        float di = g_dinv[w];
        float4 v = make_float4(0.f, 0.f, 0.f, 0.f);
        if (act) {
            float4 b = ((const float4*)bias)[lane];
            v.x = fmaf(di, acc.x, b.x); v.y = fmaf(di, acc.y, b.y);
            v.z = fmaf(di, acc.z, b.z); v.w = fmaf(di, acc.w, b.w);
        }
        float m = act ? fmaxf(fmaxf(v.x, v.y), fmaxf(v.z, v.w)) : -3.4e38f;
#pragma unroll
        for (int o2 = 16; o2 > 0; o2 >>= 1)
            m = fmaxf(m, __shfl_xor_sync(0xffffffffu, m, o2));
        float se = act ? (expf(v.x - m) + expf(v.y - m) + expf(v.z - m) + expf(v.w - m)) : 0.f;
#pragma unroll
        for (int o2 = 16; o2 > 0; o2 >>= 1)
            se += __shfl_xor_sync(0xffffffffu, se, o2);
        float lse = m + logf(se);
        if (act) {
            float4 o;
            o.x = v.x - lse; o.y = v.y - lse; o.z = v.z - lse; o.w = v.w - lse;
            ((float4*)out)[w * M4 + lane] = o;
        }
    }
}

extern "C" void kernel_launch(void* const* d_in, const int* in_sizes, int n_in,
                              void* d_out, int out_size)
{
    const float* X     = (const float*)d_in[0];
    const int*   ei    = (const int*)  d_in[1];
    const float* W1    = (const float*)d_in[3];
    const float* b1    = (const float*)d_in[4];
    const float* g1    = (const float*)d_in[5];
    const float* be1   = (const float*)d_in[6];
    const float* W2    = (const float*)d_in[7];
    const float* b2    = (const float*)d_in[8];
    const float* g2    = (const float*)d_in[9];
    const float* be2   = (const float*)d_in[10];
    const float* Wrel  = (const float*)d_in[11];
    const float* Wself = (const float*)d_in[12];
    const float* rb    = (const float*)d_in[13];
    const float* c1W   = (const float*)d_in[14];
    const float* c1b   = (const float*)d_in[15];
    const float* c2W   = (const float*)d_in[16];
    const float* c2b   = (const float*)d_in[17];
    float* out = (float*)d_out;

    const int* src = ei;
    const int* tgt = ei + NE;

    float *B1, *B2, *B3, *B4;
    cudaGetSymbolAddress((void**)&B1, g_B1);
    cudaGetSymbolAddress((void**)&B2, g_B2);
    cudaGetSymbolAddress((void**)&B3, g_B3);
    cudaGetSymbolAddress((void**)&B4, g_B4);

    const int SM_BIG  = 3 * (128 * 36 + 32 * 112) * 4;          // 98304
    const int SM_112  = (128 * 108 + 100 * 112) * 4;            // 100096
    const int SM_224  = (128 * 108 + 100 * 224) * 4;            // 144896
    const int SM_64   = (128 * 108 + 100 * 64) * 4;             // 80896

    cudaFuncSetAttribute(gemm_big_kernel,
                         cudaFuncAttributeMaxDynamicSharedMemorySize, SM_BIG);
    cudaFuncSetAttribute(gemm_small_kernel<112, 2>,
                         cudaFuncAttributeMaxDynamicSharedMemorySize, SM_112);
    cudaFuncSetAttribute(gemm_small_kernel<112, 3>,
                         cudaFuncAttributeMaxDynamicSharedMemorySize, SM_112);
    cudaFuncSetAttribute(gemm_small_kernel<224, 4>,
                         cudaFuncAttributeMaxDynamicSharedMemorySize, SM_224);
    cudaFuncSetAttribute(gemm_small_kernel<64, 3>,
                         cudaFuncAttributeMaxDynamicSharedMemorySize, SM_64);

    const int GB = (NN + 127) / 128;   // 391
    const int GGATHER = (NN * 32 + 255) / 256;

    // Fork a side stream for the CSR build so it overlaps the transform GEMMs.
    // Host resources are created/destroyed every call (deterministic, no
    // device allocation). Event record/wait encode the fork/join in the graph.
    cudaStream_t s2;
    cudaEvent_t evFork, evJoin;
    cudaStreamCreateWithFlags(&s2, cudaStreamNonBlocking);
    cudaEventCreateWithFlags(&evFork, cudaEventDisableTiming);
    cudaEventCreateWithFlags(&evJoin, cudaEventDisableTiming);

    cudaEventRecord(evFork, 0);
    cudaStreamWaitEvent(s2, evFork, 0);

    // CSR build on side stream (needed first by gather<25,0>)
    deg_zero_kernel <<<(NN / 4 + 255) / 256, 256, 0, s2>>>();
    deg_count_kernel<<<(NE / 4 + 255) / 256, 256, 0, s2>>>(tgt);
    scan_kernel     <<<1, 1024, 0, s2>>>();
    fill_kernel     <<<(NE / 4 + 255) / 256, 256, 0, s2>>>(src, tgt);
    cudaEventRecord(evJoin, s2);

    // Main stream: transform GEMMs (independent of CSR)
    gemm_big_kernel<<<GB, dim3(14, 16), SM_BIG>>>(X, W1, b1, g1, be1, B1);
    gemm_small_kernel<112, 2><<<GB, dim3(14, 16), SM_112>>>(
        B1, W2, nullptr, b2, g2, be2, B2, nullptr);
    gemm_small_kernel<224, 4><<<GB, dim3(28, 16), SM_224>>>(
        B2, Wself, Wrel, rb, nullptr, nullptr, B3, B4);

    // Join: gathers need the CSR (and g_dinv from scan)
    cudaStreamWaitEvent(0, evJoin, 0);
    gather_kernel<25, 0><<<GGATHER, 256>>>(B4, B3, nullptr, B1);

    // GCNConv1
    gemm_small_kernel<112, 3><<<GB, dim3(14, 16), SM_112>>>(
        B1, c1W, nullptr, nullptr, nullptr, nullptr, B2, nullptr);
    gather_kernel<25, 1><<<GGATHER, 256>>>(B2, nullptr, c1b, B3);

    // GCNConv2 (->64) + log_softmax
    gemm_small_kernel<64, 3><<<GB, dim3(8, 16), SM_64>>>(
        B3, c2W, nullptr, nullptr, nullptr, nullptr, B4, nullptr);
    gather_kernel<16, 2><<<GGATHER, 256>>>(B4, nullptr, c2b, out);

    cudaEventDestroy(evFork);
    cudaEventDestroy(evJoin);
    cudaStreamDestroy(s2);
}

// round 10
// speedup vs baseline: 2.3751x; 1.1844x over previous
#include <cuda_runtime.h>
#include <cuda_bf16.h>
#include <math.h>
#include <stdint.h>

#define NN    50000
#define NE    800000
#define D_IN  500
#define D_HID 100
#define D_OUT 64

__device__ float g_B1[NN * D_HID];
__device__ float g_B2[NN * D_HID];
__device__ float g_B3[NN * D_HID];
__device__ float g_B4[NN * D_HID];
__device__ float g_dinv[NN];
__device__ int   g_deg[NN];
__device__ int   g_off[NN + 1];
__device__ int   g_cur[NN];
__device__ int   g_el[NE];

// ---------------------------------------------------------------------------
// f32x2 packed helpers (FFMA2 path, small GEMMs)
// ---------------------------------------------------------------------------
__device__ __forceinline__ unsigned long long ffma2(unsigned long long a,
                                                    unsigned long long b,
                                                    unsigned long long c) {
    unsigned long long d;
    asm("fma.rn.f32x2 %0, %1, %2, %3;" : "=l"(d) : "l"(a), "l"(b), "l"(c));
    return d;
}
__device__ __forceinline__ unsigned long long dup2(float x) {
    unsigned long long d;
    asm("mov.b64 %0, {%1, %1};" : "=l"(d) : "r"(__float_as_uint(x)));
    return d;
}
__device__ __forceinline__ float2 unpack2(unsigned long long v) {
    unsigned int lo, hi;
    asm("mov.b64 {%0, %1}, %2;" : "=r"(lo), "=r"(hi) : "l"(v));
    float2 r; r.x = __uint_as_float(lo); r.y = __uint_as_float(hi);
    return r;
}
__device__ __forceinline__ unsigned int smem_u32(const void* p) {
    unsigned int a;
    asm("{ .reg .u64 t; cvta.to.shared.u64 t, %1; cvt.u32.u64 %0, t; }"
        : "=r"(a) : "l"(p));
    return a;
}

// ---------------------------------------------------------------------------
// mma.sync (base-ISA tensor path; compiles for plain compute_103)
// ---------------------------------------------------------------------------
__device__ __forceinline__ void ldsm4(uint32_t* r, uint32_t addr) {
    asm volatile("ldmatrix.sync.aligned.m8n8.x4.shared.b16 {%0,%1,%2,%3}, [%4];"
                 : "=r"(r[0]), "=r"(r[1]), "=r"(r[2]), "=r"(r[3]) : "r"(addr));
}
__device__ __forceinline__ void ldsm4t(uint32_t* r, uint32_t addr) {
    asm volatile("ldmatrix.sync.aligned.m8n8.x4.trans.shared.b16 {%0,%1,%2,%3}, [%4];"
                 : "=r"(r[0]), "=r"(r[1]), "=r"(r[2]), "=r"(r[3]) : "r"(addr));
}
__device__ __forceinline__ void mma16816(float* c, const uint32_t* a,
                                         uint32_t b0, uint32_t b1) {
    asm volatile(
        "mma.sync.aligned.m16n8k16.row.col.f32.bf16.bf16.f32 "
        "{%0,%1,%2,%3}, {%4,%5,%6,%7}, {%8,%9}, {%0,%1,%2,%3};"
        : "+f"(c[0]), "+f"(c[1]), "+f"(c[2]), "+f"(c[3])
        : "r"(a[0]), "r"(a[1]), "r"(a[2]), "r"(a[3]), "r"(b0), "r"(b1));
}
__device__ __forceinline__ uint32_t bfpack(float a, float b) {
    __nv_bfloat162 t = __floats2bfloat162_rn(a, b);
    return *(uint32_t*)&t;
}

// ---------------------------------------------------------------------------
// CSR construction (unchanged)
// ---------------------------------------------------------------------------
__global__ void deg_zero_kernel() {
    int i = blockIdx.x * blockDim.x + threadIdx.x;
    if (i < NN / 4) ((int4*)g_deg)[i] = make_int4(0, 0, 0, 0);
}
__global__ void deg_count_kernel(const int* __restrict__ tgt) {
    int base = (blockIdx.x * blockDim.x + threadIdx.x) * 4;
    if (base + 3 < NE) {
        int4 t = *(const int4*)(tgt + base);
        atomicAdd(&g_deg[t.x], 1);
        atomicAdd(&g_deg[t.y], 1);
        atomicAdd(&g_deg[t.z], 1);
        atomicAdd(&g_deg[t.w], 1);
    }
}
__global__ void scan_kernel() {
    __shared__ int warp_sums[32];
    const int tid = threadIdx.x;
    const int lane = tid & 31, wid = tid >> 5;
    int carry = 0;
    for (int base = 0; base < NN; base += 1024) {
        int i = base + tid;
        int v = (i < NN) ? g_deg[i] : 0;
        int x = v;
#pragma unroll
        for (int d = 1; d < 32; d <<= 1) {
            int t = __shfl_up_sync(0xffffffffu, x, d);
            if (lane >= d) x += t;
        }
        if (lane == 31) warp_sums[wid] = x;
        __syncthreads();
        if (wid == 0) {
            int s = warp_sums[lane];
#pragma unroll
            for (int d = 1; d < 32; d <<= 1) {
                int t = __shfl_up_sync(0xffffffffu, s, d);
                if (lane >= d) s += t;
            }
            warp_sums[lane] = s;
        }
        __syncthreads();
        int warp_prefix = (wid > 0) ? warp_sums[wid - 1] : 0;
        int incl = warp_prefix + x;
        if (i < NN) {
            g_off[i]  = carry + incl - v;
            g_dinv[i] = rsqrtf((float)(v + 1));
            g_cur[i]  = 0;
        }
        carry += warp_sums[31];
        __syncthreads();
    }
    if (tid == 0) g_off[NN] = carry;
}
__global__ void fill_kernel(const int* __restrict__ src, const int* __restrict__ tgt) {
    int base = (blockIdx.x * blockDim.x + threadIdx.x) * 4;
    if (base + 3 < NE) {
        int4 t = *(const int4*)(tgt + base);
        int4 s = *(const int4*)(src + base);
        int p0 = g_off[t.x] + atomicAdd(&g_cur[t.x], 1);
        int p1 = g_off[t.y] + atomicAdd(&g_cur[t.y], 1);
        int p2 = g_off[t.z] + atomicAdd(&g_cur[t.z], 1);
        int p3 = g_off[t.w] + atomicAdd(&g_cur[t.w], 1);
        g_el[p0] = s.x; g_el[p1] = s.y; g_el[p2] = s.z; g_el[p3] = s.w;
    }
}

// ---------------------------------------------------------------------------
// Big GEMM via mma.sync bf16 split: C = X @ W1 + b1 -> LayerNorm -> ReLU
// Split-bf16 hi/lo: D = Ah*Bh + Ah*Bl + Al*Bh (fp32 accum).
// 256 threads (8 warps), BM=128 (warp strip 16), N=112 (100 valid),
// K padded to 512, chunks of 16 with LDG prefetch.
// smem (bytes): AHI [128x24 bf16]=6144, ALO=6144, BHI [16x120 bf16]=3840,
// BLO=3840 (total 19968); epilogue reuses as sC[128][100] f32 (51200).
// ---------------------------------------------------------------------------
#define MB_AHI 0
#define MB_ALO 6144
#define MB_BHI 12288
#define MB_BLO 16128
#define MB_SMEM 51200

__global__ void __launch_bounds__(256)
gemm_big_mma(const float* __restrict__ X,
             const float* __restrict__ W,
             const float* __restrict__ bias,
             const float* __restrict__ gamma,
             const float* __restrict__ beta,
             float* __restrict__ out)
{
    extern __shared__ char smx[];
    const uint32_t sb = smem_u32(smx);
    const int tid = threadIdx.x;
    const int wid = tid >> 5, lane = tid & 31;
    const int r0 = blockIdx.x * 128;
    const int m0 = wid * 16;

    float acc[56];
#pragma unroll
    for (int i = 0; i < 56; i++) acc[i] = 0.f;

    float4 ax0, ax1, wq0, wq1;
    const int ar = tid >> 1, akc = (tid & 1) * 8;

    auto load_chunk = [&](int t) {
        const int k0 = t * 16;
        // A: thread -> row ar, k offset akc..akc+7
        int row = r0 + ar;
        const float* xp = X + (size_t)row * D_IN + k0 + akc;
        if (row < NN && k0 + akc + 8 <= D_IN) {
            ax0 = *(const float4*)xp;
            ax1 = *(const float4*)(xp + 4);
        } else {
            float tv[8];
#pragma unroll
            for (int j = 0; j < 8; j++)
                tv[j] = (row < NN && k0 + akc + j < D_IN) ? xp[j] : 0.f;
            ax0 = make_float4(tv[0], tv[1], tv[2], tv[3]);
            ax1 = make_float4(tv[4], tv[5], tv[6], tv[7]);
        }
        // W: slots tid and tid+256 over 16x28 float4 slots
        {
            int k = tid / 28, c = (tid % 28) * 4;
            wq0 = (k0 + k < D_IN && c < D_HID)
                ? *(const float4*)(W + (size_t)(k0 + k) * D_HID + c)
                : make_float4(0.f, 0.f, 0.f, 0.f);
        }
        if (tid < 192) {
            int s1 = tid + 256;
            int k = s1 / 28, c = (s1 % 28) * 4;
            wq1 = (k0 + k < D_IN && c < D_HID)
                ? *(const float4*)(W + (size_t)(k0 + k) * D_HID + c)
                : make_float4(0.f, 0.f, 0.f, 0.f);
        }
    };

    auto sts_chunk = [&]() {
        // A hi/lo, 8 values -> 4 packed uint32 each, one 16B STS each
        float xv[8] = {ax0.x, ax0.y, ax0.z, ax0.w, ax1.x, ax1.y, ax1.z, ax1.w};
        uint32_t ph[4], pl[4];
#pragma unroll
        for (int j = 0; j < 4; j++) {
            float f0 = xv[2 * j], f1 = xv[2 * j + 1];
            __nv_bfloat16 h0 = __float2bfloat16(f0);
            __nv_bfloat16 h1 = __float2bfloat16(f1);
            float l0 = f0 - __bfloat162float(h0);
            float l1 = f1 - __bfloat162float(h1);
            ph[j] = bfpack(__bfloat162float(h0), __bfloat162float(h1));
            pl[j] = bfpack(l0, l1);
        }
        uint32_t aoff = (uint32_t)(ar * 48 + akc * 2);
        *(uint4*)(smx + MB_AHI + aoff) = make_uint4(ph[0], ph[1], ph[2], ph[3]);
        *(uint4*)(smx + MB_ALO + aoff) = make_uint4(pl[0], pl[1], pl[2], pl[3]);
        // W hi/lo
        {
            int k = tid / 28, c = (tid % 28) * 4;
            float f[4] = {wq0.x, wq0.y, wq0.z, wq0.w};
            uint32_t h0, h1, l0, l1;
            __nv_bfloat16 b0 = __float2bfloat16(f[0]), b1 = __float2bfloat16(f[1]);
            __nv_bfloat16 b2 = __float2bfloat16(f[2]), b3 = __float2bfloat16(f[3]);
            h0 = bfpack(__bfloat162float(b0), __bfloat162float(b1));
            h1 = bfpack(__bfloat162float(b2), __bfloat162float(b3));
            l0 = bfpack(f[0] - __bfloat162float(b0), f[1] - __bfloat162float(b1));
            l1 = bfpack(f[2] - __bfloat162float(b2), f[3] - __bfloat162float(b3));
            uint32_t boff = (uint32_t)(k * 240 + c * 2);
            *(uint2*)(smx + MB_BHI + boff) = make_uint2(h0, h1);
            *(uint2*)(smx + MB_BLO + boff) = make_uint2(l0, l1);
        }
        if (tid < 192) {
            int s1 = tid + 256;
            int k = s1 / 28, c = (s1 % 28) * 4;
            float f[4] = {wq1.x, wq1.y, wq1.z, wq1.w};
            __nv_bfloat16 b0 = __float2bfloat16(f[0]), b1 = __float2bfloat16(f[1]);
            __nv_bfloat16 b2 = __float2bfloat16(f[2]), b3 = __float2bfloat16(f[3]);
            uint32_t h0 = bfpack(__bfloat162float(b0), __bfloat162float(b1));
            uint32_t h1 = bfpack(__bfloat162float(b2), __bfloat162float(b3));
            uint32_t l0 = bfpack(f[0] - __bfloat162float(b0), f[1] - __bfloat162float(b1));
            uint32_t l1 = bfpack(f[2] - __bfloat162float(b2), f[3] - __bfloat162float(b3));
            uint32_t boff = (uint32_t)(k * 240 + c * 2);
            *(uint2*)(smx + MB_BHI + boff) = make_uint2(h0, h1);
            *(uint2*)(smx + MB_BLO + boff) = make_uint2(l0, l1);
        }
    };

    // A-frag ldmatrix address (row-major, x4): row = lane&15, colhalf = lane>>4
    const uint32_t a_addr_off =
        (uint32_t)((m0 + (lane & 15)) * 48 + (lane >> 4) * 16);
    // B-frag ldmatrix address (trans, x4): k = lane&15, nhalf = lane>>4
    const uint32_t b_addr_row = (uint32_t)((lane & 15) * 240 + (lane >> 4) * 16);

    load_chunk(0);
    for (int t = 0; t < 32; t++) {
        __syncthreads();
        sts_chunk();
        __syncthreads();
        if (t + 1 < 32) load_chunk(t + 1);

        uint32_t ah[4], al[4];
        ldsm4(ah, sb + MB_AHI + a_addr_off);
        ldsm4(al, sb + MB_ALO + a_addr_off);
#pragma unroll
        for (int p = 0; p < 7; p++) {
            uint32_t bh[4], bl[4];
            uint32_t bo = b_addr_row + (uint32_t)(p * 32);
            ldsm4t(bh, sb + MB_BHI + bo);
            ldsm4t(bl, sb + MB_BLO + bo);
#pragma unroll
            for (int h = 0; h < 2; h++) {
                float* c = &acc[p * 8 + h * 4];
                mma16816(c, ah, bh[2 * h], bh[2 * h + 1]);
                mma16816(c, ah, bl[2 * h], bl[2 * h + 1]);
                mma16816(c, al, bh[2 * h], bh[2 * h + 1]);
            }
        }
    }

    // Epilogue: acc -> sC (+bias), then LayerNorm + ReLU
    __syncthreads();
    float* sC = (float*)smx;
#pragma unroll
    for (int p = 0; p < 7; p++) {
#pragma unroll
        for (int h = 0; h < 2; h++) {
            int n0 = p * 16 + h * 8;
            int col = n0 + (lane & 3) * 2;
            if (col < D_HID) {
                int rA = m0 + (lane >> 2);
                float b0v = bias[col], b1v = bias[col + 1];
                const float* c = &acc[p * 8 + h * 4];
                sC[rA * D_HID + col]           = c[0] + b0v;
                sC[rA * D_HID + col + 1]       = c[1] + b1v;
                sC[(rA + 8) * D_HID + col]     = c[2] + b0v;
                sC[(rA + 8) * D_HID + col + 1] = c[3] + b1v;
            }
        }
    }
    __syncthreads();
    for (int r = wid; r < 128; r += 8) {
        int row = r0 + r;
        float vals[4];
        float s = 0.f, sq = 0.f;
#pragma unroll
        for (int q = 0; q < 4; q++) {
            int c = lane + 32 * q;
            float v = (c < D_HID) ? sC[r * D_HID + c] : 0.f;
            vals[q] = v; s += v; sq += v * v;
        }
#pragma unroll
        for (int o2 = 16; o2 > 0; o2 >>= 1) {
            s  += __shfl_xor_sync(0xffffffffu, s,  o2);
            sq += __shfl_xor_sync(0xffffffffu, sq, o2);
        }
        float mean = s / D_HID;
        float var  = sq / D_HID - mean * mean;
        float rstd = rsqrtf(var + 1e-5f);
        if (row < NN) {
#pragma unroll
            for (int q = 0; q < 4; q++) {
                int c = lane + 32 * q;
                if (c < D_HID)
                    out[row * D_HID + c] =
                        fmaxf((vals[q] - mean) * rstd * gamma[c] + beta[c], 0.f);
            }
        }
    }
}

// ---------------------------------------------------------------------------
// Small GEMM (K=100, whole K in smem), f32x2 pairs on N, vectorized A LDS.
// (unchanged from R8 winner)
// ---------------------------------------------------------------------------
template<int NPAD, int EPI>
__global__ void __launch_bounds__((NPAD/8)*16)
gemm_small_kernel(const float* __restrict__ A,
                  const float* __restrict__ Wa,
                  const float* __restrict__ Wb,
                  const float* __restrict__ bias,
                  const float* __restrict__ gamma,
                  const float* __restrict__ beta,
                  float* __restrict__ out,
                  float* __restrict__ out2)
{
    constexpr int TX = NPAD / 8, BLK = TX * 16, OFF1 = NPAD / 2;
    constexpr int KK = 100;
    constexpr int M = (NPAD == 64) ? 64 : 100;
    constexpr int AP = 108;
    extern __shared__ float sm[];
    float* sA = sm;
    float* sW = sm + 128 * AP;
    const int tx = threadIdx.x, ty = threadIdx.y;
    const int tid = ty * TX + tx;
    const int r0 = blockIdx.x * 128;

    for (int i = tid; i < 128 * 25; i += BLK) {
        int r = i / 25, kq = i % 25;
        int row = r0 + r;
        float4 v = make_float4(0.f, 0.f, 0.f, 0.f);
        if (row < NN) v = *(const float4*)(A + row * 100 + kq * 4);
        *(float4*)(sA + r * AP + kq * 4) = v;
    }
    for (int i = tid; i < KK * (NPAD / 4); i += BLK) {
        int kk = i / (NPAD / 4), c = (i % (NPAD / 4)) * 4;
        float4 v = make_float4(0.f, 0.f, 0.f, 0.f);
        if (EPI == 4) {
            if (c < 100)                  v = *(const float4*)(Wa + kk * 100 + c);
            else if (c >= 112 && c < 212) v = *(const float4*)(Wb + kk * 100 + (c - 112));
        } else {
            if (c < M) v = *(const float4*)(Wa + kk * M + c);
        }
        *(float4*)(sW + kk * NPAD + c) = v;
    }
    __syncthreads();

    unsigned long long acc[8][4];
#pragma unroll
    for (int j = 0; j < 8; j++)
#pragma unroll
        for (int c = 0; c < 4; c++) acc[j][c] = 0ULL;

    const float* aB  = sA + (ty * 4) * AP;
    const float* aB2 = sA + (64 + ty * 4) * AP;
#pragma unroll 5
    for (int k4 = 0; k4 < KK; k4 += 4) {
        float4 av[8];
#pragma unroll
        for (int j = 0; j < 4; j++) {
            av[j]     = *(const float4*)(aB  + j * AP + k4);
            av[j + 4] = *(const float4*)(aB2 + j * AP + k4);
        }
        const float* af = (const float*)av;
#pragma unroll
        for (int kk = 0; kk < 4; kk++) {
            ulonglong2 w0 = *(const ulonglong2*)(sW + (k4 + kk) * NPAD + tx * 4);
            ulonglong2 w1 = *(const ulonglong2*)(sW + (k4 + kk) * NPAD + OFF1 + tx * 4);
#pragma unroll
            for (int j = 0; j < 8; j++) {
                unsigned long long ad = dup2(af[j * 4 + kk]);
                acc[j][0] = ffma2(ad, w0.x, acc[j][0]);
                acc[j][1] = ffma2(ad, w0.y, acc[j][1]);
                acc[j][2] = ffma2(ad, w1.x, acc[j][2]);
                acc[j][3] = ffma2(ad, w1.y, acc[j][3]);
            }
        }
    }

    if (EPI == 2) {
        __syncthreads();
        float* sC = sm;
#pragma unroll
        for (int j = 0; j < 8; j++) {
            int lr = (j < 4) ? (ty * 4 + j) : (64 + ty * 4 + (j - 4));
            int c0 = tx * 4;
            if (c0 + 3 < M) {
                float2 p0 = unpack2(acc[j][0]);
                float2 p1 = unpack2(acc[j][1]);
                sC[lr * M + c0 + 0] = p0.x + bias[c0 + 0];
                sC[lr * M + c0 + 1] = p0.y + bias[c0 + 1];
                sC[lr * M + c0 + 2] = p1.x + bias[c0 + 2];
                sC[lr * M + c0 + 3] = p1.y + bias[c0 + 3];
            }
            int c1 = OFF1 + tx * 4;
            if (c1 + 3 < M) {
                float2 p2 = unpack2(acc[j][2]);
                float2 p3 = unpack2(acc[j][3]);
                sC[lr * M + c1 + 0] = p2.x + bias[c1 + 0];
                sC[lr * M + c1 + 1] = p2.y + bias[c1 + 1];
                sC[lr * M + c1 + 2] = p3.x + bias[c1 + 2];
                sC[lr * M + c1 + 3] = p3.y + bias[c1 + 3];
            }
        }
        __syncthreads();
        const int wid = tid >> 5, lane = tid & 31;
        for (int r = wid; r < 128; r += BLK / 32) {
            int row = r0 + r;
            float vals[4];
            float s = 0.f, sq = 0.f;
#pragma unroll
            for (int q = 0; q < 4; q++) {
                int c = lane + 32 * q;
                float v = (c < M) ? sC[r * M + c] : 0.f;
                vals[q] = v; s += v; sq += v * v;
            }
#pragma unroll
            for (int o2 = 16; o2 > 0; o2 >>= 1) {
                s  += __shfl_xor_sync(0xffffffffu, s,  o2);
                sq += __shfl_xor_sync(0xffffffffu, sq, o2);
            }
            float mean = s / M;
            float var  = sq / M - mean * mean;
            float rstd = rsqrtf(var + 1e-5f);
            if (row < NN) {
#pragma unroll
                for (int q = 0; q < 4; q++) {
                    int c = lane + 32 * q;
                    if (c < M)
                        out[row * M + c] =
                            fmaxf((vals[q] - mean) * rstd * gamma[c] + beta[c], 0.f);
                }
            }
        }
    } else if (EPI == 3) {
#pragma unroll
        for (int j = 0; j < 8; j++) {
            int row = r0 + ((j < 4) ? (ty * 4 + j) : (64 + ty * 4 + (j - 4)));
            if (row >= NN) continue;
            float di = g_dinv[row];
            int c0 = tx * 4;
            if (c0 + 3 < M) {
                float2 p0 = unpack2(acc[j][0]);
                float2 p1 = unpack2(acc[j][1]);
                *(float4*)(out + row * M + c0) =
                    make_float4(di * p0.x, di * p0.y, di * p1.x, di * p1.y);
            }
            int c1 = OFF1 + tx * 4;
            if (c1 + 3 < M) {
                float2 p2 = unpack2(acc[j][2]);
                float2 p3 = unpack2(acc[j][3]);
                *(float4*)(out + row * M + c1) =
                    make_float4(di * p2.x, di * p2.y, di * p3.x, di * p3.y);
            }
        }
    } else {
#pragma unroll
        for (int j = 0; j < 8; j++) {
            int row = r0 + ((j < 4) ? (ty * 4 + j) : (64 + ty * 4 + (j - 4)));
            if (row >= NN) continue;
            int c0 = tx * 4;
            if (c0 + 3 < 100) {
                float2 p0 = unpack2(acc[j][0]);
                float2 p1 = unpack2(acc[j][1]);
                float4 b = *(const float4*)(bias + c0);
                *(float4*)(out + row * 100 + c0) =
                    make_float4(p0.x + b.x, p0.y + b.y, p1.x + b.z, p1.y + b.w);
                float2 q0 = unpack2(acc[j][2]);
                float2 q1 = unpack2(acc[j][3]);
                *(float4*)(out2 + row * 100 + c0) =
                    make_float4(q0.x, q0.y, q1.x, q1.y);
            }
        }
    }
}

// ---------------------------------------------------------------------------
// Gather aggregation (warp per node), 4-way edge ILP. (unchanged)
// ---------------------------------------------------------------------------
template<int M4, int MODE>
__global__ void gather_kernel(const float* __restrict__ h,
                              const float* __restrict__ self,
                              const float* __restrict__ bias,
                              float* __restrict__ out)
{
    int w = (blockIdx.x * blockDim.x + threadIdx.x) >> 5;
    if (w >= NN) return;
    const int lane = threadIdx.x & 31;
    const bool act = lane < M4;
    const float4* h4 = (const float4*)h;

    float4 a0 = make_float4(0.f, 0.f, 0.f, 0.f);
    float4 a1 = a0, a2 = a0, a3 = a0;
    if (act) {
        if (MODE == 0) a0 = ((const float4*)self)[w * M4 + lane];
        else           a0 = h4[w * M4 + lane];
    }

    const int off = g_off[w];
    const int dg  = g_off[w + 1] - off;
    for (int base = 0; base < dg; base += 32) {
        int idx = base + lane;
        int myel = (idx < dg) ? g_el[off + idx] : 0;
        int cnt = dg - base; if (cnt > 32) cnt = 32;
        int j = 0;
        for (; j + 3 < cnt; j += 4) {
            int s0 = __shfl_sync(0xffffffffu, myel, j);
            int s1 = __shfl_sync(0xffffffffu, myel, j + 1);
            int s2 = __shfl_sync(0xffffffffu, myel, j + 2);
            int s3 = __shfl_sync(0xffffffffu, myel, j + 3);
            if (act) {
                float4 v0 = h4[s0 * M4 + lane];
                float4 v1 = h4[s1 * M4 + lane];
                float4 v2 = h4[s2 * M4 + lane];
                float4 v3 = h4[s3 * M4 + lane];
                a0.x += v0.x; a0.y += v0.y; a0.z += v0.z; a0.w += v0.w;
                a1.x += v1.x; a1.y += v1.y; a1.z += v1.z; a1.w += v1.w;
                a2.x += v2.x; a2.y += v2.y; a2.z += v2.z; a2.w += v2.w;
                a3.x += v3.x; a3.y += v3.y; a3.z += v3.z; a3.w += v3.w;
            }
        }
        for (; j < cnt; j++) {
            int s0 = __shfl_sync(0xffffffffu, myel, j);
            if (act) {
                float4 v0 = h4[s0 * M4 + lane];
                a0.x += v0.x; a0.y += v0.y; a0.z += v0.z; a0.w += v0.w;
            }
        }
    }
    float4 acc;
    acc.x = (a0.x + a1.x) + (a2.x + a3.x);
    acc.y = (a0.y + a1.y) + (a2.y + a3.y);
    acc.z = (a0.z + a1.z) + (a2.z + a3.z);
    acc.w = (a0.w + a1.w) + (a2.w + a3.w);

    if (MODE == 0) {
        if (act) {
            float4 o;
            o.x = fmaxf(acc.x, 0.f); o.y = fmaxf(acc.y, 0.f);
            o.z = fmaxf(acc.z, 0.f); o.w = fmaxf(acc.w, 0.f);
            ((float4*)out)[w * M4 + lane] = o;
        }
    } else if (MODE == 1) {
        if (act) {
            float di = g_dinv[w];
            float4 b = ((const float4*)bias)[lane];
            float4 o;
            o.x = fmaxf(fmaf(di, acc.x, b.x), 0.f);
            o.y = fmaxf(fmaf(di, acc.y, b.y), 0.f);
            o.z = fmaxf(fmaf(di, acc.z, b.z), 0.f);
            o.w = fmaxf(fmaf(di, acc.w, b.w), 0.f);
            ((float4*)out)[w * M4 + lane] = o;
        }
    } else {
        float di = g_dinv[w];
        float4 v = make_float4(0.f, 0.f, 0.f, 0.f);
        if (act) {
            float4 b = ((const float4*)bias)[lane];
            v.x = fmaf(di, acc.x, b.x); v.y = fmaf(di, acc.y, b.y);
            v.z = fmaf(di, acc.z, b.z); v.w = fmaf(di, acc.w, b.w);
        }
        float m = act ? fmaxf(fmaxf(v.x, v.y), fmaxf(v.z, v.w)) : -3.4e38f;
#pragma unroll
        for (int o2 = 16; o2 > 0; o2 >>= 1)
            m = fmaxf(m, __shfl_xor_sync(0xffffffffu, m, o2));
        float se = act ? (expf(v.x - m) + expf(v.y - m) + expf(v.z - m) + expf(v.w - m)) : 0.f;
#pragma unroll
        for (int o2 = 16; o2 > 0; o2 >>= 1)
            se += __shfl_xor_sync(0xffffffffu, se, o2);
        float lse = m + logf(se);
        if (act) {
            float4 o;
            o.x = v.x - lse; o.y = v.y - lse; o.z = v.z - lse; o.w = v.w - lse;
            ((float4*)out)[w * M4 + lane] = o;
        }
    }
}

extern "C" void kernel_launch(void* const* d_in, const int* in_sizes, int n_in,
                              void* d_out, int out_size)
{
    const float* X     = (const float*)d_in[0];
    const int*   ei    = (const int*)  d_in[1];
    const float* W1    = (const float*)d_in[3];
    const float* b1    = (const float*)d_in[4];
    const float* g1    = (const float*)d_in[5];
    const float* be1   = (const float*)d_in[6];
    const float* W2    = (const float*)d_in[7];
    const float* b2    = (const float*)d_in[8];
    const float* g2    = (const float*)d_in[9];
    const float* be2   = (const float*)d_in[10];
    const float* Wrel  = (const float*)d_in[11];
    const float* Wself = (const float*)d_in[12];
    const float* rb    = (const float*)d_in[13];
    const float* c1W   = (const float*)d_in[14];
    const float* c1b   = (const float*)d_in[15];
    const float* c2W   = (const float*)d_in[16];
    const float* c2b   = (const float*)d_in[17];
    float* out = (float*)d_out;

    const int* src = ei;
    const int* tgt = ei + NE;

    float *B1, *B2, *B3, *B4;
    cudaGetSymbolAddress((void**)&B1, g_B1);
    cudaGetSymbolAddress((void**)&B2, g_B2);
    cudaGetSymbolAddress((void**)&B3, g_B3);
    cudaGetSymbolAddress((void**)&B4, g_B4);

    const int SM_112  = (128 * 108 + 100 * 112) * 4;             // 100096
    const int SM_224  = (128 * 108 + 100 * 224) * 4;             // 144896
    const int SM_64   = (128 * 108 + 100 * 64) * 4;              // 80896

    cudaFuncSetAttribute(gemm_big_mma,
                         cudaFuncAttributeMaxDynamicSharedMemorySize, MB_SMEM);
    cudaFuncSetAttribute(gemm_small_kernel<112, 2>,
                         cudaFuncAttributeMaxDynamicSharedMemorySize, SM_112);
    cudaFuncSetAttribute(gemm_small_kernel<112, 3>,
                         cudaFuncAttributeMaxDynamicSharedMemorySize, SM_112);
    cudaFuncSetAttribute(gemm_small_kernel<224, 4>,
                         cudaFuncAttributeMaxDynamicSharedMemorySize, SM_224);
    cudaFuncSetAttribute(gemm_small_kernel<64, 3>,
                         cudaFuncAttributeMaxDynamicSharedMemorySize, SM_64);

    const int GB = (NN + 127) / 128;   // 391
    const int GGATHER = (NN * 32 + 255) / 256;

    // Fork a side stream for the CSR build (overlaps the transform GEMMs).
    cudaStream_t s2;
    cudaEvent_t evFork, evJoin;
    cudaStreamCreateWithFlags(&s2, cudaStreamNonBlocking);
    cudaEventCreateWithFlags(&evFork, cudaEventDisableTiming);
    cudaEventCreateWithFlags(&evJoin, cudaEventDisableTiming);

    cudaEventRecord(evFork, 0);
    cudaStreamWaitEvent(s2, evFork, 0);

    deg_zero_kernel <<<(NN / 4 + 255) / 256, 256, 0, s2>>>();
    deg_count_kernel<<<(NE / 4 + 255) / 256, 256, 0, s2>>>(tgt);
    scan_kernel     <<<1, 1024, 0, s2>>>();
    fill_kernel     <<<(NE / 4 + 255) / 256, 256, 0, s2>>>(src, tgt);
    cudaEventRecord(evJoin, s2);

    // transform: (Linear -> LN -> ReLU) x2; layer 1 on mma.sync tensor path
    gemm_big_mma<<<GB, 256, MB_SMEM>>>(X, W1, b1, g1, be1, B1);
    gemm_small_kernel<112, 2><<<GB, dim3(14, 16), SM_112>>>(
        B1, W2, nullptr, b2, g2, be2, B2, nullptr);

    // RGCN: fused self|rel GEMM, then gather
    gemm_small_kernel<224, 4><<<GB, dim3(28, 16), SM_224>>>(
        B2, Wself, Wrel, rb, nullptr, nullptr, B3, B4);

    cudaStreamWaitEvent(0, evJoin, 0);
    gather_kernel<25, 0><<<GGATHER, 256>>>(B4, B3, nullptr, B1);

    // GCNConv1
    gemm_small_kernel<112, 3><<<GB, dim3(14, 16), SM_112>>>(
        B1, c1W, nullptr, nullptr, nullptr, nullptr, B2, nullptr);
    gather_kernel<25, 1><<<GGATHER, 256>>>(B2, nullptr, c1b, B3);

    // GCNConv2 (->64) + log_softmax
    gemm_small_kernel<64, 3><<<GB, dim3(8, 16), SM_64>>>(
        B3, c2W, nullptr, nullptr, nullptr, nullptr, B4, nullptr);
    gather_kernel<16, 2><<<GGATHER, 256>>>(B4, nullptr, c2b, out);

    cudaEventDestroy(evFork);
    cudaEventDestroy(evJoin);
    cudaStreamDestroy(s2);
}

// round 11
// speedup vs baseline: 2.5743x; 1.0839x over previous
#include <cuda_runtime.h>
#include <cuda_bf16.h>
#include <math.h>
#include <stdint.h>

#define NN    50000
#define NE    800000
#define D_IN  500
#define D_HID 100
#define D_OUT 64

__device__ float g_B1[NN * D_HID];
__device__ float g_B2[NN * D_HID];
__device__ float g_B3[NN * D_HID];
__device__ float g_B4[NN * D_HID];
__device__ float g_dinv[NN];
__device__ int   g_deg[NN];
__device__ int   g_off[NN + 1];
__device__ int   g_cur[NN];
__device__ int   g_el[NE];

__device__ __forceinline__ unsigned int smem_u32(const void* p) {
    unsigned int a;
    asm("{ .reg .u64 t; cvta.to.shared.u64 t, %1; cvt.u32.u64 %0, t; }"
        : "=r"(a) : "l"(p));
    return a;
}

// ---------------------------------------------------------------------------
// mma.sync helpers (base-ISA tensor path; compiles for plain compute_103)
// ---------------------------------------------------------------------------
__device__ __forceinline__ void ldsm4(uint32_t* r, uint32_t addr) {
    asm volatile("ldmatrix.sync.aligned.m8n8.x4.shared.b16 {%0,%1,%2,%3}, [%4];"
                 : "=r"(r[0]), "=r"(r[1]), "=r"(r[2]), "=r"(r[3]) : "r"(addr));
}
__device__ __forceinline__ void ldsm4t(uint32_t* r, uint32_t addr) {
    asm volatile("ldmatrix.sync.aligned.m8n8.x4.trans.shared.b16 {%0,%1,%2,%3}, [%4];"
                 : "=r"(r[0]), "=r"(r[1]), "=r"(r[2]), "=r"(r[3]) : "r"(addr));
}
__device__ __forceinline__ void mma16816(float* c, const uint32_t* a,
                                         uint32_t b0, uint32_t b1) {
    asm volatile(
        "mma.sync.aligned.m16n8k16.row.col.f32.bf16.bf16.f32 "
        "{%0,%1,%2,%3}, {%4,%5,%6,%7}, {%8,%9}, {%0,%1,%2,%3};"
        : "+f"(c[0]), "+f"(c[1]), "+f"(c[2]), "+f"(c[3])
        : "r"(a[0]), "r"(a[1]), "r"(a[2]), "r"(a[3]), "r"(b0), "r"(b1));
}
__device__ __forceinline__ uint32_t bfpack(float a, float b) {
    __nv_bfloat162 t = __floats2bfloat162_rn(a, b);
    return *(uint32_t*)&t;
}
__device__ __forceinline__ void split4(float4 v, uint2& hi, uint2& lo) {
    __nv_bfloat16 a = __float2bfloat16(v.x), b = __float2bfloat16(v.y);
    __nv_bfloat16 c = __float2bfloat16(v.z), d = __float2bfloat16(v.w);
    float fa = __bfloat162float(a), fb = __bfloat162float(b);
    float fc = __bfloat162float(c), fd = __bfloat162float(d);
    hi.x = bfpack(fa, fb);
    hi.y = bfpack(fc, fd);
    lo.x = bfpack(v.x - fa, v.y - fb);
    lo.y = bfpack(v.z - fc, v.w - fd);
}

// ---------------------------------------------------------------------------
// CSR construction (unchanged)
// ---------------------------------------------------------------------------
__global__ void deg_zero_kernel() {
    int i = blockIdx.x * blockDim.x + threadIdx.x;
    if (i < NN / 4) ((int4*)g_deg)[i] = make_int4(0, 0, 0, 0);
}
__global__ void deg_count_kernel(const int* __restrict__ tgt) {
    int base = (blockIdx.x * blockDim.x + threadIdx.x) * 4;
    if (base + 3 < NE) {
        int4 t = *(const int4*)(tgt + base);
        atomicAdd(&g_deg[t.x], 1);
        atomicAdd(&g_deg[t.y], 1);
        atomicAdd(&g_deg[t.z], 1);
        atomicAdd(&g_deg[t.w], 1);
    }
}
__global__ void scan_kernel() {
    __shared__ int warp_sums[32];
    const int tid = threadIdx.x;
    const int lane = tid & 31, wid = tid >> 5;
    int carry = 0;
    for (int base = 0; base < NN; base += 1024) {
        int i = base + tid;
        int v = (i < NN) ? g_deg[i] : 0;
        int x = v;
#pragma unroll
        for (int d = 1; d < 32; d <<= 1) {
            int t = __shfl_up_sync(0xffffffffu, x, d);
            if (lane >= d) x += t;
        }
        if (lane == 31) warp_sums[wid] = x;
        __syncthreads();
        if (wid == 0) {
            int s = warp_sums[lane];
#pragma unroll
            for (int d = 1; d < 32; d <<= 1) {
                int t = __shfl_up_sync(0xffffffffu, s, d);
                if (lane >= d) s += t;
            }
            warp_sums[lane] = s;
        }
        __syncthreads();
        int warp_prefix = (wid > 0) ? warp_sums[wid - 1] : 0;
        int incl = warp_prefix + x;
        if (i < NN) {
            g_off[i]  = carry + incl - v;
            g_dinv[i] = rsqrtf((float)(v + 1));
            g_cur[i]  = 0;
        }
        carry += warp_sums[31];
        __syncthreads();
    }
    if (tid == 0) g_off[NN] = carry;
}
__global__ void fill_kernel(const int* __restrict__ src, const int* __restrict__ tgt) {
    int base = (blockIdx.x * blockDim.x + threadIdx.x) * 4;
    if (base + 3 < NE) {
        int4 t = *(const int4*)(tgt + base);
        int4 s = *(const int4*)(src + base);
        int p0 = g_off[t.x] + atomicAdd(&g_cur[t.x], 1);
        int p1 = g_off[t.y] + atomicAdd(&g_cur[t.y], 1);
        int p2 = g_off[t.z] + atomicAdd(&g_cur[t.z], 1);
        int p3 = g_off[t.w] + atomicAdd(&g_cur[t.w], 1);
        g_el[p0] = s.x; g_el[p1] = s.y; g_el[p2] = s.z; g_el[p3] = s.w;
    }
}

// ---------------------------------------------------------------------------
// Big GEMM via mma.sync bf16 split (unchanged R10 winner)
// ---------------------------------------------------------------------------
#define MB_AHI 0
#define MB_ALO 6144
#define MB_BHI 12288
#define MB_BLO 16128
#define MB_SMEM 51200

__global__ void __launch_bounds__(256)
gemm_big_mma(const float* __restrict__ X,
             const float* __restrict__ W,
             const float* __restrict__ bias,
             const float* __restrict__ gamma,
             const float* __restrict__ beta,
             float* __restrict__ out)
{
    extern __shared__ char smx[];
    const uint32_t sb = smem_u32(smx);
    const int tid = threadIdx.x;
    const int wid = tid >> 5, lane = tid & 31;
    const int r0 = blockIdx.x * 128;
    const int m0 = wid * 16;

    float acc[56];
#pragma unroll
    for (int i = 0; i < 56; i++) acc[i] = 0.f;

    float4 ax0, ax1, wq0, wq1;
    const int ar = tid >> 1, akc = (tid & 1) * 8;

    auto load_chunk = [&](int t) {
        const int k0 = t * 16;
        int row = r0 + ar;
        const float* xp = X + (size_t)row * D_IN + k0 + akc;
        if (row < NN && k0 + akc + 8 <= D_IN) {
            ax0 = *(const float4*)xp;
            ax1 = *(const float4*)(xp + 4);
        } else {
            float tv[8];
#pragma unroll
            for (int j = 0; j < 8; j++)
                tv[j] = (row < NN && k0 + akc + j < D_IN) ? xp[j] : 0.f;
            ax0 = make_float4(tv[0], tv[1], tv[2], tv[3]);
            ax1 = make_float4(tv[4], tv[5], tv[6], tv[7]);
        }
        {
            int k = tid / 28, c = (tid % 28) * 4;
            wq0 = (k0 + k < D_IN && c < D_HID)
                ? *(const float4*)(W + (size_t)(k0 + k) * D_HID + c)
                : make_float4(0.f, 0.f, 0.f, 0.f);
        }
        if (tid < 192) {
            int s1 = tid + 256;
            int k = s1 / 28, c = (s1 % 28) * 4;
            wq1 = (k0 + k < D_IN && c < D_HID)
                ? *(const float4*)(W + (size_t)(k0 + k) * D_HID + c)
                : make_float4(0.f, 0.f, 0.f, 0.f);
        }
    };

    auto sts_chunk = [&]() {
        uint2 h0, l0, h1, l1;
        split4(ax0, h0, l0);
        split4(ax1, h1, l1);
        uint32_t aoff = (uint32_t)(ar * 48 + akc * 2);
        *(uint4*)(smx + MB_AHI + aoff) = make_uint4(h0.x, h0.y, h1.x, h1.y);
        *(uint4*)(smx + MB_ALO + aoff) = make_uint4(l0.x, l0.y, l1.x, l1.y);
        {
            int k = tid / 28, c = (tid % 28) * 4;
            uint2 hh, ll;
            split4(wq0, hh, ll);
            uint32_t boff = (uint32_t)(k * 240 + c * 2);
            *(uint2*)(smx + MB_BHI + boff) = hh;
            *(uint2*)(smx + MB_BLO + boff) = ll;
        }
        if (tid < 192) {
            int s1 = tid + 256;
            int k = s1 / 28, c = (s1 % 28) * 4;
            uint2 hh, ll;
            split4(wq1, hh, ll);
            uint32_t boff = (uint32_t)(k * 240 + c * 2);
            *(uint2*)(smx + MB_BHI + boff) = hh;
            *(uint2*)(smx + MB_BLO + boff) = ll;
        }
    };

    const uint32_t a_addr_off =
        (uint32_t)((m0 + (lane & 15)) * 48 + (lane >> 4) * 16);
    const uint32_t b_addr_row = (uint32_t)((lane & 15) * 240 + (lane >> 4) * 16);

    load_chunk(0);
    for (int t = 0; t < 32; t++) {
        __syncthreads();
        sts_chunk();
        __syncthreads();
        if (t + 1 < 32) load_chunk(t + 1);

        uint32_t ah[4], al[4];
        ldsm4(ah, sb + MB_AHI + a_addr_off);
        ldsm4(al, sb + MB_ALO + a_addr_off);
#pragma unroll
        for (int p = 0; p < 7; p++) {
            uint32_t bh[4], bl[4];
            uint32_t bo = b_addr_row + (uint32_t)(p * 32);
            ldsm4t(bh, sb + MB_BHI + bo);
            ldsm4t(bl, sb + MB_BLO + bo);
#pragma unroll
            for (int h = 0; h < 2; h++) {
                float* c = &acc[p * 8 + h * 4];
                mma16816(c, ah, bh[2 * h], bh[2 * h + 1]);
                mma16816(c, ah, bl[2 * h], bl[2 * h + 1]);
                mma16816(c, al, bh[2 * h], bh[2 * h + 1]);
            }
        }
    }

    __syncthreads();
    float* sC = (float*)smx;
#pragma unroll
    for (int p = 0; p < 7; p++) {
#pragma unroll
        for (int h = 0; h < 2; h++) {
            int n0 = p * 16 + h * 8;
            int col = n0 + (lane & 3) * 2;
            if (col < D_HID) {
                int rA = m0 + (lane >> 2);
                float b0v = bias[col], b1v = bias[col + 1];
                const float* c = &acc[p * 8 + h * 4];
                sC[rA * D_HID + col]           = c[0] + b0v;
                sC[rA * D_HID + col + 1]       = c[1] + b1v;
                sC[(rA + 8) * D_HID + col]     = c[2] + b0v;
                sC[(rA + 8) * D_HID + col + 1] = c[3] + b1v;
            }
        }
    }
    __syncthreads();
    for (int r = wid; r < 128; r += 8) {
        int row = r0 + r;
        float vals[4];
        float s = 0.f, sq = 0.f;
#pragma unroll
        for (int q = 0; q < 4; q++) {
            int c = lane + 32 * q;
            float v = (c < D_HID) ? sC[r * D_HID + c] : 0.f;
            vals[q] = v; s += v; sq += v * v;
        }
#pragma unroll
        for (int o2 = 16; o2 > 0; o2 >>= 1) {
            s  += __shfl_xor_sync(0xffffffffu, s,  o2);
            sq += __shfl_xor_sync(0xffffffffu, sq, o2);
        }
        float mean = s / D_HID;
        float var  = sq / D_HID - mean * mean;
        float rstd = rsqrtf(var + 1e-5f);
        if (row < NN) {
#pragma unroll
            for (int q = 0; q < 4; q++) {
                int c = lane + 32 * q;
                if (c < D_HID)
                    out[row * D_HID + c] =
                        fmaxf((vals[q] - mean) * rstd * gamma[c] + beta[c], 0.f);
            }
        }
    }
}

// ---------------------------------------------------------------------------
// Small GEMM on mma.sync split-bf16. K=100 (padded 112), whole K in smem.
// A: [128][120 bf16] hi/lo (pitch 240B). B: [112][120 bf16] hi/lo per matrix.
// NOUT = 100 or 64. EPI: 2 = +bias,LN,ReLU | 3 = *dinv | 4 = dual (Wa+bias, Wb)
// ---------------------------------------------------------------------------
#define SG_AHI 0
#define SG_ALO 30720
#define SG_BHI 61440
#define SG_BLO 88320
#define SG_B2HI 115200
#define SG_B2LO 142080
#define SG_TOT_S 115200
#define SG_TOT_D 168960

template<int NOUT, int EPI>
__global__ void __launch_bounds__(256)
gemm_small_mma(const float* __restrict__ A,
               const float* __restrict__ Wa,
               const float* __restrict__ Wb,
               const float* __restrict__ bias,
               const float* __restrict__ gamma,
               const float* __restrict__ beta,
               float* __restrict__ out,
               float* __restrict__ out2)
{
    constexpr int NP  = (NOUT == 64) ? 4 : 7;       // n16-tiles
    constexpr int NO4 = NOUT / 4;
    constexpr int TOT = (EPI == 4) ? SG_TOT_D : SG_TOT_S;
    extern __shared__ char smx[];
    const uint32_t sb = smem_u32(smx);
    const int tid = threadIdx.x;
    const int wid = tid >> 5, lane = tid & 31;
    const int r0 = blockIdx.x * 128;
    const int m0 = wid * 16;

    // Zero-fill (covers k/n padding)
    for (int i = tid * 16; i < TOT; i += 256 * 16)
        *(uint4*)(smx + i) = make_uint4(0, 0, 0, 0);
    __syncthreads();

    // Convert A [128 x 100] -> hi/lo bf16, pitch 240B
    for (int i = tid; i < 128 * 25; i += 256) {
        int r = i / 25, q = i % 25;
        int row = r0 + r;
        float4 v = make_float4(0.f, 0.f, 0.f, 0.f);
        if (row < NN) v = *(const float4*)(A + (size_t)row * 100 + q * 4);
        uint2 hi, lo; split4(v, hi, lo);
        *(uint2*)(smx + SG_AHI + r * 240 + q * 8) = hi;
        *(uint2*)(smx + SG_ALO + r * 240 + q * 8) = lo;
    }
    // Convert B (Wa), and Wb for dual
    for (int i = tid; i < 100 * NO4; i += 256) {
        int k = i / NO4, q = i % NO4;
        float4 v = *(const float4*)(Wa + (size_t)k * NOUT + q * 4);
        uint2 hi, lo; split4(v, hi, lo);
        *(uint2*)(smx + SG_BHI + k * 240 + q * 8) = hi;
        *(uint2*)(smx + SG_BLO + k * 240 + q * 8) = lo;
    }
    if (EPI == 4) {
        for (int i = tid; i < 100 * NO4; i += 256) {
            int k = i / NO4, q = i % NO4;
            float4 v = *(const float4*)(Wb + (size_t)k * NOUT + q * 4);
            uint2 hi, lo; split4(v, hi, lo);
            *(uint2*)(smx + SG_B2HI + k * 240 + q * 8) = hi;
            *(uint2*)(smx + SG_B2LO + k * 240 + q * 8) = lo;
        }
    }
    __syncthreads();

    const uint32_t a_off = (uint32_t)((m0 + (lane & 15)) * 240 + (lane >> 4) * 16);
    const uint32_t b_row = (uint32_t)((lane & 15) * 240 + (lane >> 4) * 16);

    float acc[NP * 8];
    auto run_pass = [&](uint32_t sbh, uint32_t sbl) {
#pragma unroll
        for (int i = 0; i < NP * 8; i++) acc[i] = 0.f;
#pragma unroll
        for (int kc = 0; kc < 7; kc++) {
            uint32_t ah[4], al[4];
            ldsm4(ah, sb + SG_AHI + a_off + kc * 32);
            ldsm4(al, sb + SG_ALO + a_off + kc * 32);
#pragma unroll
            for (int p = 0; p < NP; p++) {
                uint32_t bh[4], bl[4];
                uint32_t bo = b_row + (uint32_t)(kc * 3840 + p * 32);
                ldsm4t(bh, sbh + bo);
                ldsm4t(bl, sbl + bo);
#pragma unroll
                for (int h = 0; h < 2; h++) {
                    float* c = &acc[p * 8 + h * 4];
                    mma16816(c, ah, bh[2 * h], bh[2 * h + 1]);
                    mma16816(c, ah, bl[2 * h], bl[2 * h + 1]);
                    mma16816(c, al, bh[2 * h], bh[2 * h + 1]);
                }
            }
        }
    };

    run_pass(sb + SG_BHI, sb + SG_BLO);

    const int rA = m0 + (lane >> 2);
    const int rowA = r0 + rA, rowB = rowA + 8;

    if (EPI == 2) {
        __syncthreads();
        float* sC = (float*)smx;
#pragma unroll
        for (int p = 0; p < NP; p++) {
#pragma unroll
            for (int h = 0; h < 2; h++) {
                int col = p * 16 + h * 8 + (lane & 3) * 2;
                if (col < NOUT) {
                    float b0v = bias[col], b1v = bias[col + 1];
                    const float* c = &acc[p * 8 + h * 4];
                    sC[rA * NOUT + col]           = c[0] + b0v;
                    sC[rA * NOUT + col + 1]       = c[1] + b1v;
                    sC[(rA + 8) * NOUT + col]     = c[2] + b0v;
                    sC[(rA + 8) * NOUT + col + 1] = c[3] + b1v;
                }
            }
        }
        __syncthreads();
        for (int r = wid; r < 128; r += 8) {
            int row = r0 + r;
            float vals[4];
            float s = 0.f, sq = 0.f;
#pragma unroll
            for (int q = 0; q < 4; q++) {
                int c = lane + 32 * q;
                float v = (c < NOUT) ? sC[r * NOUT + c] : 0.f;
                vals[q] = v; s += v; sq += v * v;
            }
#pragma unroll
            for (int o2 = 16; o2 > 0; o2 >>= 1) {
                s  += __shfl_xor_sync(0xffffffffu, s,  o2);
                sq += __shfl_xor_sync(0xffffffffu, sq, o2);
            }
            float mean = s / NOUT;
            float var  = sq / NOUT - mean * mean;
            float rstd = rsqrtf(var + 1e-5f);
            if (row < NN) {
#pragma unroll
                for (int q = 0; q < 4; q++) {
                    int c = lane + 32 * q;
                    if (c < NOUT)
                        out[row * NOUT + c] =
                            fmaxf((vals[q] - mean) * rstd * gamma[c] + beta[c], 0.f);
                }
            }
        }
    } else if (EPI == 3) {
        float d0 = (rowA < NN) ? g_dinv[rowA] : 0.f;
        float d1 = (rowB < NN) ? g_dinv[rowB] : 0.f;
#pragma unroll
        for (int p = 0; p < NP; p++) {
#pragma unroll
            for (int h = 0; h < 2; h++) {
                int col = p * 16 + h * 8 + (lane & 3) * 2;
                if (col < NOUT) {
                    const float* c = &acc[p * 8 + h * 4];
                    if (rowA < NN) {
                        out[(size_t)rowA * NOUT + col]     = d0 * c[0];
                        out[(size_t)rowA * NOUT + col + 1] = d0 * c[1];
                    }
                    if (rowB < NN) {
                        out[(size_t)rowB * NOUT + col]     = d1 * c[2];
                        out[(size_t)rowB * NOUT + col + 1] = d1 * c[3];
                    }
                }
            }
        }
    } else {  // EPI == 4: dual
#pragma unroll
        for (int p = 0; p < NP; p++) {
#pragma unroll
            for (int h = 0; h < 2; h++) {
                int col = p * 16 + h * 8 + (lane & 3) * 2;
                if (col < NOUT) {
                    const float* c = &acc[p * 8 + h * 4];
                    float b0v = bias[col], b1v = bias[col + 1];
                    if (rowA < NN) {
                        out[(size_t)rowA * NOUT + col]     = c[0] + b0v;
                        out[(size_t)rowA * NOUT + col + 1] = c[1] + b1v;
                    }
                    if (rowB < NN) {
                        out[(size_t)rowB * NOUT + col]     = c[2] + b0v;
                        out[(size_t)rowB * NOUT + col + 1] = c[3] + b1v;
                    }
                }
            }
        }
        run_pass(sb + SG_B2HI, sb + SG_B2LO);
#pragma unroll
        for (int p = 0; p < NP; p++) {
#pragma unroll
            for (int h = 0; h < 2; h++) {
                int col = p * 16 + h * 8 + (lane & 3) * 2;
                if (col < NOUT) {
                    const float* c = &acc[p * 8 + h * 4];
                    if (rowA < NN) {
                        out2[(size_t)rowA * NOUT + col]     = c[0];
                        out2[(size_t)rowA * NOUT + col + 1] = c[1];
                    }
                    if (rowB < NN) {
                        out2[(size_t)rowB * NOUT + col]     = c[2];
                        out2[(size_t)rowB * NOUT + col + 1] = c[3];
                    }
                }
            }
        }
    }
}

// ---------------------------------------------------------------------------
// Gather aggregation (warp per node), 4-way edge ILP. (unchanged)
// ---------------------------------------------------------------------------
template<int M4, int MODE>
__global__ void gather_kernel(const float* __restrict__ h,
                              const float* __restrict__ self,
                              const float* __restrict__ bias,
                              float* __restrict__ out)
{
    int w = (blockIdx.x * blockDim.x + threadIdx.x) >> 5;
    if (w >= NN) return;
    const int lane = threadIdx.x & 31;
    const bool act = lane < M4;
    const float4* h4 = (const float4*)h;

    float4 a0 = make_float4(0.f, 0.f, 0.f, 0.f);
    float4 a1 = a0, a2 = a0, a3 = a0;
    if (act) {
        if (MODE == 0) a0 = ((const float4*)self)[w * M4 + lane];
        else           a0 = h4[w * M4 + lane];
    }

    const int off = g_off[w];
    const int dg  = g_off[w + 1] - off;
    for (int base = 0; base < dg; base += 32) {
        int idx = base + lane;
        int myel = (idx < dg) ? g_el[off + idx] : 0;
        int cnt = dg - base; if (cnt > 32) cnt = 32;
        int j = 0;
        for (; j + 3 < cnt; j += 4) {
            int s0 = __shfl_sync(0xffffffffu, myel, j);
            int s1 = __shfl_sync(0xffffffffu, myel, j + 1);
            int s2 = __shfl_sync(0xffffffffu, myel, j + 2);
            int s3 = __shfl_sync(0xffffffffu, myel, j + 3);
            if (act) {
                float4 v0 = h4[s0 * M4 + lane];
                float4 v1 = h4[s1 * M4 + lane];
                float4 v2 = h4[s2 * M4 + lane];
                float4 v3 = h4[s3 * M4 + lane];
                a0.x += v0.x; a0.y += v0.y; a0.z += v0.z; a0.w += v0.w;
                a1.x += v1.x; a1.y += v1.y; a1.z += v1.z; a1.w += v1.w;
                a2.x += v2.x; a2.y += v2.y; a2.z += v2.z; a2.w += v2.w;
                a3.x += v3.x; a3.y += v3.y; a3.z += v3.z; a3.w += v3.w;
            }
        }
        for (; j < cnt; j++) {
            int s0 = __shfl_sync(0xffffffffu, myel, j);
            if (act) {
                float4 v0 = h4[s0 * M4 + lane];
                a0.x += v0.x; a0.y += v0.y; a0.z += v0.z; a0.w += v0.w;
            }
        }
    }
    float4 acc;
    acc.x = (a0.x + a1.x) + (a2.x + a3.x);
    acc.y = (a0.y + a1.y) + (a2.y + a3.y);
    acc.z = (a0.z + a1.z) + (a2.z + a3.z);
    acc.w = (a0.w + a1.w) + (a2.w + a3.w);

    if (MODE == 0) {
        if (act) {
            float4 o;
            o.x = fmaxf(acc.x, 0.f); o.y = fmaxf(acc.y, 0.f);
            o.z = fmaxf(acc.z, 0.f); o.w = fmaxf(acc.w, 0.f);
            ((float4*)out)[w * M4 + lane] = o;
        }
    } else if (MODE == 1) {
        if (act) {
            float di = g_dinv[w];
            float4 b = ((const float4*)bias)[lane];
            float4 o;
            o.x = fmaxf(fmaf(di, acc.x, b.x), 0.f);
            o.y = fmaxf(fmaf(di, acc.y, b.y), 0.f);
            o.z = fmaxf(fmaf(di, acc.z, b.z), 0.f);
            o.w = fmaxf(fmaf(di, acc.w, b.w), 0.f);
            ((float4*)out)[w * M4 + lane] = o;
        }
    } else {
        float di = g_dinv[w];
        float4 v = make_float4(0.f, 0.f, 0.f, 0.f);
        if (act) {
            float4 b = ((const float4*)bias)[lane];
            v.x = fmaf(di, acc.x, b.x); v.y = fmaf(di, acc.y, b.y);
            v.z = fmaf(di, acc.z, b.z); v.w = fmaf(di, acc.w, b.w);
        }
        float m = act ? fmaxf(fmaxf(v.x, v.y), fmaxf(v.z, v.w)) : -3.4e38f;
#pragma unroll
        for (int o2 = 16; o2 > 0; o2 >>= 1)
            m = fmaxf(m, __shfl_xor_sync(0xffffffffu, m, o2));
        float se = act ? (expf(v.x - m) + expf(v.y - m) + expf(v.z - m) + expf(v.w - m)) : 0.f;
#pragma unroll
        for (int o2 = 16; o2 > 0; o2 >>= 1)
            se += __shfl_xor_sync(0xffffffffu, se, o2);
        float lse = m + logf(se);
        if (act) {
            float4 o;
            o.x = v.x - lse; o.y = v.y - lse; o.z = v.z - lse; o.w = v.w - lse;
            ((float4*)out)[w * M4 + lane] = o;
        }
    }
}

extern "C" void kernel_launch(void* const* d_in, const int* in_sizes, int n_in,
                              void* d_out, int out_size)
{
    const float* X     = (const float*)d_in[0];
    const int*   ei    = (const int*)  d_in[1];
    const float* W1    = (const float*)d_in[3];
    const float* b1    = (const float*)d_in[4];
    const float* g1    = (const float*)d_in[5];
    const float* be1   = (const float*)d_in[6];
    const float* W2    = (const float*)d_in[7];
    const float* b2    = (const float*)d_in[8];
    const float* g2    = (const float*)d_in[9];
    const float* be2   = (const float*)d_in[10];
    const float* Wrel  = (const float*)d_in[11];
    const float* Wself = (const float*)d_in[12];
    const float* rb    = (const float*)d_in[13];
    const float* c1W   = (const float*)d_in[14];
    const float* c1b   = (const float*)d_in[15];
    const float* c2W   = (const float*)d_in[16];
    const float* c2b   = (const float*)d_in[17];
    float* out = (float*)d_out;

    const int* src = ei;
    const int* tgt = ei + NE;

    float *B1, *B2, *B3, *B4;
    cudaGetSymbolAddress((void**)&B1, g_B1);
    cudaGetSymbolAddress((void**)&B2, g_B2);
    cudaGetSymbolAddress((void**)&B3, g_B3);
    cudaGetSymbolAddress((void**)&B4, g_B4);

    cudaFuncSetAttribute(gemm_big_mma,
                         cudaFuncAttributeMaxDynamicSharedMemorySize, MB_SMEM);
    cudaFuncSetAttribute(gemm_small_mma<100, 2>,
                         cudaFuncAttributeMaxDynamicSharedMemorySize, SG_TOT_S);
    cudaFuncSetAttribute(gemm_small_mma<100, 3>,
                         cudaFuncAttributeMaxDynamicSharedMemorySize, SG_TOT_S);
    cudaFuncSetAttribute(gemm_small_mma<100, 4>,
                         cudaFuncAttributeMaxDynamicSharedMemorySize, SG_TOT_D);
    cudaFuncSetAttribute(gemm_small_mma<64, 3>,
                         cudaFuncAttributeMaxDynamicSharedMemorySize, SG_TOT_S);

    const int GB = (NN + 127) / 128;   // 391
    const int GGATHER = (NN * 32 + 255) / 256;

    // Fork a side stream for the CSR build (overlaps the transform GEMMs).
    cudaStream_t s2;
    cudaEvent_t evFork, evJoin;
    cudaStreamCreateWithFlags(&s2, cudaStreamNonBlocking);
    cudaEventCreateWithFlags(&evFork, cudaEventDisableTiming);
    cudaEventCreateWithFlags(&evJoin, cudaEventDisableTiming);

    cudaEventRecord(evFork, 0);
    cudaStreamWaitEvent(s2, evFork, 0);

    deg_zero_kernel <<<(NN / 4 + 255) / 256, 256, 0, s2>>>();
    deg_count_kernel<<<(NE / 4 + 255) / 256, 256, 0, s2>>>(tgt);
    scan_kernel     <<<1, 1024, 0, s2>>>();
    fill_kernel     <<<(NE / 4 + 255) / 256, 256, 0, s2>>>(src, tgt);
    cudaEventRecord(evJoin, s2);

    // transform: (Linear -> LN -> ReLU) x2, both on mma.sync tensor path
    gemm_big_mma<<<GB, 256, MB_SMEM>>>(X, W1, b1, g1, be1, B1);
    gemm_small_mma<100, 2><<<GB, 256, SG_TOT_S>>>(
        B1, W2, nullptr, b2, g2, be2, B2, nullptr);

    // RGCN: dual GEMM (Wself + rb -> B3, Wrel -> B4), then gather
    gemm_small_mma<100, 4><<<GB, 256, SG_TOT_D>>>(
        B2, Wself, Wrel, rb, nullptr, nullptr, B3, B4);

    cudaStreamWaitEvent(0, evJoin, 0);
    gather_kernel<25, 0><<<GGATHER, 256>>>(B4, B3, nullptr, B1);

    // GCNConv1
    gemm_small_mma<100, 3><<<GB, 256, SG_TOT_S>>>(
        B1, c1W, nullptr, nullptr, nullptr, nullptr, B2, nullptr);
    gather_kernel<25, 1><<<GGATHER, 256>>>(B2, nullptr, c1b, B3);

    // GCNConv2 (->64) + log_softmax
    gemm_small_mma<64, 3><<<GB, 256, SG_TOT_S>>>(
        B3, c2W, nullptr, nullptr, nullptr, nullptr, B4, nullptr);
    gather_kernel<16, 2><<<GGATHER, 256>>>(B4, nullptr, c2b, out);

    cudaEventDestroy(evFork);
    cudaEventDestroy(evJoin);
    cudaStreamDestroy(s2);
}

// round 12
// speedup vs baseline: 2.7020x; 1.0496x over previous
#include <cuda_runtime.h>
#include <cuda_bf16.h>
#include <math.h>
#include <stdint.h>

#define NN    50000
#define NE    800000
#define D_IN  500
#define D_HID 100
#define D_OUT 64

__device__ float g_B1[NN * D_HID];
__device__ float g_B2[NN * D_HID];
__device__ float g_B3[NN * D_HID];
__device__ float g_B4[NN * D_HID];
__device__ float g_dinv[NN];
__device__ int   g_deg[NN];
__device__ int   g_off[NN + 1];
__device__ int   g_cur[NN];
__device__ int   g_el[NE];

// Precomputed weight splits (hi/lo bf16), padded to tile layouts.
// W1: [512][112]  (k-major, zero-padded)
// small weights [5]: [112][120] (k rows x n cols, pitch 240B) 0=W2 1=Wself 2=Wrel 3=c1W 4=c2W
__device__ __align__(16) __nv_bfloat16 g_W1h[512 * 112];
__device__ __align__(16) __nv_bfloat16 g_W1l[512 * 112];
__device__ __align__(16) __nv_bfloat16 g_Wh[5][112 * 120];
__device__ __align__(16) __nv_bfloat16 g_Wl[5][112 * 120];

__device__ __forceinline__ unsigned int smem_u32(const void* p) {
    unsigned int a;
    asm("{ .reg .u64 t; cvta.to.shared.u64 t, %1; cvt.u32.u64 %0, t; }"
        : "=r"(a) : "l"(p));
    return a;
}

// ---------------------------------------------------------------------------
// mma.sync helpers (base-ISA tensor path; compiles for plain compute_103)
// ---------------------------------------------------------------------------
__device__ __forceinline__ void ldsm4(uint32_t* r, uint32_t addr) {
    asm volatile("ldmatrix.sync.aligned.m8n8.x4.shared.b16 {%0,%1,%2,%3}, [%4];"
                 : "=r"(r[0]), "=r"(r[1]), "=r"(r[2]), "=r"(r[3]) : "r"(addr));
}
__device__ __forceinline__ void ldsm4t(uint32_t* r, uint32_t addr) {
    asm volatile("ldmatrix.sync.aligned.m8n8.x4.trans.shared.b16 {%0,%1,%2,%3}, [%4];"
                 : "=r"(r[0]), "=r"(r[1]), "=r"(r[2]), "=r"(r[3]) : "r"(addr));
}
__device__ __forceinline__ void mma16816(float* c, const uint32_t* a,
                                         uint32_t b0, uint32_t b1) {
    asm volatile(
        "mma.sync.aligned.m16n8k16.row.col.f32.bf16.bf16.f32 "
        "{%0,%1,%2,%3}, {%4,%5,%6,%7}, {%8,%9}, {%0,%1,%2,%3};"
        : "+f"(c[0]), "+f"(c[1]), "+f"(c[2]), "+f"(c[3])
        : "r"(a[0]), "r"(a[1]), "r"(a[2]), "r"(a[3]), "r"(b0), "r"(b1));
}
__device__ __forceinline__ uint32_t bfpack(float a, float b) {
    __nv_bfloat162 t = __floats2bfloat162_rn(a, b);
    return *(uint32_t*)&t;
}
__device__ __forceinline__ void split4(float4 v, uint2& hi, uint2& lo) {
    __nv_bfloat16 a = __float2bfloat16(v.x), b = __float2bfloat16(v.y);
    __nv_bfloat16 c = __float2bfloat16(v.z), d = __float2bfloat16(v.w);
    float fa = __bfloat162float(a), fb = __bfloat162float(b);
    float fc = __bfloat162float(c), fd = __bfloat162float(d);
    hi.x = bfpack(fa, fb);
    hi.y = bfpack(fc, fd);
    lo.x = bfpack(v.x - fa, v.y - fb);
    lo.y = bfpack(v.z - fc, v.w - fd);
}

// ---------------------------------------------------------------------------
// Weight split precompute (runs once per launch, ~3us)
// ---------------------------------------------------------------------------
__global__ void wsplit_kernel(const float* __restrict__ W1,
                              const float* __restrict__ W2,
                              const float* __restrict__ Ws,
                              const float* __restrict__ Wr,
                              const float* __restrict__ c1,
                              const float* __restrict__ c2)
{
    int i = blockIdx.x * blockDim.x + threadIdx.x;
    if (i < 512 * 112) {
        int k = i / 112, c = i % 112;
        float v = (k < D_IN && c < D_HID) ? W1[k * D_HID + c] : 0.f;
        __nv_bfloat16 h = __float2bfloat16(v);
        g_W1h[i] = h;
        g_W1l[i] = __float2bfloat16(v - __bfloat162float(h));
    } else {
        int j = i - 512 * 112;
        if (j < 5 * 13440) {
            int m = j / 13440, r = j % 13440;
            int k = r / 120, n = r % 120;
            const float* Wp; int NO;
            switch (m) {
                case 0: Wp = W2; NO = 100; break;
                case 1: Wp = Ws; NO = 100; break;
                case 2: Wp = Wr; NO = 100; break;
                case 3: Wp = c1; NO = 100; break;
                default: Wp = c2; NO = 64; break;
            }
            float v = (k < 100 && n < NO) ? Wp[k * NO + n] : 0.f;
            __nv_bfloat16 h = __float2bfloat16(v);
            g_Wh[m][r] = h;
            g_Wl[m][r] = __float2bfloat16(v - __bfloat162float(h));
        }
    }
}

// ---------------------------------------------------------------------------
// CSR construction (unchanged)
// ---------------------------------------------------------------------------
__global__ void deg_zero_kernel() {
    int i = blockIdx.x * blockDim.x + threadIdx.x;
    if (i < NN / 4) ((int4*)g_deg)[i] = make_int4(0, 0, 0, 0);
}
__global__ void deg_count_kernel(const int* __restrict__ tgt) {
    int base = (blockIdx.x * blockDim.x + threadIdx.x) * 4;
    if (base + 3 < NE) {
        int4 t = *(const int4*)(tgt + base);
        atomicAdd(&g_deg[t.x], 1);
        atomicAdd(&g_deg[t.y], 1);
        atomicAdd(&g_deg[t.z], 1);
        atomicAdd(&g_deg[t.w], 1);
    }
}
__global__ void scan_kernel() {
    __shared__ int warp_sums[32];
    const int tid = threadIdx.x;
    const int lane = tid & 31, wid = tid >> 5;
    int carry = 0;
    for (int base = 0; base < NN; base += 1024) {
        int i = base + tid;
        int v = (i < NN) ? g_deg[i] : 0;
        int x = v;
#pragma unroll
        for (int d = 1; d < 32; d <<= 1) {
            int t = __shfl_up_sync(0xffffffffu, x, d);
            if (lane >= d) x += t;
        }
        if (lane == 31) warp_sums[wid] = x;
        __syncthreads();
        if (wid == 0) {
            int s = warp_sums[lane];
#pragma unroll
            for (int d = 1; d < 32; d <<= 1) {
                int t = __shfl_up_sync(0xffffffffu, s, d);
                if (lane >= d) s += t;
            }
            warp_sums[lane] = s;
        }
        __syncthreads();
        int warp_prefix = (wid > 0) ? warp_sums[wid - 1] : 0;
        int incl = warp_prefix + x;
        if (i < NN) {
            g_off[i]  = carry + incl - v;
            g_dinv[i] = rsqrtf((float)(v + 1));
            g_cur[i]  = 0;
        }
        carry += warp_sums[31];
        __syncthreads();
    }
    if (tid == 0) g_off[NN] = carry;
}
__global__ void fill_kernel(const int* __restrict__ src, const int* __restrict__ tgt) {
    int base = (blockIdx.x * blockDim.x + threadIdx.x) * 4;
    if (base + 3 < NE) {
        int4 t = *(const int4*)(tgt + base);
        int4 s = *(const int4*)(src + base);
        int p0 = g_off[t.x] + atomicAdd(&g_cur[t.x], 1);
        int p1 = g_off[t.y] + atomicAdd(&g_cur[t.y], 1);
        int p2 = g_off[t.z] + atomicAdd(&g_cur[t.z], 1);
        int p3 = g_off[t.w] + atomicAdd(&g_cur[t.w], 1);
        g_el[p0] = s.x; g_el[p1] = s.y; g_el[p2] = s.z; g_el[p3] = s.w;
    }
}

// ---------------------------------------------------------------------------
// Big GEMM via mma.sync bf16 split; W staged from precomputed splits.
// ---------------------------------------------------------------------------
#define MB_AHI 0
#define MB_ALO 6144
#define MB_BHI 12288
#define MB_BLO 16128
#define MB_SMEM 51200

__global__ void __launch_bounds__(256)
gemm_big_mma(const float* __restrict__ X,
             const float* __restrict__ bias,
             const float* __restrict__ gamma,
             const float* __restrict__ beta,
             float* __restrict__ out)
{
    extern __shared__ char smx[];
    const uint32_t sb = smem_u32(smx);
    const int tid = threadIdx.x;
    const int wid = tid >> 5, lane = tid & 31;
    const int r0 = blockIdx.x * 128;
    const int m0 = wid * 16;

    float acc[56];
#pragma unroll
    for (int i = 0; i < 56; i++) acc[i] = 0.f;

    float4 ax0, ax1;
    uint4 w0r, w1r;
    const int ar = tid >> 1, akc = (tid & 1) * 8;
    // W slot decomposition (constant per thread)
    const int s0buf = tid / 224, s0idx = tid % 224;
    const int s0row = s0idx / 14, s0c = s0idx % 14;
    const int s1idx = tid + 32;             // lo slots 32..223 (tid<192)
    const int s1row = s1idx / 14, s1c = s1idx % 14;

    auto load_chunk = [&](int t) {
        const int k0 = t * 16;
        int row = r0 + ar;
        const float* xp = X + (size_t)row * D_IN + k0 + akc;
        if (row < NN && k0 + akc + 8 <= D_IN) {
            ax0 = *(const float4*)xp;
            ax1 = *(const float4*)(xp + 4);
        } else {
            float tv[8];
#pragma unroll
            for (int j = 0; j < 8; j++)
                tv[j] = (row < NN && k0 + akc + j < D_IN) ? xp[j] : 0.f;
            ax0 = make_float4(tv[0], tv[1], tv[2], tv[3]);
            ax1 = make_float4(tv[4], tv[5], tv[6], tv[7]);
        }
        {
            const __nv_bfloat16* srcw = s0buf ? g_W1l : g_W1h;
            w0r = *(const uint4*)(srcw + (k0 + s0row) * 112 + s0c * 8);
        }
        if (tid < 192)
            w1r = *(const uint4*)(g_W1l + (k0 + s1row) * 112 + s1c * 8);
    };

    auto sts_chunk = [&]() {
        uint2 h0, l0, h1, l1;
        split4(ax0, h0, l0);
        split4(ax1, h1, l1);
        uint32_t aoff = (uint32_t)(ar * 48 + akc * 2);
        *(uint4*)(smx + MB_AHI + aoff) = make_uint4(h0.x, h0.y, h1.x, h1.y);
        *(uint4*)(smx + MB_ALO + aoff) = make_uint4(l0.x, l0.y, l1.x, l1.y);
        *(uint4*)(smx + (s0buf ? MB_BLO : MB_BHI) + s0row * 240 + s0c * 16) = w0r;
        if (tid < 192)
            *(uint4*)(smx + MB_BLO + s1row * 240 + s1c * 16) = w1r;
    };

    const uint32_t a_addr_off =
        (uint32_t)((m0 + (lane & 15)) * 48 + (lane >> 4) * 16);
    const uint32_t b_addr_row = (uint32_t)((lane & 15) * 240 + (lane >> 4) * 16);

    load_chunk(0);
    for (int t = 0; t < 32; t++) {
        __syncthreads();
        sts_chunk();
        __syncthreads();
        if (t + 1 < 32) load_chunk(t + 1);

        uint32_t ah[4], al[4];
        ldsm4(ah, sb + MB_AHI + a_addr_off);
        ldsm4(al, sb + MB_ALO + a_addr_off);
#pragma unroll
        for (int p = 0; p < 7; p++) {
            uint32_t bh[4], bl[4];
            uint32_t bo = b_addr_row + (uint32_t)(p * 32);
            ldsm4t(bh, sb + MB_BHI + bo);
            ldsm4t(bl, sb + MB_BLO + bo);
#pragma unroll
            for (int h = 0; h < 2; h++) {
                float* c = &acc[p * 8 + h * 4];
                mma16816(c, ah, bh[2 * h], bh[2 * h + 1]);
                mma16816(c, ah, bl[2 * h], bl[2 * h + 1]);
                mma16816(c, al, bh[2 * h], bh[2 * h + 1]);
            }
        }
    }

    __syncthreads();
    float* sC = (float*)smx;
#pragma unroll
    for (int p = 0; p < 7; p++) {
#pragma unroll
        for (int h = 0; h < 2; h++) {
            int n0 = p * 16 + h * 8;
            int col = n0 + (lane & 3) * 2;
            if (col < D_HID) {
                int rA = m0 + (lane >> 2);
                float b0v = bias[col], b1v = bias[col + 1];
                const float* c = &acc[p * 8 + h * 4];
                sC[rA * D_HID + col]           = c[0] + b0v;
                sC[rA * D_HID + col + 1]       = c[1] + b1v;
                sC[(rA + 8) * D_HID + col]     = c[2] + b0v;
                sC[(rA + 8) * D_HID + col + 1] = c[3] + b1v;
            }
        }
    }
    __syncthreads();
    for (int r = wid; r < 128; r += 8) {
        int row = r0 + r;
        float vals[4];
        float s = 0.f, sq = 0.f;
#pragma unroll
        for (int q = 0; q < 4; q++) {
            int c = lane + 32 * q;
            float v = (c < D_HID) ? sC[r * D_HID + c] : 0.f;
            vals[q] = v; s += v; sq += v * v;
        }
#pragma unroll
        for (int o2 = 16; o2 > 0; o2 >>= 1) {
            s  += __shfl_xor_sync(0xffffffffu, s,  o2);
            sq += __shfl_xor_sync(0xffffffffu, sq, o2);
        }
        float mean = s / D_HID;
        float var  = sq / D_HID - mean * mean;
        float rstd = rsqrtf(var + 1e-5f);
        if (row < NN) {
#pragma unroll
            for (int q = 0; q < 4; q++) {
                int c = lane + 32 * q;
                if (c < D_HID)
                    out[row * D_HID + c] =
                        fmaxf((vals[q] - mean) * rstd * gamma[c] + beta[c], 0.f);
            }
        }
    }
}

// ---------------------------------------------------------------------------
// Small GEMM on mma.sync split-bf16; B tiles memcpy'd from precomputed splits.
// A: [128][120 bf16] hi/lo (pitch 240B). Single B buffer (dual runs 2 passes).
// NOUT = 100 or 64. EPI: 2 = +bias,LN,ReLU | 3 = *dinv | 4 = dual (wA+bias, wB)
// ---------------------------------------------------------------------------
#define SG_AHI 0
#define SG_ALO 30720
#define SG_BHI 61440
#define SG_BLO 88320
#define SG_TOT 115200

template<int NOUT, int EPI>
__global__ void __launch_bounds__(256)
gemm_small_mma(const float* __restrict__ A, int widx, int widx2,
               const float* __restrict__ bias,
               const float* __restrict__ gamma,
               const float* __restrict__ beta,
               float* __restrict__ out,
               float* __restrict__ out2)
{
    constexpr int NP = (NOUT == 64) ? 4 : 7;       // n16-tiles
    extern __shared__ char smx[];
    const uint32_t sb = smem_u32(smx);
    const int tid = threadIdx.x;
    const int wid = tid >> 5, lane = tid & 31;
    const int r0 = blockIdx.x * 128;
    const int m0 = wid * 16;

    // Zero A region (covers k-pad cols 100..119)
    for (int i = tid * 16; i < 61440; i += 256 * 16)
        *(uint4*)(smx + i) = make_uint4(0, 0, 0, 0);
    __syncthreads();

    // Convert A [128 x 100] -> hi/lo bf16, pitch 240B
    for (int i = tid; i < 128 * 25; i += 256) {
        int r = i / 25, q = i % 25;
        int row = r0 + r;
        float4 v = make_float4(0.f, 0.f, 0.f, 0.f);
        if (row < NN) v = *(const float4*)(A + (size_t)row * 100 + q * 4);
        uint2 hi, lo; split4(v, hi, lo);
        *(uint2*)(smx + SG_AHI + r * 240 + q * 8) = hi;
        *(uint2*)(smx + SG_ALO + r * 240 + q * 8) = lo;
    }
    // Copy B tile (precomputed, layout-identical, padding included)
    {
        const uint4* gh = (const uint4*)g_Wh[widx];
        const uint4* gl = (const uint4*)g_Wl[widx];
        for (int i = tid; i < 1680; i += 256) {
            ((uint4*)(smx + SG_BHI))[i] = gh[i];
            ((uint4*)(smx + SG_BLO))[i] = gl[i];
        }
    }
    __syncthreads();

    const uint32_t a_off = (uint32_t)((m0 + (lane & 15)) * 240 + (lane >> 4) * 16);
    const uint32_t b_row = (uint32_t)((lane & 15) * 240 + (lane >> 4) * 16);

    float acc[NP * 8];
    auto run_pass = [&]() {
#pragma unroll
        for (int i = 0; i < NP * 8; i++) acc[i] = 0.f;
#pragma unroll
        for (int kc = 0; kc < 7; kc++) {
            uint32_t ah[4], al[4];
            ldsm4(ah, sb + SG_AHI + a_off + kc * 32);
            ldsm4(al, sb + SG_ALO + a_off + kc * 32);
#pragma unroll
            for (int p = 0; p < NP; p++) {
                uint32_t bh[4], bl[4];
                uint32_t bo = b_row + (uint32_t)(kc * 3840 + p * 32);
                ldsm4t(bh, sb + SG_BHI + bo);
                ldsm4t(bl, sb + SG_BLO + bo);
#pragma unroll
                for (int h = 0; h < 2; h++) {
                    float* c = &acc[p * 8 + h * 4];
                    mma16816(c, ah, bh[2 * h], bh[2 * h + 1]);
                    mma16816(c, ah, bl[2 * h], bl[2 * h + 1]);
                    mma16816(c, al, bh[2 * h], bh[2 * h + 1]);
                }
            }
        }
    };

    run_pass();

    const int rA = m0 + (lane >> 2);
    const int rowA = r0 + rA, rowB = rowA + 8;

    if (EPI == 2) {
        __syncthreads();
        float* sC = (float*)smx;
#pragma unroll
        for (int p = 0; p < NP; p++) {
#pragma unroll
            for (int h = 0; h < 2; h++) {
                int col = p * 16 + h * 8 + (lane & 3) * 2;
                if (col < NOUT) {
                    float b0v = bias[col], b1v = bias[col + 1];
                    const float* c = &acc[p * 8 + h * 4];
                    sC[rA * NOUT + col]           = c[0] + b0v;
                    sC[rA * NOUT + col + 1]       = c[1] + b1v;
                    sC[(rA + 8) * NOUT + col]     = c[2] + b0v;
                    sC[(rA + 8) * NOUT + col + 1] = c[3] + b1v;
                }
            }
        }
        __syncthreads();
        for (int r = wid; r < 128; r += 8) {
            int row = r0 + r;
            float vals[4];
            float s = 0.f, sq = 0.f;
#pragma unroll
            for (int q = 0; q < 4; q++) {
                int c = lane + 32 * q;
                float v = (c < NOUT) ? sC[r * NOUT + c] : 0.f;
                vals[q] = v; s += v; sq += v * v;
            }
#pragma unroll
            for (int o2 = 16; o2 > 0; o2 >>= 1) {
                s  += __shfl_xor_sync(0xffffffffu, s,  o2);
                sq += __shfl_xor_sync(0xffffffffu, sq, o2);
            }
            float mean = s / NOUT;
            float var  = sq / NOUT - mean * mean;
            float rstd = rsqrtf(var + 1e-5f);
            if (row < NN) {
#pragma unroll
                for (int q = 0; q < 4; q++) {
                    int c = lane + 32 * q;
                    if (c < NOUT)
                        out[row * NOUT + c] =
                            fmaxf((vals[q] - mean) * rstd * gamma[c] + beta[c], 0.f);
                }
            }
        }
    } else if (EPI == 3) {
        float d0 = (rowA < NN) ? g_dinv[rowA] : 0.f;
        float d1 = (rowB < NN) ? g_dinv[rowB] : 0.f;
#pragma unroll
        for (int p = 0; p < NP; p++) {
#pragma unroll
            for (int h = 0; h < 2; h++) {
                int col = p * 16 + h * 8 + (lane & 3) * 2;
                if (col < NOUT) {
                    const float* c = &acc[p * 8 + h * 4];
                    if (rowA < NN) {
                        out[(size_t)rowA * NOUT + col]     = d0 * c[0];
                        out[(size_t)rowA * NOUT + col + 1] = d0 * c[1];
                    }
                    if (rowB < NN) {
                        out[(size_t)rowB * NOUT + col]     = d1 * c[2];
                        out[(size_t)rowB * NOUT + col + 1] = d1 * c[3];
                    }
                }
            }
        }
    } else {  // EPI == 4: dual, two passes over same B buffer
#pragma unroll
        for (int p = 0; p < NP; p++) {
#pragma unroll
            for (int h = 0; h < 2; h++) {
                int col = p * 16 + h * 8 + (lane & 3) * 2;
                if (col < NOUT) {
                    const float* c = &acc[p * 8 + h * 4];
                    float b0v = bias[col], b1v = bias[col + 1];
                    if (rowA < NN) {
                        out[(size_t)rowA * NOUT + col]     = c[0] + b0v;
                        out[(size_t)rowA * NOUT + col + 1] = c[1] + b1v;
                    }
                    if (rowB < NN) {
                        out[(size_t)rowB * NOUT + col]     = c[2] + b0v;
                        out[(size_t)rowB * NOUT + col + 1] = c[3] + b1v;
                    }
                }
            }
        }
        __syncthreads();
        {
            const uint4* gh = (const uint4*)g_Wh[widx2];
            const uint4* gl = (const uint4*)g_Wl[widx2];
            for (int i = tid; i < 1680; i += 256) {
                ((uint4*)(smx + SG_BHI))[i] = gh[i];
                ((uint4*)(smx + SG_BLO))[i] = gl[i];
            }
        }
        __syncthreads();
        run_pass();
#pragma unroll
        for (int p = 0; p < NP; p++) {
#pragma unroll
            for (int h = 0; h < 2; h++) {
                int col = p * 16 + h * 8 + (lane & 3) * 2;
                if (col < NOUT) {
                    const float* c = &acc[p * 8 + h * 4];
                    if (rowA < NN) {
                        out2[(size_t)rowA * NOUT + col]     = c[0];
                        out2[(size_t)rowA * NOUT + col + 1] = c[1];
                    }
                    if (rowB < NN) {
                        out2[(size_t)rowB * NOUT + col]     = c[2];
                        out2[(size_t)rowB * NOUT + col + 1] = c[3];
                    }
                }
            }
        }
    }
}

// ---------------------------------------------------------------------------
// Gather aggregation (warp per node), 4-way edge ILP. (unchanged)
// ---------------------------------------------------------------------------
template<int M4, int MODE>
__global__ void gather_kernel(const float* __restrict__ h,
                              const float* __restrict__ self,
                              const float* __restrict__ bias,
                              float* __restrict__ out)
{
    int w = (blockIdx.x * blockDim.x + threadIdx.x) >> 5;
    if (w >= NN) return;
    const int lane = threadIdx.x & 31;
    const bool act = lane < M4;
    const float4* h4 = (const float4*)h;

    float4 a0 = make_float4(0.f, 0.f, 0.f, 0.f);
    float4 a1 = a0, a2 = a0, a3 = a0;
    if (act) {
        if (MODE == 0) a0 = ((const float4*)self)[w * M4 + lane];
        else           a0 = h4[w * M4 + lane];
    }

    const int off = g_off[w];
    const int dg  = g_off[w + 1] - off;
    for (int base = 0; base < dg; base += 32) {
        int idx = base + lane;
        int myel = (idx < dg) ? g_el[off + idx] : 0;
        int cnt = dg - base; if (cnt > 32) cnt = 32;
        int j = 0;
        for (; j + 3 < cnt; j += 4) {
            int s0 = __shfl_sync(0xffffffffu, myel, j);
            int s1 = __shfl_sync(0xffffffffu, myel, j + 1);
            int s2 = __shfl_sync(0xffffffffu, myel, j + 2);
            int s3 = __shfl_sync(0xffffffffu, myel, j + 3);
            if (act) {
                float4 v0 = h4[s0 * M4 + lane];
                float4 v1 = h4[s1 * M4 + lane];
                float4 v2 = h4[s2 * M4 + lane];
                float4 v3 = h4[s3 * M4 + lane];
                a0.x += v0.x; a0.y += v0.y; a0.z += v0.z; a0.w += v0.w;
                a1.x += v1.x; a1.y += v1.y; a1.z += v1.z; a1.w += v1.w;
                a2.x += v2.x; a2.y += v2.y; a2.z += v2.z; a2.w += v2.w;
                a3.x += v3.x; a3.y += v3.y; a3.z += v3.z; a3.w += v3.w;
            }
        }
        for (; j < cnt; j++) {
            int s0 = __shfl_sync(0xffffffffu, myel, j);
            if (act) {
                float4 v0 = h4[s0 * M4 + lane];
                a0.x += v0.x; a0.y += v0.y; a0.z += v0.z; a0.w += v0.w;
            }
        }
    }
    float4 acc;
    acc.x = (a0.x + a1.x) + (a2.x + a3.x);
    acc.y = (a0.y + a1.y) + (a2.y + a3.y);
    acc.z = (a0.z + a1.z) + (a2.z + a3.z);
    acc.w = (a0.w + a1.w) + (a2.w + a3.w);

    if (MODE == 0) {
        if (act) {
            float4 o;
            o.x = fmaxf(acc.x, 0.f); o.y = fmaxf(acc.y, 0.f);
            o.z = fmaxf(acc.z, 0.f); o.w = fmaxf(acc.w, 0.f);
            ((float4*)out)[w * M4 + lane] = o;
        }
    } else if (MODE == 1) {
        if (act) {
            float di = g_dinv[w];
            float4 b = ((const float4*)bias)[lane];
            float4 o;
            o.x = fmaxf(fmaf(di, acc.x, b.x), 0.f);
            o.y = fmaxf(fmaf(di, acc.y, b.y), 0.f);
            o.z = fmaxf(fmaf(di, acc.z, b.z), 0.f);
            o.w = fmaxf(fmaf(di, acc.w, b.w), 0.f);
            ((float4*)out)[w * M4 + lane] = o;
        }
    } else {
        float di = g_dinv[w];
        float4 v = make_float4(0.f, 0.f, 0.f, 0.f);
        if (act) {
            float4 b = ((const float4*)bias)[lane];
            v.x = fmaf(di, acc.x, b.x); v.y = fmaf(di, acc.y, b.y);
            v.z = fmaf(di, acc.z, b.z); v.w = fmaf(di, acc.w, b.w);
        }
        float m = act ? fmaxf(fmaxf(v.x, v.y), fmaxf(v.z, v.w)) : -3.4e38f;
#pragma unroll
        for (int o2 = 16; o2 > 0; o2 >>= 1)
            m = fmaxf(m, __shfl_xor_sync(0xffffffffu, m, o2));
        float se = act ? (expf(v.x - m) + expf(v.y - m) + expf(v.z - m) + expf(v.w - m)) : 0.f;
#pragma unroll
        for (int o2 = 16; o2 > 0; o2 >>= 1)
            se += __shfl_xor_sync(0xffffffffu, se, o2);
        float lse = m + logf(se);
        if (act) {
            float4 o;
            o.x = v.x - lse; o.y = v.y - lse; o.z = v.z - lse; o.w = v.w - lse;
            ((float4*)out)[w * M4 + lane] = o;
        }
    }
}

extern "C" void kernel_launch(void* const* d_in, const int* in_sizes, int n_in,
                              void* d_out, int out_size)
{
    const float* X     = (const float*)d_in[0];
    const int*   ei    = (const int*)  d_in[1];
    const float* W1    = (const float*)d_in[3];
    const float* b1    = (const float*)d_in[4];
    const float* g1    = (const float*)d_in[5];
    const float* be1   = (const float*)d_in[6];
    const float* W2    = (const float*)d_in[7];
    const float* b2    = (const float*)d_in[8];
    const float* g2    = (const float*)d_in[9];
    const float* be2   = (const float*)d_in[10];
    const float* Wrel  = (const float*)d_in[11];
    const float* Wself = (const float*)d_in[12];
    const float* rb    = (const float*)d_in[13];
    const float* c1W   = (const float*)d_in[14];
    const float* c1b   = (const float*)d_in[15];
    const float* c2W   = (const float*)d_in[16];
    const float* c2b   = (const float*)d_in[17];
    float* out = (float*)d_out;

    const int* src = ei;
    const int* tgt = ei + NE;

    float *B1, *B2, *B3, *B4;
    cudaGetSymbolAddress((void**)&B1, g_B1);
    cudaGetSymbolAddress((void**)&B2, g_B2);
    cudaGetSymbolAddress((void**)&B3, g_B3);
    cudaGetSymbolAddress((void**)&B4, g_B4);

    cudaFuncSetAttribute(gemm_big_mma,
                         cudaFuncAttributeMaxDynamicSharedMemorySize, MB_SMEM);
    cudaFuncSetAttribute(gemm_small_mma<100, 2>,
                         cudaFuncAttributeMaxDynamicSharedMemorySize, SG_TOT);
    cudaFuncSetAttribute(gemm_small_mma<100, 3>,
                         cudaFuncAttributeMaxDynamicSharedMemorySize, SG_TOT);
    cudaFuncSetAttribute(gemm_small_mma<100, 4>,
                         cudaFuncAttributeMaxDynamicSharedMemorySize, SG_TOT);
    cudaFuncSetAttribute(gemm_small_mma<64, 3>,
                         cudaFuncAttributeMaxDynamicSharedMemorySize, SG_TOT);

    const int GB = (NN + 127) / 128;   // 391
    const int GGATHER = (NN * 32 + 255) / 256;

    // Fork a side stream for the CSR build (overlaps the transform GEMMs).
    cudaStream_t s2;
    cudaEvent_t evFork, evJoin;
    cudaStreamCreateWithFlags(&s2, cudaStreamNonBlocking);
    cudaEventCreateWithFlags(&evFork, cudaEventDisableTiming);
    cudaEventCreateWithFlags(&evJoin, cudaEventDisableTiming);

    cudaEventRecord(evFork, 0);
    cudaStreamWaitEvent(s2, evFork, 0);

    deg_zero_kernel <<<(NN / 4 + 255) / 256, 256, 0, s2>>>();
    deg_count_kernel<<<(NE / 4 + 255) / 256, 256, 0, s2>>>(tgt);
    scan_kernel     <<<1, 1024, 0, s2>>>();
    fill_kernel     <<<(NE / 4 + 255) / 256, 256, 0, s2>>>(src, tgt);
    cudaEventRecord(evJoin, s2);

    // Weight splits (once, tiny)
    wsplit_kernel<<<(512 * 112 + 5 * 13440 + 255) / 256, 256>>>(
        W1, W2, Wself, Wrel, c1W, c2W);

    // transform: (Linear -> LN -> ReLU) x2, both on mma.sync tensor path
    gemm_big_mma<<<GB, 256, MB_SMEM>>>(X, b1, g1, be1, B1);
    gemm_small_mma<100, 2><<<GB, 256, SG_TOT>>>(
        B1, 0, 0, b2, g2, be2, B2, nullptr);

    // RGCN: dual GEMM (Wself + rb -> B3, Wrel -> B4), then gather
    gemm_small_mma<100, 4><<<GB, 256, SG_TOT>>>(
        B2, 1, 2, rb, nullptr, nullptr, B3, B4);

    cudaStreamWaitEvent(0, evJoin, 0);
    gather_kernel<25, 0><<<GGATHER, 256>>>(B4, B3, nullptr, B1);

    // GCNConv1
    gemm_small_mma<100, 3><<<GB, 256, SG_TOT>>>(
        B1, 3, 0, nullptr, nullptr, nullptr, B2, nullptr);
    gather_kernel<25, 1><<<GGATHER, 256>>>(B2, nullptr, c1b, B3);

    // GCNConv2 (->64) + log_softmax
    gemm_small_mma<64, 3><<<GB, 256, SG_TOT>>>(
        B3, 4, 0, nullptr, nullptr, nullptr, B4, nullptr);
    gather_kernel<16, 2><<<GGATHER, 256>>>(B4, nullptr, c2b, out);

    cudaEventDestroy(evFork);
    cudaEventDestroy(evJoin);
    cudaStreamDestroy(s2);
}